// round 8
// baseline (speedup 1.0000x reference)
#include <cuda_runtime.h>
#include <math.h>
#include <stdint.h>

#define S_    1024
#define H_    2048
#define NH_   16
#define DH_   128
#define NN_   32
#define NP_   48
#define MK_   8192
#define HQKV_ 6144
#define KB_   6144

__device__ __align__(16) float g_qkv[S_ * HQKV_];
__device__ __align__(16) float g_q  [NH_ * S_ * DH_];
__device__ __align__(16) float g_k  [NH_ * S_ * DH_];
__device__ __align__(16) float g_v  [NH_ * S_ * DH_];
__device__ __align__(16) float g_ctx[S_ * H_];
__device__ __align__(16) float g_topv[NH_ * S_ * NN_];
__device__ __align__(16) int   g_topi[NH_ * S_ * NN_];
__device__ __align__(16) int   g_pooli[NH_ * S_ * NP_];

__device__ __align__(16) float g_ctx_s[S_ * KB_];
__device__ __align__(16) float g_wd_s [(size_t)H_ * KB_];

static __device__ __forceinline__ uint32_t smem_u32(const void* p){
    uint32_t a;
    asm("{ .reg .u64 t; cvta.to.shared.u64 t, %1; cvt.u32.u64 %0, t; }" : "=r"(a) : "l"(p));
    return a;
}
__device__ __forceinline__ int SWZ(int x){ return x ^ ((x >> 3) & 0x70); }
__device__ __forceinline__ float to_tf32(float x){
    float r; asm("cvt.rna.tf32.f32 %0, %1;" : "=f"(r) : "f"(x)); return r;
}
__device__ __forceinline__ void ldsm4(uint32_t* r, uint32_t a){
    asm volatile("ldmatrix.sync.aligned.m8n8.x4.shared.b16 {%0,%1,%2,%3}, [%4];"
        : "=r"(r[0]), "=r"(r[1]), "=r"(r[2]), "=r"(r[3]) : "r"(a));
}
__device__ __forceinline__ void mmat(float* c, const uint32_t* a, uint32_t b0, uint32_t b1){
    asm volatile(
        "mma.sync.aligned.m16n8k8.row.col.f32.tf32.tf32.f32 "
        "{%0,%1,%2,%3}, {%4,%5,%6,%7}, {%8,%9}, {%0,%1,%2,%3};"
        : "+f"(c[0]), "+f"(c[1]), "+f"(c[2]), "+f"(c[3])
        : "r"(a[0]), "r"(a[1]), "r"(a[2]), "r"(a[3]), "r"(b0), "r"(b1));
}

template<int MT>
__device__ __forceinline__ void mma_chunk(uint32_t sA, uint32_t sB,
                                          int lane, int wm, int wn, float* acc){
    const int rl = lane & 15, uh = lane >> 4;
#pragma unroll
    for (int ks = 0; ks < 4; ks++){
        uint32_t a[MT][4], b[2][4];
#pragma unroll
        for (int mt = 0; mt < MT; mt++)
            ldsm4(a[mt], sA + SWZ((wm*(MT*16) + mt*16 + rl)*128 + (ks*2+uh)*16));
#pragma unroll
        for (int bt = 0; bt < 2; bt++)
            ldsm4(b[bt], sB + SWZ((wn*32 + bt*16 + rl)*128 + (ks*2+uh)*16));
#pragma unroll
        for (int mt = 0; mt < MT; mt++)
#pragma unroll
            for (int nt = 0; nt < 4; nt++)
                mmat(acc + (mt*4+nt)*4, a[mt], b[nt>>1][nt&1], b[nt>>1][(nt&1)+2]);
    }
}

// ---- splits for out-GEMM only (ctx = A-type [h|l|h], Wd = B-type [h|h|l])
__global__ void split_kernel(const float* __restrict__ src, int total, int Kc, int which)
{
    const float* s = src; float* d; int atype = 0;
    if (which == 3) { s = g_ctx; d = g_ctx_s; atype = 1; } else { d = g_wd_s; }
    for (int i = blockIdx.x * blockDim.x + threadIdx.x; i < total;
         i += gridDim.x * blockDim.x) {
        float x  = s[i];
        float hi = to_tf32(x);
        float lo = to_tf32(x - hi);
        int r = i / Kc, k = i - r * Kc;
        size_t base = (size_t)r * 3 * Kc + k;
        d[base] = hi;
        d[base + Kc]     = atype ? lo : hi;
        d[base + 2 * Kc] = atype ? hi : lo;
    }
}

// ---- tf32 MMA out-GEMM (Lipschitz-only path) ----
#define GEMM_SMEM 65536
__global__ void __launch_bounds__(256) out_mma_kernel(const float* __restrict__ bias,
                                                      float* __restrict__ C)
{
    extern __shared__ char smraw[];
    uint32_t sb = smem_u32(smraw);
    const float* A = g_ctx_s; const float* B = g_wd_s;
    const int N = H_, K = KB_;
    const int tid = threadIdx.x, lane = tid & 31, wid = tid >> 5;
    const int wm = wid >> 2, wn = wid & 3;
    const int m0 = blockIdx.y * 128, n0 = blockIdx.x * 128;
    const int nch = K >> 5;

    float acc[64];
#pragma unroll
    for (int i = 0; i < 64; i++) acc[i] = 0.f;

#pragma unroll
    for (int i = 0; i < 4; i++){
        int g = tid + i * 256, r = g >> 3, u = g & 7;
        uint4 va = ((const uint4*)(A + (size_t)(m0 + r) * K))[u];
        uint4 vb = ((const uint4*)(B + (size_t)(n0 + r) * K))[u];
        *(uint4*)(smraw + SWZ(r*128 + u*16)) = va;
        *(uint4*)(smraw + 32768 + SWZ(r*128 + u*16)) = vb;
    }
    __syncthreads();

    for (int c = 0; c < nch; c++){
        const int buf = c & 1;
        uint4 pa[4], pb[4];
        if (c + 1 < nch){
#pragma unroll
            for (int i = 0; i < 4; i++){
                int g = tid + i * 256, r = g >> 3, u = g & 7;
                pa[i] = ((const uint4*)(A + (size_t)(m0 + r) * K))[(c+1)*8 + u];
                pb[i] = ((const uint4*)(B + (size_t)(n0 + r) * K))[(c+1)*8 + u];
            }
        }
        mma_chunk<4>(sb + buf*16384, sb + 32768 + buf*16384, lane, wm, wn, acc);
        if (c + 1 < nch){
            int nb = buf ^ 1;
#pragma unroll
            for (int i = 0; i < 4; i++){
                int g = tid + i * 256, r = g >> 3, u = g & 7;
                *(uint4*)(smraw + nb*16384 + SWZ(r*128 + u*16)) = pa[i];
                *(uint4*)(smraw + 32768 + nb*16384 + SWZ(r*128 + u*16)) = pb[i];
            }
        }
        __syncthreads();
    }

    const int gr = lane >> 2, gc2 = (lane & 3) * 2;
#pragma unroll
    for (int mt = 0; mt < 4; mt++)
#pragma unroll
        for (int nt = 0; nt < 4; nt++){
            const float* cp = acc + (mt*4+nt)*4;
            int r = m0 + wm*64 + mt*16 + gr;
            int col = n0 + wn*32 + nt*8 + gc2;
            float b0 = bias[col], b1 = bias[col+1];
            *(float2*)(C + (size_t)r * N + col)     = make_float2(cp[0]+b0, cp[1]+b1);
            *(float2*)(C + (size_t)(r+8) * N + col) = make_float2(cp[2]+b0, cp[3]+b1);
        }
}

// ---- r2 verbatim SIMT fp32 qkv GEMM (q must be bit-accurate for top-k) ----
__global__ void qkv_gemm_kernel(const float* __restrict__ A,
                                const float* __restrict__ B,
                                const float* __restrict__ bias)
{
    const int N = HQKV_, K = H_;
    __shared__ float As[8 * 128];
    __shared__ float Bs[8 * 128];
    const int tid  = threadIdx.x;
    const int m0   = blockIdx.y * 128;
    const int n0   = blockIdx.x * 128;
    const int ty   = tid >> 4, tx = tid & 15;
    const int lrow = tid >> 1, lk4 = (tid & 1) * 4;

    float c[8][8];
#pragma unroll
    for (int i = 0; i < 8; i++)
#pragma unroll
        for (int j = 0; j < 8; j++) c[i][j] = 0.f;

    const float* Ab = A + (size_t)(m0 + lrow) * K + lk4;
    const float* Bb = B + (size_t)(n0 + lrow) * K + lk4;

    for (int k0 = 0; k0 < K; k0 += 8) {
        float4 av = *(const float4*)(Ab + k0);
        float4 bv = *(const float4*)(Bb + k0);
        As[(lk4+0)*128+lrow] = av.x; As[(lk4+1)*128+lrow] = av.y;
        As[(lk4+2)*128+lrow] = av.z; As[(lk4+3)*128+lrow] = av.w;
        Bs[(lk4+0)*128+lrow] = bv.x; Bs[(lk4+1)*128+lrow] = bv.y;
        Bs[(lk4+2)*128+lrow] = bv.z; Bs[(lk4+3)*128+lrow] = bv.w;
        __syncthreads();
#pragma unroll
        for (int kk = 0; kk < 8; kk++) {
            float a[8], b[8];
            *(float4*)&a[0] = *(const float4*)&As[kk*128 + ty*8];
            *(float4*)&a[4] = *(const float4*)&As[kk*128 + ty*8 + 4];
            *(float4*)&b[0] = *(const float4*)&Bs[kk*128 + tx*8];
            *(float4*)&b[4] = *(const float4*)&Bs[kk*128 + tx*8 + 4];
#pragma unroll
            for (int i = 0; i < 8; i++)
#pragma unroll
                for (int j = 0; j < 8; j++) c[i][j] += a[i] * b[j];
        }
        __syncthreads();
    }
#pragma unroll
    for (int i = 0; i < 8; i++) {
        int row = m0 + ty * 8 + i;
#pragma unroll
        for (int j = 0; j < 8; j++) {
            int col = n0 + tx * 8 + j;
            g_qkv[(size_t)row * N + col] = c[i][j] + bias[col];
        }
    }
}

// ---- r2 verbatim norm+rope ----
__global__ void norm_rope_kernel(const int* __restrict__ pos)
{
    const int s = blockIdx.x, h = blockIdx.y, d = threadIdx.x;
    const float* base = g_qkv + (size_t)s * HQKV_ + h * (3 * DH_);
    float qv = base[d], kv = base[DH_ + d], vv = base[2 * DH_ + d];

    float sq = qv * qv, sk = kv * kv;
#pragma unroll
    for (int o = 16; o > 0; o >>= 1) {
        sq += __shfl_xor_sync(0xffffffffu, sq, o);
        sk += __shfl_xor_sync(0xffffffffu, sk, o);
    }
    __shared__ float rq[4], rk[4];
    if ((d & 31) == 0) { rq[d >> 5] = sq; rk[d >> 5] = sk; }
    __syncthreads();
    float nq = sqrtf(rq[0] + rq[1] + rq[2] + rq[3]);
    float nk = sqrtf(rk[0] + rk[1] + rk[2] + rk[3]);
    float qn = qv / fmaxf(nq, 1e-12f);
    float kn = kv / fmaxf(nk, 1e-12f);

    __shared__ float qs[DH_], ks[DH_];
    qs[d] = qn; ks[d] = kn;
    __syncthreads();

    float qo = qn, ko = kn;
    if (d < 32) {
        int i = (d < 16) ? d : d - 16;
        float freq = powf(10000.0f, -(float)i / 16.0f);
        float ang  = (float)pos[s] * freq;
        float cs = cosf(ang), sn = sinf(ang);
        float rqh = (d < 16) ? -qs[d + 16] : qs[d - 16];
        float rkh = (d < 16) ? -ks[d + 16] : ks[d - 16];
        qo = qn * cs + rqh * sn;
        ko = kn * cs + rkh * sn;
    }
    size_t o = ((size_t)h * S_ + s) * DH_ + d;
    g_q[o] = qo; g_k[o] = ko; g_v[o] = vv;
}

// ---- kNN candidate pool: plain-tf32 MMA scores + online top-48 ----
#define KNP_SMEM 123392
__global__ void __launch_bounds__(256) knn_pool_kernel(const float* __restrict__ mem_keys)
{
    extern __shared__ char smraw[];
    uint32_t sb = smem_u32(smraw);
    const int tid = threadIdx.x, lane = tid & 31, wid = tid >> 5;
    const int wm = wid >> 2, wn = wid & 3;
    const int h = blockIdx.y, q0 = blockIdx.x * 64;
    float* Sc = (float*)(smraw + 65536);   // [64][130]
    float* Tv = (float*)(smraw + 98816);   // [64][48]
    int*   Ti = (int*)(smraw + 111104);    // [64][48]

    {   // resident A: 64 q rows x 128 fp32 -> 4 chunk tiles of 8KB
        int r = tid >> 2, part = tid & 3;
        const uint4* Ar = (const uint4*)(g_q + ((size_t)h * S_ + q0 + r) * DH_);
#pragma unroll
        for (int j = 0; j < 8; j++)
            *(uint4*)(smraw + part*8192 + SWZ(r*128 + j*16)) = Ar[part*8 + j];
    }
    float minv = -3.0e38f; int minpos = 0;
    if (tid < 64){
#pragma unroll
        for (int n = 0; n < NP_; n++){ Tv[tid*NP_+n] = -3.0e38f; Ti[tid*NP_+n] = 0; }
    }
#pragma unroll
    for (int i = 0; i < 4; i++){
        int g = tid + i * 256, r = g >> 3, u = g & 7;
        uint4 v = ((const uint4*)(mem_keys + ((size_t)h * MK_ + r) * DH_))[u];
        *(uint4*)(smraw + 32768 + SWZ(r*128 + u*16)) = v;
    }
    __syncthreads();

    float acc[32];
#pragma unroll
    for (int i = 0; i < 32; i++) acc[i] = 0.f;

    for (int g = 0; g < 64 * 4; g++){
        const int t = g >> 2, ci = g & 3;
        const int buf = g & 1;
        uint4 pb[4];
        if (g + 1 < 64 * 4){
            int tn = (g + 1) >> 2, cn = (g + 1) & 3;
#pragma unroll
            for (int i = 0; i < 4; i++){
                int gi = tid + i * 256, r = gi >> 3, u = gi & 7;
                pb[i] = ((const uint4*)(mem_keys +
                         ((size_t)h * MK_ + tn * 128 + r) * DH_))[cn*8 + u];
            }
        }
        mma_chunk<2>(sb + ci*8192, sb + 32768 + buf*16384, lane, wm, wn, acc);
        if (g + 1 < 64 * 4){
            int nb = buf ^ 1;
#pragma unroll
            for (int i = 0; i < 4; i++){
                int gi = tid + i * 256, r = gi >> 3, u = gi & 7;
                *(uint4*)(smraw + 32768 + nb*16384 + SWZ(r*128 + u*16)) = pb[i];
            }
        }
        __syncthreads();

        if (ci == 3){
            const int gr = lane >> 2, gc2 = (lane & 3) * 2;
#pragma unroll
            for (int mt = 0; mt < 2; mt++)
#pragma unroll
                for (int nt = 0; nt < 4; nt++){
                    float* cp = acc + (mt*4+nt)*4;
                    int r = wm*32 + mt*16 + gr, col = wn*32 + nt*8 + gc2;
                    *(float2*)(Sc + r*130 + col)     = make_float2(cp[0], cp[1]);
                    *(float2*)(Sc + (r+8)*130 + col) = make_float2(cp[2], cp[3]);
                }
#pragma unroll
            for (int i = 0; i < 32; i++) acc[i] = 0.f;
            __syncthreads();

            if (tid < 64){
                const float* srow = Sc + tid * 130;
                float* tv = Tv + tid * NP_;
                int*   ti = Ti + tid * NP_;
                for (int n = 0; n < 128; n++){
                    float s = srow[n];
                    if (s > minv){
                        tv[minpos] = s; ti[minpos] = t*128 + n;
                        minv = tv[0]; minpos = 0;
#pragma unroll
                        for (int u2 = 1; u2 < NP_; u2++){
                            float x = tv[u2];
                            if (x < minv){ minv = x; minpos = u2; }
                        }
                    }
                }
            }
            __syncthreads();
        }
    }
    if (tid < 64){
#pragma unroll
        for (int n = 0; n < NP_; n++)
            g_pooli[((size_t)h * S_ + q0 + tid) * NP_ + n] = Ti[tid*NP_+n];
    }
}

// ---- exact fp32 rescore of 48 candidates -> true top-32 ----
__global__ void rescore_kernel(const float* __restrict__ mem_keys)
{
    __shared__ float ssc[4][NP_];
    __shared__ int   sid[4][NP_];
    const int lane = threadIdx.x & 31, w = threadIdx.x >> 5;
    const int h = blockIdx.y;
    const int q = blockIdx.x * 4 + w;
    const size_t qi = (size_t)h * S_ + q;

    float4 qv = ((const float4*)(g_q + qi * DH_))[lane];
    for (int c = lane; c < NP_; c += 32) sid[w][c] = g_pooli[qi * NP_ + c];
    __syncwarp();

    for (int c = 0; c < NP_; c++){
        float4 kv = ((const float4*)(mem_keys + ((size_t)h * MK_ + sid[w][c]) * DH_))[lane];
        float d = qv.x*kv.x + qv.y*kv.y + qv.z*kv.z + qv.w*kv.w;
#pragma unroll
        for (int o = 16; o > 0; o >>= 1) d += __shfl_xor_sync(0xffffffffu, d, o);
        if (lane == 0) ssc[w][c] = d;
    }
    __syncwarp();

    float v1 = ssc[w][lane];
    float v2 = (lane < NP_ - 32) ? ssc[w][32 + lane] : -3.0e38f;
    for (int it = 0; it < NN_; it++){
        float mv; int mi;
        if (v1 >= v2){ mv = v1; mi = lane; } else { mv = v2; mi = 32 + lane; }
#pragma unroll
        for (int o = 16; o > 0; o >>= 1){
            float ov = __shfl_xor_sync(0xffffffffu, mv, o);
            int   oi = __shfl_xor_sync(0xffffffffu, mi, o);
            if (ov > mv || (ov == mv && oi < mi)){ mv = ov; mi = oi; }
        }
        if (mi < 32){ if (lane == mi) v1 = -3.0e38f; }
        else        { if (lane == mi - 32) v2 = -3.0e38f; }
        if (lane == 0){
            g_topv[qi * NN_ + it] = mv;
            g_topi[qi * NN_ + it] = sid[w][mi];
        }
    }
}

// ---- r2 verbatim flash attention ----
#define K4_SMEM ((128 * 68 + 128 * 68 + 64 * 65 + 192 + 64 * 32) * 4)
__global__ void attn_kernel(const float* __restrict__ am,
                            const float* __restrict__ scale_param,
                            const float* __restrict__ mem_values)
{
    extern __shared__ float sm[];
    float* Qs  = sm;
    float* KV  = Qs + 128 * 68;
    float* Sc  = KV + 128 * 68;
    float* msh = Sc + 64 * 65;
    float* lsh = msh + 64;
    float* csh = lsh + 64;
    int*   Ti  = (int*)(csh + 64);

    const int tid = threadIdx.x;
    const int h   = blockIdx.y;
    const int q0  = blockIdx.x * 64;
    const int ty  = tid >> 4, tx = tid & 15;
    const float scale = expf(scale_param[h]);

    for (int idx = tid; idx < 64 * 32; idx += 256) {
        int row = idx >> 5, seg = idx & 31;
        float4 v = *(const float4*)(g_q + ((size_t)h * S_ + q0 + row) * DH_ + seg * 4);
        Qs[(seg*4+0)*68+row] = v.x; Qs[(seg*4+1)*68+row] = v.y;
        Qs[(seg*4+2)*68+row] = v.z; Qs[(seg*4+3)*68+row] = v.w;
    }
    for (int idx = tid; idx < 64 * 32; idx += 256) {
        int q = idx >> 5, n = idx & 31;
        Sc[q*65+n] = g_topv[((size_t)h * S_ + q0 + q) * NN_ + n] * scale;
        Ti[q*32+n] = g_topi[((size_t)h * S_ + q0 + q) * NN_ + n];
    }
    __syncthreads();

    if (tid < 64) {
        int q = tid;
        float mm = -3.0e38f;
        for (int n = 0; n < NN_; n++) mm = fmaxf(mm, Sc[q*65+n]);
        float ll = 0.f;
        for (int n = 0; n < NN_; n++) {
            float p = expf(Sc[q*65+n] - mm);
            Sc[q*65+n] = p; ll += p;
        }
        msh[q] = mm; lsh[q] = ll;
    }
    __syncthreads();

    float oacc[4][8];
#pragma unroll
    for (int i = 0; i < 4; i++)
#pragma unroll
        for (int j = 0; j < 8; j++) oacc[i][j] = 0.f;

#pragma unroll
    for (int i = 0; i < 4; i++) {
        int qr = ty * 4 + i;
        for (int n = 0; n < NN_; n++) {
            float w = Sc[qr*65+n];
            const float4* vr = (const float4*)(mem_values +
                ((size_t)h * MK_ + Ti[qr*32+n]) * DH_ + tx * 8);
            float4 v0 = vr[0], v1 = vr[1];
            oacc[i][0]+=w*v0.x; oacc[i][1]+=w*v0.y; oacc[i][2]+=w*v0.z; oacc[i][3]+=w*v0.w;
            oacc[i][4]+=w*v1.x; oacc[i][5]+=w*v1.y; oacc[i][6]+=w*v1.z; oacc[i][7]+=w*v1.w;
        }
    }

    const int kcmax = q0 / 64;
    for (int kc = 0; kc <= kcmax; kc++) {
        __syncthreads();
        for (int idx = tid; idx < 64 * 32; idx += 256) {
            int row = idx >> 5, seg = idx & 31;
            float4 v = *(const float4*)(g_k + ((size_t)h * S_ + kc*64 + row) * DH_ + seg * 4);
            KV[(seg*4+0)*68+row] = v.x; KV[(seg*4+1)*68+row] = v.y;
            KV[(seg*4+2)*68+row] = v.z; KV[(seg*4+3)*68+row] = v.w;
        }
        __syncthreads();

        float sc4[4][4];
#pragma unroll
        for (int i = 0; i < 4; i++)
#pragma unroll
            for (int j = 0; j < 4; j++) sc4[i][j] = 0.f;

#pragma unroll 8
        for (int kd = 0; kd < DH_; kd++) {
            float4 aq = *(const float4*)&Qs[kd*68 + ty*4];
            float4 bk = *(const float4*)&KV[kd*68 + tx*4];
            float a[4] = {aq.x, aq.y, aq.z, aq.w};
            float b[4] = {bk.x, bk.y, bk.z, bk.w};
#pragma unroll
            for (int i = 0; i < 4; i++)
#pragma unroll
                for (int j = 0; j < 4; j++) sc4[i][j] += a[i] * b[j];
        }
#pragma unroll
        for (int i = 0; i < 4; i++) {
            int qg = q0 + ty*4 + i;
#pragma unroll
            for (int j = 0; j < 4; j++) {
                int kg = kc*64 + tx*4 + j;
                float v = (kg <= qg) ? (sc4[i][j] * scale + am[kg]) : -1.0e30f;
                Sc[(ty*4+i)*65 + tx*4+j] = v;
            }
        }
        __syncthreads();

        if (tid < 64) {
            int q = tid;
            float mm = msh[q];
            float rmax = mm;
            for (int n = 0; n < 64; n++) rmax = fmaxf(rmax, Sc[q*65+n]);
            float cor = expf(mm - rmax);
            float ll = lsh[q] * cor;
            for (int n = 0; n < 64; n++) {
                float p = expf(Sc[q*65+n] - rmax);
                Sc[q*65+n] = p; ll += p;
            }
            msh[q] = rmax; lsh[q] = ll; csh[q] = cor;
        }
        __syncthreads();

        for (int idx = tid; idx < 64 * 32; idx += 256) {
            int row = idx >> 5, seg = idx & 31;
            float4 v = *(const float4*)(g_v + ((size_t)h * S_ + kc*64 + row) * DH_ + seg * 4);
            *(float4*)&KV[row*132 + seg*4] = v;
        }
        __syncthreads();

#pragma unroll
        for (int i = 0; i < 4; i++) {
            int qr = ty*4 + i;
            float cor = csh[qr];
#pragma unroll
            for (int j = 0; j < 8; j++) oacc[i][j] *= cor;
            for (int n = 0; n < 64; n++) {
                float w = Sc[qr*65+n];
                float4 v0 = *(const float4*)&KV[n*132 + tx*8];
                float4 v1 = *(const float4*)&KV[n*132 + tx*8 + 4];
                oacc[i][0]+=w*v0.x; oacc[i][1]+=w*v0.y; oacc[i][2]+=w*v0.z; oacc[i][3]+=w*v0.w;
                oacc[i][4]+=w*v1.x; oacc[i][5]+=w*v1.y; oacc[i][6]+=w*v1.z; oacc[i][7]+=w*v1.w;
            }
        }
    }

#pragma unroll
    for (int i = 0; i < 4; i++) {
        int qr = ty*4 + i;
        float inv = 1.0f / lsh[qr];
#pragma unroll
        for (int j = 0; j < 8; j++)
            g_ctx[(size_t)(q0+qr) * H_ + h*DH_ + tx*8 + j] = oacc[i][j] * inv;
    }
}

extern "C" void kernel_launch(void* const* d_in, const int* in_sizes, int n_in,
                              void* d_out, int out_size)
{
    const float* hidden      = (const float*)d_in[0];
    const float* am          = (const float*)d_in[1];
    const int*   pos         = (const int*)d_in[2];
    const float* Wqkv        = (const float*)d_in[3];
    const float* bqkv        = (const float*)d_in[4];
    const float* Wd          = (const float*)d_in[5];
    const float* bd          = (const float*)d_in[6];
    const float* scale_param = (const float*)d_in[7];
    const float* mem_keys    = (const float*)d_in[8];
    const float* mem_values  = (const float*)d_in[9];
    float*       out         = (float*)d_out;

    cudaFuncSetAttribute(out_mma_kernel,  cudaFuncAttributeMaxDynamicSharedMemorySize, GEMM_SMEM);
    cudaFuncSetAttribute(knn_pool_kernel, cudaFuncAttributeMaxDynamicSharedMemorySize, KNP_SMEM);
    cudaFuncSetAttribute(attn_kernel,     cudaFuncAttributeMaxDynamicSharedMemorySize, K4_SMEM);

    qkv_gemm_kernel<<<dim3(HQKV_/128, S_/128), 256>>>(hidden, Wqkv, bqkv);
    norm_rope_kernel<<<dim3(S_, NH_), 128>>>(pos);
    knn_pool_kernel<<<dim3(S_/64, NH_), 256, KNP_SMEM>>>(mem_keys);
    rescore_kernel<<<dim3(S_/4, NH_), 128>>>(mem_keys);
    attn_kernel<<<dim3(S_/64, NH_), 256, K4_SMEM>>>(am, scale_param, mem_values);

    split_kernel<<<512,  256>>>(hidden, S_ * H_, H_, 3);
    split_kernel<<<1024, 256>>>(Wd,     H_ * H_, H_, 4);
    out_mma_kernel<<<dim3(H_/128, S_/128), 256, GEMM_SMEM>>>(bd, out);
}

// round 9
// speedup vs baseline: 1.2031x; 1.2031x over previous
#include <cuda_runtime.h>
#include <math.h>
#include <stdint.h>

#define S_    1024
#define H_    2048
#define NH_   16
#define DH_   128
#define NN_   32
#define NP_   64
#define MK_   8192
#define HQKV_ 6144
#define KB_   6144

__device__ __align__(16) float g_qkv[S_ * HQKV_];
__device__ __align__(16) float g_q  [NH_ * S_ * DH_];
__device__ __align__(16) float g_k  [NH_ * S_ * DH_];
__device__ __align__(16) float g_v  [NH_ * S_ * DH_];
__device__ __align__(16) float g_ctx[S_ * H_];
__device__ __align__(16) float g_topv[NH_ * S_ * NN_];
__device__ __align__(16) int   g_topi[NH_ * S_ * NN_];
__device__ __align__(16) int   g_pooli[NH_ * S_ * NP_];

__device__ __align__(16) float g_ctx_s[S_ * KB_];
__device__ __align__(16) float g_wd_s [(size_t)H_ * KB_];

static __device__ __forceinline__ uint32_t smem_u32(const void* p){
    uint32_t a;
    asm("{ .reg .u64 t; cvta.to.shared.u64 t, %1; cvt.u32.u64 %0, t; }" : "=r"(a) : "l"(p));
    return a;
}
__device__ __forceinline__ int SWZ(int x){ return x ^ ((x >> 3) & 0x70); }
__device__ __forceinline__ float to_tf32(float x){
    float r; asm("cvt.rna.tf32.f32 %0, %1;" : "=f"(r) : "f"(x)); return r;
}
__device__ __forceinline__ void ldsm4(uint32_t* r, uint32_t a){
    asm volatile("ldmatrix.sync.aligned.m8n8.x4.shared.b16 {%0,%1,%2,%3}, [%4];"
        : "=r"(r[0]), "=r"(r[1]), "=r"(r[2]), "=r"(r[3]) : "r"(a));
}
__device__ __forceinline__ void mmat(float* c, const uint32_t* a, uint32_t b0, uint32_t b1){
    asm volatile(
        "mma.sync.aligned.m16n8k8.row.col.f32.tf32.tf32.f32 "
        "{%0,%1,%2,%3}, {%4,%5,%6,%7}, {%8,%9}, {%0,%1,%2,%3};"
        : "+f"(c[0]), "+f"(c[1]), "+f"(c[2]), "+f"(c[3])
        : "r"(a[0]), "r"(a[1]), "r"(a[2]), "r"(a[3]), "r"(b0), "r"(b1));
}

template<int MT>
__device__ __forceinline__ void mma_chunk(uint32_t sA, uint32_t sB,
                                          int lane, int wm, int wn, float* acc){
    const int rl = lane & 15, uh = lane >> 4;
#pragma unroll
    for (int ks = 0; ks < 4; ks++){
        uint32_t a[MT][4], b[2][4];
#pragma unroll
        for (int mt = 0; mt < MT; mt++)
            ldsm4(a[mt], sA + SWZ((wm*(MT*16) + mt*16 + rl)*128 + (ks*2+uh)*16));
#pragma unroll
        for (int bt = 0; bt < 2; bt++)
            ldsm4(b[bt], sB + SWZ((wn*32 + bt*16 + rl)*128 + (ks*2+uh)*16));
#pragma unroll
        for (int mt = 0; mt < MT; mt++)
#pragma unroll
            for (int nt = 0; nt < 4; nt++)
                mmat(acc + (mt*4+nt)*4, a[mt], b[nt>>1][nt&1], b[nt>>1][(nt&1)+2]);
    }
}

// ---- splits for out-GEMM (ctx = A-type [h|l|h], Wd = B-type [h|h|l]) ----
__global__ void split_kernel(const float* __restrict__ src, int total, int Kc, int which)
{
    const float* s = src; float* d; int atype = 0;
    if (which == 3) { s = g_ctx; d = g_ctx_s; atype = 1; } else { d = g_wd_s; }
    for (int i = blockIdx.x * blockDim.x + threadIdx.x; i < total;
         i += gridDim.x * blockDim.x) {
        float x  = s[i];
        float hi = to_tf32(x);
        float lo = to_tf32(x - hi);
        int r = i / Kc, k = i - r * Kc;
        size_t base = (size_t)r * 3 * Kc + k;
        d[base] = hi;
        d[base + Kc]     = atype ? lo : hi;
        d[base + 2 * Kc] = atype ? hi : lo;
    }
}

// ---- tf32 MMA out-GEMM ----
#define GEMM_SMEM 65536
__global__ void __launch_bounds__(256) out_mma_kernel(const float* __restrict__ bias,
                                                      float* __restrict__ C)
{
    extern __shared__ char smraw[];
    uint32_t sb = smem_u32(smraw);
    const float* A = g_ctx_s; const float* B = g_wd_s;
    const int N = H_, K = KB_;
    const int tid = threadIdx.x, lane = tid & 31, wid = tid >> 5;
    const int wm = wid >> 2, wn = wid & 3;
    const int m0 = blockIdx.y * 128, n0 = blockIdx.x * 128;
    const int nch = K >> 5;

    float acc[64];
#pragma unroll
    for (int i = 0; i < 64; i++) acc[i] = 0.f;

#pragma unroll
    for (int i = 0; i < 4; i++){
        int g = tid + i * 256, r = g >> 3, u = g & 7;
        uint4 va = ((const uint4*)(A + (size_t)(m0 + r) * K))[u];
        uint4 vb = ((const uint4*)(B + (size_t)(n0 + r) * K))[u];
        *(uint4*)(smraw + SWZ(r*128 + u*16)) = va;
        *(uint4*)(smraw + 32768 + SWZ(r*128 + u*16)) = vb;
    }
    __syncthreads();

    for (int c = 0; c < nch; c++){
        const int buf = c & 1;
        uint4 pa[4], pb[4];
        if (c + 1 < nch){
#pragma unroll
            for (int i = 0; i < 4; i++){
                int g = tid + i * 256, r = g >> 3, u = g & 7;
                pa[i] = ((const uint4*)(A + (size_t)(m0 + r) * K))[(c+1)*8 + u];
                pb[i] = ((const uint4*)(B + (size_t)(n0 + r) * K))[(c+1)*8 + u];
            }
        }
        mma_chunk<4>(sb + buf*16384, sb + 32768 + buf*16384, lane, wm, wn, acc);
        if (c + 1 < nch){
            int nb = buf ^ 1;
#pragma unroll
            for (int i = 0; i < 4; i++){
                int g = tid + i * 256, r = g >> 3, u = g & 7;
                *(uint4*)(smraw + nb*16384 + SWZ(r*128 + u*16)) = pa[i];
                *(uint4*)(smraw + 32768 + nb*16384 + SWZ(r*128 + u*16)) = pb[i];
            }
        }
        __syncthreads();
    }

    const int gr = lane >> 2, gc2 = (lane & 3) * 2;
#pragma unroll
    for (int mt = 0; mt < 4; mt++)
#pragma unroll
        for (int nt = 0; nt < 4; nt++){
            const float* cp = acc + (mt*4+nt)*4;
            int r = m0 + wm*64 + mt*16 + gr;
            int col = n0 + wn*32 + nt*8 + gc2;
            float b0 = bias[col], b1 = bias[col+1];
            *(float2*)(C + (size_t)r * N + col)     = make_float2(cp[0]+b0, cp[1]+b1);
            *(float2*)(C + (size_t)(r+8) * N + col) = make_float2(cp[2]+b0, cp[3]+b1);
        }
}

// ---- SIMT fp32 qkv GEMM (q must stay exact for top-k) ----
__global__ void qkv_gemm_kernel(const float* __restrict__ A,
                                const float* __restrict__ B,
                                const float* __restrict__ bias)
{
    const int N = HQKV_, K = H_;
    __shared__ float As[8 * 128];
    __shared__ float Bs[8 * 128];
    const int tid  = threadIdx.x;
    const int m0   = blockIdx.y * 128;
    const int n0   = blockIdx.x * 128;
    const int ty   = tid >> 4, tx = tid & 15;
    const int lrow = tid >> 1, lk4 = (tid & 1) * 4;

    float c[8][8];
#pragma unroll
    for (int i = 0; i < 8; i++)
#pragma unroll
        for (int j = 0; j < 8; j++) c[i][j] = 0.f;

    const float* Ab = A + (size_t)(m0 + lrow) * K + lk4;
    const float* Bb = B + (size_t)(n0 + lrow) * K + lk4;

    for (int k0 = 0; k0 < K; k0 += 8) {
        float4 av = *(const float4*)(Ab + k0);
        float4 bv = *(const float4*)(Bb + k0);
        As[(lk4+0)*128+lrow] = av.x; As[(lk4+1)*128+lrow] = av.y;
        As[(lk4+2)*128+lrow] = av.z; As[(lk4+3)*128+lrow] = av.w;
        Bs[(lk4+0)*128+lrow] = bv.x; Bs[(lk4+1)*128+lrow] = bv.y;
        Bs[(lk4+2)*128+lrow] = bv.z; Bs[(lk4+3)*128+lrow] = bv.w;
        __syncthreads();
#pragma unroll
        for (int kk = 0; kk < 8; kk++) {
            float a[8], b[8];
            *(float4*)&a[0] = *(const float4*)&As[kk*128 + ty*8];
            *(float4*)&a[4] = *(const float4*)&As[kk*128 + ty*8 + 4];
            *(float4*)&b[0] = *(const float4*)&Bs[kk*128 + tx*8];
            *(float4*)&b[4] = *(const float4*)&Bs[kk*128 + tx*8 + 4];
#pragma unroll
            for (int i = 0; i < 8; i++)
#pragma unroll
                for (int j = 0; j < 8; j++) c[i][j] += a[i] * b[j];
        }
        __syncthreads();
    }
#pragma unroll
    for (int i = 0; i < 8; i++) {
        int row = m0 + ty * 8 + i;
#pragma unroll
        for (int j = 0; j < 8; j++) {
            int col = n0 + tx * 8 + j;
            g_qkv[(size_t)row * N + col] = c[i][j] + bias[col];
        }
    }
}

// ---- norm + rope ----
__global__ void norm_rope_kernel(const int* __restrict__ pos)
{
    const int s = blockIdx.x, h = blockIdx.y, d = threadIdx.x;
    const float* base = g_qkv + (size_t)s * HQKV_ + h * (3 * DH_);
    float qv = base[d], kv = base[DH_ + d], vv = base[2 * DH_ + d];

    float sq = qv * qv, sk = kv * kv;
#pragma unroll
    for (int o = 16; o > 0; o >>= 1) {
        sq += __shfl_xor_sync(0xffffffffu, sq, o);
        sk += __shfl_xor_sync(0xffffffffu, sk, o);
    }
    __shared__ float rq[4], rk[4];
    if ((d & 31) == 0) { rq[d >> 5] = sq; rk[d >> 5] = sk; }
    __syncthreads();
    float nq = sqrtf(rq[0] + rq[1] + rq[2] + rq[3]);
    float nk = sqrtf(rk[0] + rk[1] + rk[2] + rk[3]);
    float qn = qv / fmaxf(nq, 1e-12f);
    float kn = kv / fmaxf(nk, 1e-12f);

    __shared__ float qs[DH_], ks[DH_];
    qs[d] = qn; ks[d] = kn;
    __syncthreads();

    float qo = qn, ko = kn;
    if (d < 32) {
        int i = (d < 16) ? d : d - 16;
        float freq = powf(10000.0f, -(float)i / 16.0f);
        float ang  = (float)pos[s] * freq;
        float cs = cosf(ang), sn = sinf(ang);
        float rqh = (d < 16) ? -qs[d + 16] : qs[d - 16];
        float rkh = (d < 16) ? -ks[d + 16] : ks[d - 16];
        qo = qn * cs + rqh * sn;
        ko = kn * cs + rkh * sn;
    }
    size_t o = ((size_t)h * S_ + s) * DH_ + d;
    g_q[o] = qo; g_k[o] = ko; g_v[o] = vv;
}

// ---- kNN pool: tf32 MMA scores + warp-cooperative top-64 ----
#define KNA   0
#define KNB   32768
#define KNSC  65536
#define KNTV  98816
#define KNTI  115200
#define KNMN  131584
#define KNP_SMEM 131840
__global__ void __launch_bounds__(256) knn_pool_kernel(const float* __restrict__ mem_keys)
{
    extern __shared__ char smraw[];
    uint32_t sb = smem_u32(smraw);
    const int tid = threadIdx.x, lane = tid & 31, wid = tid >> 5;
    const int wm = wid >> 2, wn = wid & 3;
    const int h = blockIdx.y, q0 = blockIdx.x * 64;
    float* Sc    = (float*)(smraw + KNSC);   // [64][130]
    float* Tv    = (float*)(smraw + KNTV);   // [64][64]
    int*   Ti    = (int*)(smraw + KNTI);     // [64][64]
    float* minsh = (float*)(smraw + KNMN);   // [64]

    {   // resident A: 64 q rows x 128 fp32 -> 4 chunk tiles of 8KB
        int r = tid >> 2, part = tid & 3;
        const uint4* Ar = (const uint4*)(g_q + ((size_t)h * S_ + q0 + r) * DH_);
#pragma unroll
        for (int j = 0; j < 8; j++)
            *(uint4*)(smraw + KNA + part*8192 + SWZ(r*128 + j*16)) = Ar[part*8 + j];
    }
    for (int i = tid; i < 64 * NP_; i += 256){ Tv[i] = -3.0e38f; Ti[i] = 0; }
    if (tid < 64) minsh[tid] = -3.0e38f;

#pragma unroll
    for (int i = 0; i < 4; i++){
        int g = tid + i * 256, r = g >> 3, u = g & 7;
        uint4 v = ((const uint4*)(mem_keys + ((size_t)h * MK_ + r) * DH_))[u];
        *(uint4*)(smraw + KNB + SWZ(r*128 + u*16)) = v;
    }
    __syncthreads();

    float acc[32];
#pragma unroll
    for (int i = 0; i < 32; i++) acc[i] = 0.f;

    for (int g = 0; g < 64 * 4; g++){
        const int t = g >> 2, ci = g & 3;
        const int buf = g & 1;
        uint4 pb[4];
        if (g + 1 < 64 * 4){
            int tn = (g + 1) >> 2, cn = (g + 1) & 3;
#pragma unroll
            for (int i = 0; i < 4; i++){
                int gi = tid + i * 256, r = gi >> 3, u = gi & 7;
                pb[i] = ((const uint4*)(mem_keys +
                         ((size_t)h * MK_ + tn * 128 + r) * DH_))[cn*8 + u];
            }
        }
        mma_chunk<2>(sb + KNA + ci*8192, sb + KNB + buf*16384, lane, wm, wn, acc);
        if (g + 1 < 64 * 4){
            int nb = buf ^ 1;
#pragma unroll
            for (int i = 0; i < 4; i++){
                int gi = tid + i * 256, r = gi >> 3, u = gi & 7;
                *(uint4*)(smraw + KNB + nb*16384 + SWZ(r*128 + u*16)) = pb[i];
            }
        }
        __syncthreads();

        if (ci == 3){
            const int gr = lane >> 2, gc2 = (lane & 3) * 2;
#pragma unroll
            for (int mt = 0; mt < 2; mt++)
#pragma unroll
                for (int nt = 0; nt < 4; nt++){
                    float* cp = acc + (mt*4+nt)*4;
                    int r = wm*32 + mt*16 + gr, col = wn*32 + nt*8 + gc2;
                    *(float2*)(Sc + r*130 + col)     = make_float2(cp[0], cp[1]);
                    *(float2*)(Sc + (r+8)*130 + col) = make_float2(cp[2], cp[3]);
                }
#pragma unroll
            for (int i = 0; i < 32; i++) acc[i] = 0.f;
            __syncthreads();

            // warp-cooperative top-64 update: warp w owns queries w*8..w*8+7
            for (int qq = 0; qq < 8; qq++){
                const int q = wid * 8 + qq;
                float mv = minsh[q];
                float* pool = Tv + q * NP_;
                int*   pidx = Ti + q * NP_;
#pragma unroll
                for (int seg = 0; seg < 4; seg++){
                    float s = Sc[q*130 + seg*32 + lane];
                    unsigned m = __ballot_sync(0xffffffffu, s > mv);
                    while (m){
                        int b = __ffs(m) - 1; m &= m - 1;
                        float sv = __shfl_sync(0xffffffffu, s, b);
                        // warp-parallel argmin over the 64-slot pool
                        float p0 = pool[lane], p1 = pool[lane + 32];
                        float pm; int ps;
                        if (p0 <= p1){ pm = p0; ps = lane; }
                        else         { pm = p1; ps = lane + 32; }
#pragma unroll
                        for (int o = 16; o > 0; o >>= 1){
                            float ov = __shfl_xor_sync(0xffffffffu, pm, o);
                            int   os = __shfl_xor_sync(0xffffffffu, ps, o);
                            if (ov < pm || (ov == pm && os < ps)){ pm = ov; ps = os; }
                        }
                        if (sv > pm && lane == (ps & 31)){
                            pool[ps] = sv;
                            pidx[ps] = t*128 + seg*32 + b;
                        }
                        mv = pm;   // fresh lower bound (pre-replacement min)
                        __syncwarp();
                    }
                }
                if (lane == 0) minsh[q] = mv;
            }
            __syncthreads();
        }
    }
    if (tid < 64){
        for (int n = 0; n < NP_; n++)
            g_pooli[((size_t)h * S_ + q0 + tid) * NP_ + n] = Ti[tid*NP_ + n];
    }
}

// ---- exact fp32 rescore of 64 candidates -> true top-32 ----
__global__ void rescore_kernel(const float* __restrict__ mem_keys)
{
    __shared__ float ssc[4][NP_];
    __shared__ int   sid[4][NP_];
    const int lane = threadIdx.x & 31, w = threadIdx.x >> 5;
    const int h = blockIdx.y;
    const int q = blockIdx.x * 4 + w;
    const size_t qi = (size_t)h * S_ + q;

    float4 qv = ((const float4*)(g_q + qi * DH_))[lane];
    for (int c = lane; c < NP_; c += 32) sid[w][c] = g_pooli[qi * NP_ + c];
    __syncwarp();

    for (int c = 0; c < NP_; c++){
        float4 kv = ((const float4*)(mem_keys + ((size_t)h * MK_ + sid[w][c]) * DH_))[lane];
        float d = qv.x*kv.x + qv.y*kv.y + qv.z*kv.z + qv.w*kv.w;
#pragma unroll
        for (int o = 16; o > 0; o >>= 1) d += __shfl_xor_sync(0xffffffffu, d, o);
        if (lane == 0) ssc[w][c] = d;
    }
    __syncwarp();

    float v1 = ssc[w][lane];
    float v2 = ssc[w][32 + lane];
    for (int it = 0; it < NN_; it++){
        float mvv; int mi;
        if (v1 >= v2){ mvv = v1; mi = lane; } else { mvv = v2; mi = 32 + lane; }
#pragma unroll
        for (int o = 16; o > 0; o >>= 1){
            float ov = __shfl_xor_sync(0xffffffffu, mvv, o);
            int   oi = __shfl_xor_sync(0xffffffffu, mi, o);
            if (ov > mvv || (ov == mvv && oi < mi)){ mvv = ov; mi = oi; }
        }
        if (mi < 32){ if (lane == mi) v1 = -3.0e38f; }
        else        { if (lane == mi - 32) v2 = -3.0e38f; }
        if (lane == 0){
            g_topv[qi * NN_ + it] = mvv;
            g_topi[qi * NN_ + it] = sid[w][mi];
        }
    }
}

// ---- flash attention (parallel softmax) ----
#define K4_SMEM ((128 * 68 + 128 * 68 + 64 * 65 + 192 + 64 * 32) * 4)
__global__ void attn_kernel(const float* __restrict__ am,
                            const float* __restrict__ scale_param,
                            const float* __restrict__ mem_values)
{
    extern __shared__ float sm[];
    float* Qs  = sm;
    float* KV  = Qs + 128 * 68;
    float* Sc  = KV + 128 * 68;
    float* msh = Sc + 64 * 65;
    float* lsh = msh + 64;
    float* csh = lsh + 64;
    int*   Ti  = (int*)(csh + 64);

    const int tid = threadIdx.x;
    const int h   = blockIdx.y;
    const int q0  = blockIdx.x * 64;
    const int ty  = tid >> 4, tx = tid & 15;
    const int srow = tid >> 2, sl4 = tid & 3;
    const float scale = expf(scale_param[h]);

    for (int idx = tid; idx < 64 * 32; idx += 256) {
        int row = idx >> 5, seg = idx & 31;
        float4 v = *(const float4*)(g_q + ((size_t)h * S_ + q0 + row) * DH_ + seg * 4);
        Qs[(seg*4+0)*68+row] = v.x; Qs[(seg*4+1)*68+row] = v.y;
        Qs[(seg*4+2)*68+row] = v.z; Qs[(seg*4+3)*68+row] = v.w;
    }
    for (int idx = tid; idx < 64 * 32; idx += 256) {
        int q = idx >> 5, n = idx & 31;
        Sc[q*65+n] = g_topv[((size_t)h * S_ + q0 + q) * NN_ + n] * scale;
        Ti[q*32+n] = g_topi[((size_t)h * S_ + q0 + q) * NN_ + n];
    }
    __syncthreads();

    {   // mem softmax init: 64 rows x 4 lanes (8 cols each)
        float mm = -3.0e38f;
#pragma unroll
        for (int j = 0; j < 8; j++) mm = fmaxf(mm, Sc[srow*65 + sl4*8 + j]);
        mm = fmaxf(mm, __shfl_xor_sync(0xffffffffu, mm, 1));
        mm = fmaxf(mm, __shfl_xor_sync(0xffffffffu, mm, 2));
        float ll = 0.f;
#pragma unroll
        for (int j = 0; j < 8; j++){
            float p = expf(Sc[srow*65 + sl4*8 + j] - mm);
            Sc[srow*65 + sl4*8 + j] = p; ll += p;
        }
        ll += __shfl_xor_sync(0xffffffffu, ll, 1);
        ll += __shfl_xor_sync(0xffffffffu, ll, 2);
        if (sl4 == 0){ msh[srow] = mm; lsh[srow] = ll; }
    }
    __syncthreads();

    float oacc[4][8];
#pragma unroll
    for (int i = 0; i < 4; i++)
#pragma unroll
        for (int j = 0; j < 8; j++) oacc[i][j] = 0.f;

#pragma unroll
    for (int i = 0; i < 4; i++) {
        int qr = ty * 4 + i;
        for (int n = 0; n < NN_; n++) {
            float w = Sc[qr*65+n];
            const float4* vr = (const float4*)(mem_values +
                ((size_t)h * MK_ + Ti[qr*32+n]) * DH_ + tx * 8);
            float4 v0 = vr[0], v1 = vr[1];
            oacc[i][0]+=w*v0.x; oacc[i][1]+=w*v0.y; oacc[i][2]+=w*v0.z; oacc[i][3]+=w*v0.w;
            oacc[i][4]+=w*v1.x; oacc[i][5]+=w*v1.y; oacc[i][6]+=w*v1.z; oacc[i][7]+=w*v1.w;
        }
    }

    const int kcmax = q0 / 64;
    for (int kc = 0; kc <= kcmax; kc++) {
        __syncthreads();
        for (int idx = tid; idx < 64 * 32; idx += 256) {
            int row = idx >> 5, seg = idx & 31;
            float4 v = *(const float4*)(g_k + ((size_t)h * S_ + kc*64 + row) * DH_ + seg * 4);
            KV[(seg*4+0)*68+row] = v.x; KV[(seg*4+1)*68+row] = v.y;
            KV[(seg*4+2)*68+row] = v.z; KV[(seg*4+3)*68+row] = v.w;
        }
        __syncthreads();

        float sc4[4][4];
#pragma unroll
        for (int i = 0; i < 4; i++)
#pragma unroll
            for (int j = 0; j < 4; j++) sc4[i][j] = 0.f;

#pragma unroll 8
        for (int kd = 0; kd < DH_; kd++) {
            float4 aq = *(const float4*)&Qs[kd*68 + ty*4];
            float4 bk = *(const float4*)&KV[kd*68 + tx*4];
            float a[4] = {aq.x, aq.y, aq.z, aq.w};
            float b[4] = {bk.x, bk.y, bk.z, bk.w};
#pragma unroll
            for (int i = 0; i < 4; i++)
#pragma unroll
                for (int j = 0; j < 4; j++) sc4[i][j] += a[i] * b[j];
        }
#pragma unroll
        for (int i = 0; i < 4; i++) {
            int qg = q0 + ty*4 + i;
#pragma unroll
            for (int j = 0; j < 4; j++) {
                int kg = kc*64 + tx*4 + j;
                float v = (kg <= qg) ? (sc4[i][j] * scale + am[kg]) : -1.0e30f;
                Sc[(ty*4+i)*65 + tx*4+j] = v;
            }
        }
        __syncthreads();

        {   // chunk softmax: 64 rows x 4 lanes (16 cols each)
            float mm = msh[srow], rmax = mm;
#pragma unroll
            for (int j = 0; j < 16; j++) rmax = fmaxf(rmax, Sc[srow*65 + sl4*16 + j]);
            rmax = fmaxf(rmax, __shfl_xor_sync(0xffffffffu, rmax, 1));
            rmax = fmaxf(rmax, __shfl_xor_sync(0xffffffffu, rmax, 2));
            float cor = expf(mm - rmax);
            float ll = (sl4 == 0) ? lsh[srow] * cor : 0.f;
#pragma unroll
            for (int j = 0; j < 16; j++){
                float p = expf(Sc[srow*65 + sl4*16 + j] - rmax);
                Sc[srow*65 + sl4*16 + j] = p; ll += p;
            }
            ll += __shfl_xor_sync(0xffffffffu, ll, 1);
            ll += __shfl_xor_sync(0xffffffffu, ll, 2);
            if (sl4 == 0){ msh[srow] = rmax; lsh[srow] = ll; csh[srow] = cor; }
        }
        __syncthreads();

        for (int idx = tid; idx < 64 * 32; idx += 256) {
            int row = idx >> 5, seg = idx & 31;
            float4 v = *(const float4*)(g_v + ((size_t)h * S_ + kc*64 + row) * DH_ + seg * 4);
            *(float4*)&KV[row*132 + seg*4] = v;
        }
        __syncthreads();

#pragma unroll
        for (int i = 0; i < 4; i++) {
            int qr = ty*4 + i;
            float cor = csh[qr];
#pragma unroll
            for (int j = 0; j < 8; j++) oacc[i][j] *= cor;
            for (int n = 0; n < 64; n++) {
                float w = Sc[qr*65+n];
                float4 v0 = *(const float4*)&KV[n*132 + tx*8];
                float4 v1 = *(const float4*)&KV[n*132 + tx*8 + 4];
                oacc[i][0]+=w*v0.x; oacc[i][1]+=w*v0.y; oacc[i][2]+=w*v0.z; oacc[i][3]+=w*v0.w;
                oacc[i][4]+=w*v1.x; oacc[i][5]+=w*v1.y; oacc[i][6]+=w*v1.z; oacc[i][7]+=w*v1.w;
            }
        }
    }

#pragma unroll
    for (int i = 0; i < 4; i++) {
        int qr = ty*4 + i;
        float inv = 1.0f / lsh[qr];
#pragma unroll
        for (int j = 0; j < 8; j++)
            g_ctx[(size_t)(q0+qr) * H_ + h*DH_ + tx*8 + j] = oacc[i][j] * inv;
    }
}

extern "C" void kernel_launch(void* const* d_in, const int* in_sizes, int n_in,
                              void* d_out, int out_size)
{
    const float* hidden      = (const float*)d_in[0];
    const float* am          = (const float*)d_in[1];
    const int*   pos         = (const int*)d_in[2];
    const float* Wqkv        = (const float*)d_in[3];
    const float* bqkv        = (const float*)d_in[4];
    const float* Wd          = (const float*)d_in[5];
    const float* bd          = (const float*)d_in[6];
    const float* scale_param = (const float*)d_in[7];
    const float* mem_keys    = (const float*)d_in[8];
    const float* mem_values  = (const float*)d_in[9];
    float*       out         = (float*)d_out;

    cudaFuncSetAttribute(out_mma_kernel,  cudaFuncAttributeMaxDynamicSharedMemorySize, GEMM_SMEM);
    cudaFuncSetAttribute(knn_pool_kernel, cudaFuncAttributeMaxDynamicSharedMemorySize, KNP_SMEM);
    cudaFuncSetAttribute(attn_kernel,     cudaFuncAttributeMaxDynamicSharedMemorySize, K4_SMEM);

    qkv_gemm_kernel<<<dim3(HQKV_/128, S_/128), 256>>>(hidden, Wqkv, bqkv);
    norm_rope_kernel<<<dim3(S_, NH_), 128>>>(pos);
    knn_pool_kernel<<<dim3(S_/64, NH_), 256, KNP_SMEM>>>(mem_keys);
    rescore_kernel<<<dim3(S_/4, NH_), 128>>>(mem_keys);
    attn_kernel<<<dim3(S_/64, NH_), 256, K4_SMEM>>>(am, scale_param, mem_values);

    split_kernel<<<512,  256>>>(hidden, S_ * H_, H_, 3);
    split_kernel<<<1024, 256>>>(Wd,     H_ * H_, H_, 4);
    out_mma_kernel<<<dim3(H_/128, S_/128), 256, GEMM_SMEM>>>(bd, out);
}

// round 10
// speedup vs baseline: 1.5057x; 1.2516x over previous
#include <cuda_runtime.h>
#include <math.h>
#include <stdint.h>

#define S_    1024
#define H_    2048
#define NH_   16
#define DH_   128
#define NN_   32
#define NP_   64
#define MK_   8192
#define HQKV_ 6144
#define KB_   6144

__device__ __align__(16) float g_qkv[S_ * HQKV_];
__device__ __align__(16) float g_q  [NH_ * S_ * DH_];
__device__ __align__(16) float g_k  [NH_ * S_ * DH_];
__device__ __align__(16) float g_v  [NH_ * S_ * DH_];
__device__ __align__(16) float g_ctx[S_ * H_];
__device__ __align__(16) float g_topv[NH_ * S_ * NN_];
__device__ __align__(16) int   g_topi[NH_ * S_ * NN_];
__device__ __align__(16) int   g_pooli[NH_ * S_ * NP_];

__device__ __align__(16) float g_ctx_s[S_ * KB_];
__device__ __align__(16) float g_wd_s [(size_t)H_ * KB_];

static __device__ __forceinline__ uint32_t smem_u32(const void* p){
    uint32_t a;
    asm("{ .reg .u64 t; cvta.to.shared.u64 t, %1; cvt.u32.u64 %0, t; }" : "=r"(a) : "l"(p));
    return a;
}
__device__ __forceinline__ int SWZ(int x){ return x ^ ((x >> 3) & 0x70); }
__device__ __forceinline__ float to_tf32(float x){
    float r; asm("cvt.rna.tf32.f32 %0, %1;" : "=f"(r) : "f"(x)); return r;
}
__device__ __forceinline__ void ldsm4(uint32_t* r, uint32_t a){
    asm volatile("ldmatrix.sync.aligned.m8n8.x4.shared.b16 {%0,%1,%2,%3}, [%4];"
        : "=r"(r[0]), "=r"(r[1]), "=r"(r[2]), "=r"(r[3]) : "r"(a));
}
__device__ __forceinline__ void mmat(float* c, const uint32_t* a, uint32_t b0, uint32_t b1){
    asm volatile(
        "mma.sync.aligned.m16n8k8.row.col.f32.tf32.tf32.f32 "
        "{%0,%1,%2,%3}, {%4,%5,%6,%7}, {%8,%9}, {%0,%1,%2,%3};"
        : "+f"(c[0]), "+f"(c[1]), "+f"(c[2]), "+f"(c[3])
        : "r"(a[0]), "r"(a[1]), "r"(a[2]), "r"(a[3]), "r"(b0), "r"(b1));
}

template<int MT>
__device__ __forceinline__ void mma_chunk(uint32_t sA, uint32_t sB,
                                          int lane, int wm, int wn, float* acc){
    const int rl = lane & 15, uh = lane >> 4;
#pragma unroll
    for (int ks = 0; ks < 4; ks++){
        uint32_t a[MT][4], b[2][4];
#pragma unroll
        for (int mt = 0; mt < MT; mt++)
            ldsm4(a[mt], sA + SWZ((wm*(MT*16) + mt*16 + rl)*128 + (ks*2+uh)*16));
#pragma unroll
        for (int bt = 0; bt < 2; bt++)
            ldsm4(b[bt], sB + SWZ((wn*32 + bt*16 + rl)*128 + (ks*2+uh)*16));
#pragma unroll
        for (int mt = 0; mt < MT; mt++)
#pragma unroll
            for (int nt = 0; nt < 4; nt++)
                mmat(acc + (mt*4+nt)*4, a[mt], b[nt>>1][nt&1], b[nt>>1][(nt&1)+2]);
    }
}

// ---- splits for out-GEMM (ctx = A-type [h|l|h], Wd = B-type [h|h|l]) ----
__global__ void split_kernel(const float* __restrict__ src, int total, int Kc, int which)
{
    const float* s = src; float* d; int atype = 0;
    if (which == 3) { s = g_ctx; d = g_ctx_s; atype = 1; } else { d = g_wd_s; }
    for (int i = blockIdx.x * blockDim.x + threadIdx.x; i < total;
         i += gridDim.x * blockDim.x) {
        float x  = s[i];
        float hi = to_tf32(x);
        float lo = to_tf32(x - hi);
        int r = i / Kc, k = i - r * Kc;
        size_t base = (size_t)r * 3 * Kc + k;
        d[base] = hi;
        d[base + Kc]     = atype ? lo : hi;
        d[base + 2 * Kc] = atype ? hi : lo;
    }
}

// ---- tf32 MMA out-GEMM ----
#define GEMM_SMEM 65536
__global__ void __launch_bounds__(256) out_mma_kernel(const float* __restrict__ bias,
                                                      float* __restrict__ C)
{
    extern __shared__ char smraw[];
    uint32_t sb = smem_u32(smraw);
    const float* A = g_ctx_s; const float* B = g_wd_s;
    const int N = H_, K = KB_;
    const int tid = threadIdx.x, lane = tid & 31, wid = tid >> 5;
    const int wm = wid >> 2, wn = wid & 3;
    const int m0 = blockIdx.y * 128, n0 = blockIdx.x * 128;
    const int nch = K >> 5;

    float acc[64];
#pragma unroll
    for (int i = 0; i < 64; i++) acc[i] = 0.f;

#pragma unroll
    for (int i = 0; i < 4; i++){
        int g = tid + i * 256, r = g >> 3, u = g & 7;
        uint4 va = ((const uint4*)(A + (size_t)(m0 + r) * K))[u];
        uint4 vb = ((const uint4*)(B + (size_t)(n0 + r) * K))[u];
        *(uint4*)(smraw + SWZ(r*128 + u*16)) = va;
        *(uint4*)(smraw + 32768 + SWZ(r*128 + u*16)) = vb;
    }
    __syncthreads();

    for (int c = 0; c < nch; c++){
        const int buf = c & 1;
        uint4 pa[4], pb[4];
        if (c + 1 < nch){
#pragma unroll
            for (int i = 0; i < 4; i++){
                int g = tid + i * 256, r = g >> 3, u = g & 7;
                pa[i] = ((const uint4*)(A + (size_t)(m0 + r) * K))[(c+1)*8 + u];
                pb[i] = ((const uint4*)(B + (size_t)(n0 + r) * K))[(c+1)*8 + u];
            }
        }
        mma_chunk<4>(sb + buf*16384, sb + 32768 + buf*16384, lane, wm, wn, acc);
        if (c + 1 < nch){
            int nb = buf ^ 1;
#pragma unroll
            for (int i = 0; i < 4; i++){
                int g = tid + i * 256, r = g >> 3, u = g & 7;
                *(uint4*)(smraw + nb*16384 + SWZ(r*128 + u*16)) = pa[i];
                *(uint4*)(smraw + 32768 + nb*16384 + SWZ(r*128 + u*16)) = pb[i];
            }
        }
        __syncthreads();
    }

    const int gr = lane >> 2, gc2 = (lane & 3) * 2;
#pragma unroll
    for (int mt = 0; mt < 4; mt++)
#pragma unroll
        for (int nt = 0; nt < 4; nt++){
            const float* cp = acc + (mt*4+nt)*4;
            int r = m0 + wm*64 + mt*16 + gr;
            int col = n0 + wn*32 + nt*8 + gc2;
            float b0 = bias[col], b1 = bias[col+1];
            *(float2*)(C + (size_t)r * N + col)     = make_float2(cp[0]+b0, cp[1]+b1);
            *(float2*)(C + (size_t)(r+8) * N + col) = make_float2(cp[2]+b0, cp[3]+b1);
        }
}

// ---- SIMT fp32 qkv GEMM (q must stay exact for top-k) ----
__global__ void qkv_gemm_kernel(const float* __restrict__ A,
                                const float* __restrict__ B,
                                const float* __restrict__ bias)
{
    const int N = HQKV_, K = H_;
    __shared__ float As[8 * 128];
    __shared__ float Bs[8 * 128];
    const int tid  = threadIdx.x;
    const int m0   = blockIdx.y * 128;
    const int n0   = blockIdx.x * 128;
    const int ty   = tid >> 4, tx = tid & 15;
    const int lrow = tid >> 1, lk4 = (tid & 1) * 4;

    float c[8][8];
#pragma unroll
    for (int i = 0; i < 8; i++)
#pragma unroll
        for (int j = 0; j < 8; j++) c[i][j] = 0.f;

    const float* Ab = A + (size_t)(m0 + lrow) * K + lk4;
    const float* Bb = B + (size_t)(n0 + lrow) * K + lk4;

    for (int k0 = 0; k0 < K; k0 += 8) {
        float4 av = *(const float4*)(Ab + k0);
        float4 bv = *(const float4*)(Bb + k0);
        As[(lk4+0)*128+lrow] = av.x; As[(lk4+1)*128+lrow] = av.y;
        As[(lk4+2)*128+lrow] = av.z; As[(lk4+3)*128+lrow] = av.w;
        Bs[(lk4+0)*128+lrow] = bv.x; Bs[(lk4+1)*128+lrow] = bv.y;
        Bs[(lk4+2)*128+lrow] = bv.z; Bs[(lk4+3)*128+lrow] = bv.w;
        __syncthreads();
#pragma unroll
        for (int kk = 0; kk < 8; kk++) {
            float a[8], b[8];
            *(float4*)&a[0] = *(const float4*)&As[kk*128 + ty*8];
            *(float4*)&a[4] = *(const float4*)&As[kk*128 + ty*8 + 4];
            *(float4*)&b[0] = *(const float4*)&Bs[kk*128 + tx*8];
            *(float4*)&b[4] = *(const float4*)&Bs[kk*128 + tx*8 + 4];
#pragma unroll
            for (int i = 0; i < 8; i++)
#pragma unroll
                for (int j = 0; j < 8; j++) c[i][j] += a[i] * b[j];
        }
        __syncthreads();
    }
#pragma unroll
    for (int i = 0; i < 8; i++) {
        int row = m0 + ty * 8 + i;
#pragma unroll
        for (int j = 0; j < 8; j++) {
            int col = n0 + tx * 8 + j;
            g_qkv[(size_t)row * N + col] = c[i][j] + bias[col];
        }
    }
}

// ---- norm + rope ----
__global__ void norm_rope_kernel(const int* __restrict__ pos)
{
    const int s = blockIdx.x, h = blockIdx.y, d = threadIdx.x;
    const float* base = g_qkv + (size_t)s * HQKV_ + h * (3 * DH_);
    float qv = base[d], kv = base[DH_ + d], vv = base[2 * DH_ + d];

    float sq = qv * qv, sk = kv * kv;
#pragma unroll
    for (int o = 16; o > 0; o >>= 1) {
        sq += __shfl_xor_sync(0xffffffffu, sq, o);
        sk += __shfl_xor_sync(0xffffffffu, sk, o);
    }
    __shared__ float rq[4], rk[4];
    if ((d & 31) == 0) { rq[d >> 5] = sq; rk[d >> 5] = sk; }
    __syncthreads();
    float nq = sqrtf(rq[0] + rq[1] + rq[2] + rq[3]);
    float nk = sqrtf(rk[0] + rk[1] + rk[2] + rk[3]);
    float qn = qv / fmaxf(nq, 1e-12f);
    float kn = kv / fmaxf(nk, 1e-12f);

    __shared__ float qs[DH_], ks[DH_];
    qs[d] = qn; ks[d] = kn;
    __syncthreads();

    float qo = qn, ko = kn;
    if (d < 32) {
        int i = (d < 16) ? d : d - 16;
        float freq = powf(10000.0f, -(float)i / 16.0f);
        float ang  = (float)pos[s] * freq;
        float cs = cosf(ang), sn = sinf(ang);
        float rqh = (d < 16) ? -qs[d + 16] : qs[d - 16];
        float rkh = (d < 16) ? -ks[d + 16] : ks[d - 16];
        qo = qn * cs + rqh * sn;
        ko = kn * cs + rkh * sn;
    }
    size_t o = ((size_t)h * S_ + s) * DH_ + d;
    g_q[o] = qo; g_k[o] = ko; g_v[o] = vv;
}

// ---- kNN pool: tf32 MMA scores + register-pool half-warp top-64 ----
// smem: A 32KB | B 2x16KB | Sc [64][130] 33280B | Ti u16 [64][64] 8192B
#define KNA   0
#define KNB   32768
#define KNSC  65536
#define KNTI  98816
#define KNP_SMEM 107008
__global__ void __launch_bounds__(256, 2) knn_pool_kernel(const float* __restrict__ mem_keys)
{
    extern __shared__ char smraw[];
    uint32_t sb = smem_u32(smraw);
    const int tid = threadIdx.x, lane = tid & 31, wid = tid >> 5;
    const int wm = wid >> 2, wn = wid & 3;
    const int h = blockIdx.y, q0 = blockIdx.x * 64;
    float* Sc = (float*)(smraw + KNSC);                  // [64][130]
    unsigned short* Ti = (unsigned short*)(smraw + KNTI);// [64][64]

    const int half = lane >> 4, hl = lane & 15;
    const unsigned hmask = half ? 0xffff0000u : 0x0000ffffu;
    const int qbase = wid * 8;

    {   // resident A: 64 q rows x 128 fp32 -> 4 chunk tiles of 8KB
        int r = tid >> 2, part = tid & 3;
        const uint4* Ar = (const uint4*)(g_q + ((size_t)h * S_ + q0 + r) * DH_);
#pragma unroll
        for (int j = 0; j < 8; j++)
            *(uint4*)(smraw + KNA + part*8192 + SWZ(r*128 + j*16)) = Ar[part*8 + j];
    }
#pragma unroll
    for (int i = 0; i < 4; i++){
        int g = tid + i * 256, r = g >> 3, u = g & 7;
        uint4 v = ((const uint4*)(mem_keys + ((size_t)h * MK_ + r) * DH_))[u];
        *(uint4*)(smraw + KNB + SWZ(r*128 + u*16)) = v;
    }
    __syncthreads();

    float pv[4][4];            // [pair][slot] register pool values
    float mv[4];               // per-pair pool min
#pragma unroll
    for (int p = 0; p < 4; p++){
        mv[p] = -3.0e38f;
#pragma unroll
        for (int j = 0; j < 4; j++) pv[p][j] = -3.0e38f;
    }

    float acc[32];
#pragma unroll
    for (int i = 0; i < 32; i++) acc[i] = 0.f;

    for (int g = 0; g < 64 * 4; g++){
        const int t = g >> 2, ci = g & 3;
        const int buf = g & 1;
        uint4 pb[4];
        if (g + 1 < 64 * 4){
            int tn = (g + 1) >> 2, cn = (g + 1) & 3;
#pragma unroll
            for (int i = 0; i < 4; i++){
                int gi = tid + i * 256, r = gi >> 3, u = gi & 7;
                pb[i] = ((const uint4*)(mem_keys +
                         ((size_t)h * MK_ + tn * 128 + r) * DH_))[cn*8 + u];
            }
        }
        mma_chunk<2>(sb + KNA + ci*8192, sb + KNB + buf*16384, lane, wm, wn, acc);
        if (g + 1 < 64 * 4){
            int nb = buf ^ 1;
#pragma unroll
            for (int i = 0; i < 4; i++){
                int gi = tid + i * 256, r = gi >> 3, u = gi & 7;
                *(uint4*)(smraw + KNB + nb*16384 + SWZ(r*128 + u*16)) = pb[i];
            }
        }
        __syncthreads();

        if (ci == 3){
            const int gr = lane >> 2, gc2 = (lane & 3) * 2;
#pragma unroll
            for (int mt = 0; mt < 2; mt++)
#pragma unroll
                for (int nt = 0; nt < 4; nt++){
                    float* cp = acc + (mt*4+nt)*4;
                    int r = wm*32 + mt*16 + gr, col = wn*32 + nt*8 + gc2;
                    *(float2*)(Sc + r*130 + col)     = make_float2(cp[0], cp[1]);
                    *(float2*)(Sc + (r+8)*130 + col) = make_float2(cp[2], cp[3]);
                }
#pragma unroll
            for (int i = 0; i < 32; i++) acc[i] = 0.f;
            __syncthreads();

            // dual-query half-warp pool maintenance (warp owns 8 queries = 4 pairs)
            for (int p = 0; p < 4; p++){
                const int q = qbase + p*2 + half;
                const float* srow = Sc + q*130;
                float m_ = mv[p];
                int seg0 = 0;
                if (t == 0){
                    // seed pool with tile-0 columns 0..63
#pragma unroll
                    for (int j = 0; j < 4; j++){
                        pv[p][j] = srow[hl*4 + j];
                        Ti[q*64 + hl*4 + j] = (unsigned short)(hl*4 + j);
                    }
                    float pm = pv[p][0];
#pragma unroll
                    for (int j = 1; j < 4; j++) pm = fminf(pm, pv[p][j]);
#pragma unroll
                    for (int o = 8; o > 0; o >>= 1)
                        pm = fminf(pm, __shfl_xor_sync(hmask, pm, o));
                    m_ = pm;
                    seg0 = 4;
                }
                for (int seg = seg0; seg < 8; seg++){
                    float s = srow[seg*16 + hl];
                    unsigned bal = __ballot_sync(0xffffffffu, s > m_);
                    unsigned m = (bal >> (half*16)) & 0xffffu;
                    while (m){
                        int b = __ffs(m) - 1; m &= m - 1;
                        float sv = __shfl_sync(hmask, s, half*16 + b);
                        float pm = pv[p][0]; int pc = 0;
#pragma unroll
                        for (int j = 1; j < 4; j++)
                            if (pv[p][j] < pm){ pm = pv[p][j]; pc = j; }
                        int code = hl*4 + pc;
#pragma unroll
                        for (int o = 8; o > 0; o >>= 1){
                            float ov = __shfl_xor_sync(hmask, pm, o);
                            int   oc = __shfl_xor_sync(hmask, code, o);
                            if (ov < pm || (ov == pm && oc < code)){ pm = ov; code = oc; }
                        }
                        if (sv > pm && hl == (code >> 2)){
                            pv[p][code & 3] = sv;
                            Ti[q*64 + code] = (unsigned short)(t*128 + seg*16 + b);
                        }
                        m_ = pm;
                    }
                }
                mv[p] = m_;
            }
            __syncthreads();
        }
    }
    for (int i = tid; i < 64 * NP_; i += 256)
        g_pooli[((size_t)h * S_ + q0 + (i >> 6)) * NP_ + (i & 63)] = (int)Ti[i];
}

// ---- exact fp32 rescore of 64 candidates -> true top-32 ----
__global__ void rescore_kernel(const float* __restrict__ mem_keys)
{
    __shared__ float ssc[4][NP_];
    __shared__ int   sid[4][NP_];
    const int lane = threadIdx.x & 31, w = threadIdx.x >> 5;
    const int h = blockIdx.y;
    const int q = blockIdx.x * 4 + w;
    const size_t qi = (size_t)h * S_ + q;

    float4 qv = ((const float4*)(g_q + qi * DH_))[lane];
    for (int c = lane; c < NP_; c += 32) sid[w][c] = g_pooli[qi * NP_ + c];
    __syncwarp();

    for (int c = 0; c < NP_; c++){
        float4 kv = ((const float4*)(mem_keys + ((size_t)h * MK_ + sid[w][c]) * DH_))[lane];
        float d = qv.x*kv.x + qv.y*kv.y + qv.z*kv.z + qv.w*kv.w;
#pragma unroll
        for (int o = 16; o > 0; o >>= 1) d += __shfl_xor_sync(0xffffffffu, d, o);
        if (lane == 0) ssc[w][c] = d;
    }
    __syncwarp();

    float v1 = ssc[w][lane];
    float v2 = ssc[w][32 + lane];
    for (int it = 0; it < NN_; it++){
        float mvv; int mi;
        if (v1 >= v2){ mvv = v1; mi = lane; } else { mvv = v2; mi = 32 + lane; }
#pragma unroll
        for (int o = 16; o > 0; o >>= 1){
            float ov = __shfl_xor_sync(0xffffffffu, mvv, o);
            int   oi = __shfl_xor_sync(0xffffffffu, mi, o);
            if (ov > mvv || (ov == mvv && oi < mi)){ mvv = ov; mi = oi; }
        }
        if (mi < 32){ if (lane == mi) v1 = -3.0e38f; }
        else        { if (lane == mi - 32) v2 = -3.0e38f; }
        if (lane == 0){
            g_topv[qi * NN_ + it] = mvv;
            g_topi[qi * NN_ + it] = sid[w][mi];
        }
    }
}

// ---- flash attention (parallel softmax, heavy-first scheduling) ----
#define K4_SMEM ((128 * 68 + 128 * 68 + 64 * 65 + 192 + 64 * 32) * 4)
__global__ void attn_kernel(const float* __restrict__ am,
                            const float* __restrict__ scale_param,
                            const float* __restrict__ mem_values)
{
    extern __shared__ float sm[];
    float* Qs  = sm;
    float* KV  = Qs + 128 * 68;
    float* Sc  = KV + 128 * 68;
    float* msh = Sc + 64 * 65;
    float* lsh = msh + 64;
    float* csh = lsh + 64;
    int*   Ti  = (int*)(csh + 64);

    const int tid = threadIdx.x;
    const int h   = blockIdx.y;
    const int q0  = (gridDim.x - 1 - blockIdx.x) * 64;   // heavy tiles first
    const int ty  = tid >> 4, tx = tid & 15;
    const int srow = tid >> 2, sl4 = tid & 3;
    const float scale = expf(scale_param[h]);

    for (int idx = tid; idx < 64 * 32; idx += 256) {
        int row = idx >> 5, seg = idx & 31;
        float4 v = *(const float4*)(g_q + ((size_t)h * S_ + q0 + row) * DH_ + seg * 4);
        Qs[(seg*4+0)*68+row] = v.x; Qs[(seg*4+1)*68+row] = v.y;
        Qs[(seg*4+2)*68+row] = v.z; Qs[(seg*4+3)*68+row] = v.w;
    }
    for (int idx = tid; idx < 64 * 32; idx += 256) {
        int q = idx >> 5, n = idx & 31;
        Sc[q*65+n] = g_topv[((size_t)h * S_ + q0 + q) * NN_ + n] * scale;
        Ti[q*32+n] = g_topi[((size_t)h * S_ + q0 + q) * NN_ + n];
    }
    __syncthreads();

    {
        float mm = -3.0e38f;
#pragma unroll
        for (int j = 0; j < 8; j++) mm = fmaxf(mm, Sc[srow*65 + sl4*8 + j]);
        mm = fmaxf(mm, __shfl_xor_sync(0xffffffffu, mm, 1));
        mm = fmaxf(mm, __shfl_xor_sync(0xffffffffu, mm, 2));
        float ll = 0.f;
#pragma unroll
        for (int j = 0; j < 8; j++){
            float p = expf(Sc[srow*65 + sl4*8 + j] - mm);
            Sc[srow*65 + sl4*8 + j] = p; ll += p;
        }
        ll += __shfl_xor_sync(0xffffffffu, ll, 1);
        ll += __shfl_xor_sync(0xffffffffu, ll, 2);
        if (sl4 == 0){ msh[srow] = mm; lsh[srow] = ll; }
    }
    __syncthreads();

    float oacc[4][8];
#pragma unroll
    for (int i = 0; i < 4; i++)
#pragma unroll
        for (int j = 0; j < 8; j++) oacc[i][j] = 0.f;

#pragma unroll
    for (int i = 0; i < 4; i++) {
        int qr = ty * 4 + i;
        for (int n = 0; n < NN_; n++) {
            float w = Sc[qr*65+n];
            const float4* vr = (const float4*)(mem_values +
                ((size_t)h * MK_ + Ti[qr*32+n]) * DH_ + tx * 8);
            float4 v0 = vr[0], v1 = vr[1];
            oacc[i][0]+=w*v0.x; oacc[i][1]+=w*v0.y; oacc[i][2]+=w*v0.z; oacc[i][3]+=w*v0.w;
            oacc[i][4]+=w*v1.x; oacc[i][5]+=w*v1.y; oacc[i][6]+=w*v1.z; oacc[i][7]+=w*v1.w;
        }
    }

    const int kcmax = q0 / 64;
    for (int kc = 0; kc <= kcmax; kc++) {
        __syncthreads();
        for (int idx = tid; idx < 64 * 32; idx += 256) {
            int row = idx >> 5, seg = idx & 31;
            float4 v = *(const float4*)(g_k + ((size_t)h * S_ + kc*64 + row) * DH_ + seg * 4);
            KV[(seg*4+0)*68+row] = v.x; KV[(seg*4+1)*68+row] = v.y;
            KV[(seg*4+2)*68+row] = v.z; KV[(seg*4+3)*68+row] = v.w;
        }
        __syncthreads();

        float sc4[4][4];
#pragma unroll
        for (int i = 0; i < 4; i++)
#pragma unroll
            for (int j = 0; j < 4; j++) sc4[i][j] = 0.f;

#pragma unroll 8
        for (int kd = 0; kd < DH_; kd++) {
            float4 aq = *(const float4*)&Qs[kd*68 + ty*4];
            float4 bk = *(const float4*)&KV[kd*68 + tx*4];
            float a[4] = {aq.x, aq.y, aq.z, aq.w};
            float b[4] = {bk.x, bk.y, bk.z, bk.w};
#pragma unroll
            for (int i = 0; i < 4; i++)
#pragma unroll
                for (int j = 0; j < 4; j++) sc4[i][j] += a[i] * b[j];
        }
#pragma unroll
        for (int i = 0; i < 4; i++) {
            int qg = q0 + ty*4 + i;
#pragma unroll
            for (int j = 0; j < 4; j++) {
                int kg = kc*64 + tx*4 + j;
                float v = (kg <= qg) ? (sc4[i][j] * scale + am[kg]) : -1.0e30f;
                Sc[(ty*4+i)*65 + tx*4+j] = v;
            }
        }
        __syncthreads();

        {
            float mm = msh[srow], rmax = mm;
#pragma unroll
            for (int j = 0; j < 16; j++) rmax = fmaxf(rmax, Sc[srow*65 + sl4*16 + j]);
            rmax = fmaxf(rmax, __shfl_xor_sync(0xffffffffu, rmax, 1));
            rmax = fmaxf(rmax, __shfl_xor_sync(0xffffffffu, rmax, 2));
            float cor = expf(mm - rmax);
            float ll = (sl4 == 0) ? lsh[srow] * cor : 0.f;
#pragma unroll
            for (int j = 0; j < 16; j++){
                float p = expf(Sc[srow*65 + sl4*16 + j] - rmax);
                Sc[srow*65 + sl4*16 + j] = p; ll += p;
            }
            ll += __shfl_xor_sync(0xffffffffu, ll, 1);
            ll += __shfl_xor_sync(0xffffffffu, ll, 2);
            if (sl4 == 0){ msh[srow] = rmax; lsh[srow] = ll; csh[srow] = cor; }
        }
        __syncthreads();

        for (int idx = tid; idx < 64 * 32; idx += 256) {
            int row = idx >> 5, seg = idx & 31;
            float4 v = *(const float4*)(g_v + ((size_t)h * S_ + kc*64 + row) * DH_ + seg * 4);
            *(float4*)&KV[row*132 + seg*4] = v;
        }
        __syncthreads();

#pragma unroll
        for (int i = 0; i < 4; i++) {
            int qr = ty*4 + i;
            float cor = csh[qr];
#pragma unroll
            for (int j = 0; j < 8; j++) oacc[i][j] *= cor;
            for (int n = 0; n < 64; n++) {
                float w = Sc[qr*65+n];
                float4 v0 = *(const float4*)&KV[n*132 + tx*8];
                float4 v1 = *(const float4*)&KV[n*132 + tx*8 + 4];
                oacc[i][0]+=w*v0.x; oacc[i][1]+=w*v0.y; oacc[i][2]+=w*v0.z; oacc[i][3]+=w*v0.w;
                oacc[i][4]+=w*v1.x; oacc[i][5]+=w*v1.y; oacc[i][6]+=w*v1.z; oacc[i][7]+=w*v1.w;
            }
        }
    }

#pragma unroll
    for (int i = 0; i < 4; i++) {
        int qr = ty*4 + i;
        float inv = 1.0f / lsh[qr];
#pragma unroll
        for (int j = 0; j < 8; j++)
            g_ctx[(size_t)(q0+qr) * H_ + h*DH_ + tx*8 + j] = oacc[i][j] * inv;
    }
}

extern "C" void kernel_launch(void* const* d_in, const int* in_sizes, int n_in,
                              void* d_out, int out_size)
{
    const float* hidden      = (const float*)d_in[0];
    const float* am          = (const float*)d_in[1];
    const int*   pos         = (const int*)d_in[2];
    const float* Wqkv        = (const float*)d_in[3];
    const float* bqkv        = (const float*)d_in[4];
    const float* Wd          = (const float*)d_in[5];
    const float* bd          = (const float*)d_in[6];
    const float* scale_param = (const float*)d_in[7];
    const float* mem_keys    = (const float*)d_in[8];
    const float* mem_values  = (const float*)d_in[9];
    float*       out         = (float*)d_out;

    cudaFuncSetAttribute(out_mma_kernel,  cudaFuncAttributeMaxDynamicSharedMemorySize, GEMM_SMEM);
    cudaFuncSetAttribute(knn_pool_kernel, cudaFuncAttributeMaxDynamicSharedMemorySize, KNP_SMEM);
    cudaFuncSetAttribute(attn_kernel,     cudaFuncAttributeMaxDynamicSharedMemorySize, K4_SMEM);

    qkv_gemm_kernel<<<dim3(HQKV_/128, S_/128), 256>>>(hidden, Wqkv, bqkv);
    norm_rope_kernel<<<dim3(S_, NH_), 128>>>(pos);
    knn_pool_kernel<<<dim3(S_/64, NH_), 256, KNP_SMEM>>>(mem_keys);
    rescore_kernel<<<dim3(S_/4, NH_), 128>>>(mem_keys);
    attn_kernel<<<dim3(S_/64, NH_), 256, K4_SMEM>>>(am, scale_param, mem_values);

    split_kernel<<<512,  256>>>(hidden, S_ * H_, H_, 3);
    split_kernel<<<1024, 256>>>(Wd,     H_ * H_, H_, 4);
    out_mma_kernel<<<dim3(H_/128, S_/128), 256, GEMM_SMEM>>>(bd, out);
}

// round 11
// speedup vs baseline: 1.5186x; 1.0085x over previous
#include <cuda_runtime.h>
#include <math.h>
#include <stdint.h>

#define S_    1024
#define H_    2048
#define NH_   16
#define DH_   128
#define NN_   32
#define NP_   64
#define MK_   8192
#define HQKV_ 6144
#define KB_   6144

__device__ __align__(16) float g_qkv[S_ * HQKV_];
__device__ __align__(16) float g_q  [NH_ * S_ * DH_];
__device__ __align__(16) float g_k  [NH_ * S_ * DH_];
__device__ __align__(16) float g_v  [NH_ * S_ * DH_];
__device__ __align__(16) float g_ctx[S_ * H_];
__device__ __align__(16) float g_topv[NH_ * S_ * NN_];
__device__ __align__(16) int   g_topi[NH_ * S_ * NN_];
__device__ __align__(16) int   g_pooli[NH_ * S_ * NP_];

// tf32 3-term split buffers (A-type [h|l|h], B-type [h|h|l])
__device__ __align__(16) float g_ctx_s [S_ * KB_];
__device__ __align__(16) float g_wd_s  [(size_t)H_ * KB_];
__device__ __align__(16) float g_hid_s [S_ * KB_];
__device__ __align__(16) float g_wqkv_s[(size_t)HQKV_ * KB_];

static __device__ __forceinline__ uint32_t smem_u32(const void* p){
    uint32_t a;
    asm("{ .reg .u64 t; cvta.to.shared.u64 t, %1; cvt.u32.u64 %0, t; }" : "=r"(a) : "l"(p));
    return a;
}
__device__ __forceinline__ int SWZ(int x){ return x ^ ((x >> 3) & 0x70); }
__device__ __forceinline__ float to_tf32(float x){
    float r; asm("cvt.rna.tf32.f32 %0, %1;" : "=f"(r) : "f"(x)); return r;
}
__device__ __forceinline__ void ldsm4(uint32_t* r, uint32_t a){
    asm volatile("ldmatrix.sync.aligned.m8n8.x4.shared.b16 {%0,%1,%2,%3}, [%4];"
        : "=r"(r[0]), "=r"(r[1]), "=r"(r[2]), "=r"(r[3]) : "r"(a));
}
__device__ __forceinline__ void mmat(float* c, const uint32_t* a, uint32_t b0, uint32_t b1){
    asm volatile(
        "mma.sync.aligned.m16n8k8.row.col.f32.tf32.tf32.f32 "
        "{%0,%1,%2,%3}, {%4,%5,%6,%7}, {%8,%9}, {%0,%1,%2,%3};"
        : "+f"(c[0]), "+f"(c[1]), "+f"(c[2]), "+f"(c[3])
        : "r"(a[0]), "r"(a[1]), "r"(a[2]), "r"(a[3]), "r"(b0), "r"(b1));
}

template<int MT>
__device__ __forceinline__ void mma_chunk(uint32_t sA, uint32_t sB,
                                          int lane, int wm, int wn, float* acc){
    const int rl = lane & 15, uh = lane >> 4;
#pragma unroll
    for (int ks = 0; ks < 4; ks++){
        uint32_t a[MT][4], b[2][4];
#pragma unroll
        for (int mt = 0; mt < MT; mt++)
            ldsm4(a[mt], sA + SWZ((wm*(MT*16) + mt*16 + rl)*128 + (ks*2+uh)*16));
#pragma unroll
        for (int bt = 0; bt < 2; bt++)
            ldsm4(b[bt], sB + SWZ((wn*32 + bt*16 + rl)*128 + (ks*2+uh)*16));
#pragma unroll
        for (int mt = 0; mt < MT; mt++)
#pragma unroll
            for (int nt = 0; nt < 4; nt++)
                mmat(acc + (mt*4+nt)*4, a[mt], b[nt>>1][nt&1], b[nt>>1][(nt&1)+2]);
    }
}

// ---- tf32 hi/lo split: 0 Wqkv(B), 1 hidden(A), 3 ctx(A), 4 Wd(B) ----
__global__ void split_kernel(const float* __restrict__ src, int total, int Kc, int which)
{
    const float* s = src; float* d; int atype = 0;
    switch (which){
        case 0: d = g_wqkv_s; break;
        case 1: d = g_hid_s; atype = 1; break;
        case 3: s = g_ctx; d = g_ctx_s; atype = 1; break;
        default: d = g_wd_s; break;
    }
    for (int i = blockIdx.x * blockDim.x + threadIdx.x; i < total;
         i += gridDim.x * blockDim.x) {
        float x  = s[i];
        float hi = to_tf32(x);
        float lo = to_tf32(x - hi);
        int r = i / Kc, k = i - r * Kc;
        size_t base = (size_t)r * 3 * Kc + k;
        d[base] = hi;
        d[base + Kc]     = atype ? lo : hi;
        d[base + 2 * Kc] = atype ? hi : lo;
    }
}

// ---- shared tf32 MMA 128x128 tile body; B rows indexed by output column ----
#define GEMM_SMEM 65536
__device__ __forceinline__ void gemm_mma_tile(const float* __restrict__ A,
                                              const float* __restrict__ B,
                                              const float* __restrict__ bias,
                                              float* __restrict__ C,
                                              int N, int K, int m0, int n0)
{
    extern __shared__ char smraw[];
    uint32_t sb = smem_u32(smraw);
    const int tid = threadIdx.x, lane = tid & 31, wid = tid >> 5;
    const int wm = wid >> 2, wn = wid & 3;
    const int nch = K >> 5;

    float acc[64];
#pragma unroll
    for (int i = 0; i < 64; i++) acc[i] = 0.f;

#pragma unroll
    for (int i = 0; i < 4; i++){
        int g = tid + i * 256, r = g >> 3, u = g & 7;
        uint4 va = ((const uint4*)(A + (size_t)(m0 + r) * K))[u];
        uint4 vb = ((const uint4*)(B + (size_t)(n0 + r) * K))[u];
        *(uint4*)(smraw + SWZ(r*128 + u*16)) = va;
        *(uint4*)(smraw + 32768 + SWZ(r*128 + u*16)) = vb;
    }
    __syncthreads();

    for (int c = 0; c < nch; c++){
        const int buf = c & 1;
        uint4 pa[4], pb[4];
        if (c + 1 < nch){
#pragma unroll
            for (int i = 0; i < 4; i++){
                int g = tid + i * 256, r = g >> 3, u = g & 7;
                pa[i] = ((const uint4*)(A + (size_t)(m0 + r) * K))[(c+1)*8 + u];
                pb[i] = ((const uint4*)(B + (size_t)(n0 + r) * K))[(c+1)*8 + u];
            }
        }
        mma_chunk<4>(sb + buf*16384, sb + 32768 + buf*16384, lane, wm, wn, acc);
        if (c + 1 < nch){
            int nb = buf ^ 1;
#pragma unroll
            for (int i = 0; i < 4; i++){
                int g = tid + i * 256, r = g >> 3, u = g & 7;
                *(uint4*)(smraw + nb*16384 + SWZ(r*128 + u*16)) = pa[i];
                *(uint4*)(smraw + 32768 + nb*16384 + SWZ(r*128 + u*16)) = pb[i];
            }
        }
        __syncthreads();
    }

    const int gr = lane >> 2, gc2 = (lane & 3) * 2;
#pragma unroll
    for (int mt = 0; mt < 4; mt++)
#pragma unroll
        for (int nt = 0; nt < 4; nt++){
            const float* cp = acc + (mt*4+nt)*4;
            int r = m0 + wm*64 + mt*16 + gr;
            int col = n0 + wn*32 + nt*8 + gc2;
            float b0 = bias[col], b1 = bias[col+1];
            *(float2*)(C + (size_t)r * N + col)     = make_float2(cp[0]+b0, cp[1]+b1);
            *(float2*)(C + (size_t)(r+8) * N + col) = make_float2(cp[2]+b0, cp[3]+b1);
        }
}

__global__ void __launch_bounds__(256) out_mma_kernel(const float* __restrict__ bias,
                                                      float* __restrict__ C)
{
    gemm_mma_tile(g_ctx_s, g_wd_s, bias, C, H_, KB_,
                  blockIdx.y * 128, blockIdx.x * 128);
}

// k,v columns of qkv via 3-term tf32 MMA (Lipschitz-safe)
__global__ void __launch_bounds__(256) qkv_kv_mma_kernel(const float* __restrict__ bias)
{
    const int t = blockIdx.x >> 1, which = 1 + (blockIdx.x & 1);
    const int n0 = t * 384 + which * 128;
    gemm_mma_tile(g_hid_s, g_wqkv_s, bias, g_qkv, HQKV_, KB_,
                  blockIdx.y * 128, n0);
}

// ---- exact SIMT fp32 GEMM for q columns only (top-k needs bit-stable q) ----
__global__ void qkv_q_kernel(const float* __restrict__ A,
                             const float* __restrict__ B,
                             const float* __restrict__ bias)
{
    const int N = HQKV_, K = H_;
    __shared__ float As[8 * 128];
    __shared__ float Bs[8 * 128];
    const int tid  = threadIdx.x;
    const int m0   = blockIdx.y * 128;
    const int n0   = blockIdx.x * 384;      // q tile of head blockIdx.x
    const int ty   = tid >> 4, tx = tid & 15;
    const int lrow = tid >> 1, lk4 = (tid & 1) * 4;

    float c[8][8];
#pragma unroll
    for (int i = 0; i < 8; i++)
#pragma unroll
        for (int j = 0; j < 8; j++) c[i][j] = 0.f;

    const float* Ab = A + (size_t)(m0 + lrow) * K + lk4;
    const float* Bb = B + (size_t)(n0 + lrow) * K + lk4;

    for (int k0 = 0; k0 < K; k0 += 8) {
        float4 av = *(const float4*)(Ab + k0);
        float4 bv = *(const float4*)(Bb + k0);
        As[(lk4+0)*128+lrow] = av.x; As[(lk4+1)*128+lrow] = av.y;
        As[(lk4+2)*128+lrow] = av.z; As[(lk4+3)*128+lrow] = av.w;
        Bs[(lk4+0)*128+lrow] = bv.x; Bs[(lk4+1)*128+lrow] = bv.y;
        Bs[(lk4+2)*128+lrow] = bv.z; Bs[(lk4+3)*128+lrow] = bv.w;
        __syncthreads();
#pragma unroll
        for (int kk = 0; kk < 8; kk++) {
            float a[8], b[8];
            *(float4*)&a[0] = *(const float4*)&As[kk*128 + ty*8];
            *(float4*)&a[4] = *(const float4*)&As[kk*128 + ty*8 + 4];
            *(float4*)&b[0] = *(const float4*)&Bs[kk*128 + tx*8];
            *(float4*)&b[4] = *(const float4*)&Bs[kk*128 + tx*8 + 4];
#pragma unroll
            for (int i = 0; i < 8; i++)
#pragma unroll
                for (int j = 0; j < 8; j++) c[i][j] += a[i] * b[j];
        }
        __syncthreads();
    }
#pragma unroll
    for (int i = 0; i < 8; i++) {
        int row = m0 + ty * 8 + i;
#pragma unroll
        for (int j = 0; j < 8; j++) {
            int col = n0 + tx * 8 + j;
            g_qkv[(size_t)row * N + col] = c[i][j] + bias[col];
        }
    }
}

// ---- norm + rope ----
__global__ void norm_rope_kernel(const int* __restrict__ pos)
{
    const int s = blockIdx.x, h = blockIdx.y, d = threadIdx.x;
    const float* base = g_qkv + (size_t)s * HQKV_ + h * (3 * DH_);
    float qv = base[d], kv = base[DH_ + d], vv = base[2 * DH_ + d];

    float sq = qv * qv, sk = kv * kv;
#pragma unroll
    for (int o = 16; o > 0; o >>= 1) {
        sq += __shfl_xor_sync(0xffffffffu, sq, o);
        sk += __shfl_xor_sync(0xffffffffu, sk, o);
    }
    __shared__ float rq[4], rk[4];
    if ((d & 31) == 0) { rq[d >> 5] = sq; rk[d >> 5] = sk; }
    __syncthreads();
    float nq = sqrtf(rq[0] + rq[1] + rq[2] + rq[3]);
    float nk = sqrtf(rk[0] + rk[1] + rk[2] + rk[3]);
    float qn = qv / fmaxf(nq, 1e-12f);
    float kn = kv / fmaxf(nk, 1e-12f);

    __shared__ float qs[DH_], ks[DH_];
    qs[d] = qn; ks[d] = kn;
    __syncthreads();

    float qo = qn, ko = kn;
    if (d < 32) {
        int i = (d < 16) ? d : d - 16;
        float freq = powf(10000.0f, -(float)i / 16.0f);
        float ang  = (float)pos[s] * freq;
        float cs = cosf(ang), sn = sinf(ang);
        float rqh = (d < 16) ? -qs[d + 16] : qs[d - 16];
        float rkh = (d < 16) ? -ks[d + 16] : ks[d - 16];
        qo = qn * cs + rqh * sn;
        ko = kn * cs + rkh * sn;
    }
    size_t o = ((size_t)h * S_ + s) * DH_ + d;
    g_q[o] = qo; g_k[o] = ko; g_v[o] = vv;
}

// ---- kNN pool: tf32 MMA scores + register-pool half-warp top-64 ----
#define KNA   0
#define KNB   32768
#define KNSC  65536
#define KNTI  98816
#define KNP_SMEM 107008
__global__ void __launch_bounds__(256, 2) knn_pool_kernel(const float* __restrict__ mem_keys)
{
    extern __shared__ char smraw[];
    uint32_t sb = smem_u32(smraw);
    const int tid = threadIdx.x, lane = tid & 31, wid = tid >> 5;
    const int wm = wid >> 2, wn = wid & 3;
    const int h = blockIdx.y, q0 = blockIdx.x * 64;
    float* Sc = (float*)(smraw + KNSC);
    unsigned short* Ti = (unsigned short*)(smraw + KNTI);

    const int half = lane >> 4, hl = lane & 15;
    const unsigned hmask = half ? 0xffff0000u : 0x0000ffffu;
    const int qbase = wid * 8;

    {
        int r = tid >> 2, part = tid & 3;
        const uint4* Ar = (const uint4*)(g_q + ((size_t)h * S_ + q0 + r) * DH_);
#pragma unroll
        for (int j = 0; j < 8; j++)
            *(uint4*)(smraw + KNA + part*8192 + SWZ(r*128 + j*16)) = Ar[part*8 + j];
    }
#pragma unroll
    for (int i = 0; i < 4; i++){
        int g = tid + i * 256, r = g >> 3, u = g & 7;
        uint4 v = ((const uint4*)(mem_keys + ((size_t)h * MK_ + r) * DH_))[u];
        *(uint4*)(smraw + KNB + SWZ(r*128 + u*16)) = v;
    }
    __syncthreads();

    float pv[4][4];
    float mv[4];
#pragma unroll
    for (int p = 0; p < 4; p++){
        mv[p] = -3.0e38f;
#pragma unroll
        for (int j = 0; j < 4; j++) pv[p][j] = -3.0e38f;
    }

    float acc[32];
#pragma unroll
    for (int i = 0; i < 32; i++) acc[i] = 0.f;

    for (int g = 0; g < 64 * 4; g++){
        const int t = g >> 2, ci = g & 3;
        const int buf = g & 1;
        uint4 pb[4];
        if (g + 1 < 64 * 4){
            int tn = (g + 1) >> 2, cn = (g + 1) & 3;
#pragma unroll
            for (int i = 0; i < 4; i++){
                int gi = tid + i * 256, r = gi >> 3, u = gi & 7;
                pb[i] = ((const uint4*)(mem_keys +
                         ((size_t)h * MK_ + tn * 128 + r) * DH_))[cn*8 + u];
            }
        }
        mma_chunk<2>(sb + KNA + ci*8192, sb + KNB + buf*16384, lane, wm, wn, acc);
        if (g + 1 < 64 * 4){
            int nb = buf ^ 1;
#pragma unroll
            for (int i = 0; i < 4; i++){
                int gi = tid + i * 256, r = gi >> 3, u = gi & 7;
                *(uint4*)(smraw + KNB + nb*16384 + SWZ(r*128 + u*16)) = pb[i];
            }
        }
        __syncthreads();

        if (ci == 3){
            const int gr = lane >> 2, gc2 = (lane & 3) * 2;
#pragma unroll
            for (int mt = 0; mt < 2; mt++)
#pragma unroll
                for (int nt = 0; nt < 4; nt++){
                    float* cp = acc + (mt*4+nt)*4;
                    int r = wm*32 + mt*16 + gr, col = wn*32 + nt*8 + gc2;
                    *(float2*)(Sc + r*130 + col)     = make_float2(cp[0], cp[1]);
                    *(float2*)(Sc + (r+8)*130 + col) = make_float2(cp[2], cp[3]);
                }
#pragma unroll
            for (int i = 0; i < 32; i++) acc[i] = 0.f;
            __syncthreads();

            for (int p = 0; p < 4; p++){
                const int q = qbase + p*2 + half;
                const float* srow = Sc + q*130;
                float m_ = mv[p];
                int seg0 = 0;
                if (t == 0){
#pragma unroll
                    for (int j = 0; j < 4; j++){
                        pv[p][j] = srow[hl*4 + j];
                        Ti[q*64 + hl*4 + j] = (unsigned short)(hl*4 + j);
                    }
                    float pm = pv[p][0];
#pragma unroll
                    for (int j = 1; j < 4; j++) pm = fminf(pm, pv[p][j]);
#pragma unroll
                    for (int o = 8; o > 0; o >>= 1)
                        pm = fminf(pm, __shfl_xor_sync(hmask, pm, o));
                    m_ = pm;
                    seg0 = 4;
                }
                for (int seg = seg0; seg < 8; seg++){
                    float s = srow[seg*16 + hl];
                    unsigned bal = __ballot_sync(0xffffffffu, s > m_);
                    unsigned m = (bal >> (half*16)) & 0xffffu;
                    while (m){
                        int b = __ffs(m) - 1; m &= m - 1;
                        float sv = __shfl_sync(hmask, s, half*16 + b);
                        float pm = pv[p][0]; int pc = 0;
#pragma unroll
                        for (int j = 1; j < 4; j++)
                            if (pv[p][j] < pm){ pm = pv[p][j]; pc = j; }
                        int code = hl*4 + pc;
#pragma unroll
                        for (int o = 8; o > 0; o >>= 1){
                            float ov = __shfl_xor_sync(hmask, pm, o);
                            int   oc = __shfl_xor_sync(hmask, code, o);
                            if (ov < pm || (ov == pm && oc < code)){ pm = ov; code = oc; }
                        }
                        if (sv > pm && hl == (code >> 2)){
                            pv[p][code & 3] = sv;
                            Ti[q*64 + code] = (unsigned short)(t*128 + seg*16 + b);
                        }
                        m_ = pm;
                    }
                }
                mv[p] = m_;
            }
            __syncthreads();
        }
    }
    for (int i = tid; i < 64 * NP_; i += 256)
        g_pooli[((size_t)h * S_ + q0 + (i >> 6)) * NP_ + (i & 63)] = (int)Ti[i];
}

// ---- exact fp32 rescore of 64 candidates -> true top-32 ----
__global__ void rescore_kernel(const float* __restrict__ mem_keys)
{
    __shared__ float ssc[4][NP_];
    __shared__ int   sid[4][NP_];
    const int lane = threadIdx.x & 31, w = threadIdx.x >> 5;
    const int h = blockIdx.y;
    const int q = blockIdx.x * 4 + w;
    const size_t qi = (size_t)h * S_ + q;

    float4 qv = ((const float4*)(g_q + qi * DH_))[lane];
    for (int c = lane; c < NP_; c += 32) sid[w][c] = g_pooli[qi * NP_ + c];
    __syncwarp();

    for (int c = 0; c < NP_; c++){
        float4 kv = ((const float4*)(mem_keys + ((size_t)h * MK_ + sid[w][c]) * DH_))[lane];
        float d = qv.x*kv.x + qv.y*kv.y + qv.z*kv.z + qv.w*kv.w;
#pragma unroll
        for (int o = 16; o > 0; o >>= 1) d += __shfl_xor_sync(0xffffffffu, d, o);
        if (lane == 0) ssc[w][c] = d;
    }
    __syncwarp();

    float v1 = ssc[w][lane];
    float v2 = ssc[w][32 + lane];
    for (int it = 0; it < NN_; it++){
        float mvv; int mi;
        if (v1 >= v2){ mvv = v1; mi = lane; } else { mvv = v2; mi = 32 + lane; }
#pragma unroll
        for (int o = 16; o > 0; o >>= 1){
            float ov = __shfl_xor_sync(0xffffffffu, mvv, o);
            int   oi = __shfl_xor_sync(0xffffffffu, mi, o);
            if (ov > mvv || (ov == mvv && oi < mi)){ mvv = ov; mi = oi; }
        }
        if (mi < 32){ if (lane == mi) v1 = -3.0e38f; }
        else        { if (lane == mi - 32) v2 = -3.0e38f; }
        if (lane == 0){
            g_topv[qi * NN_ + it] = mvv;
            g_topi[qi * NN_ + it] = sid[w][mi];
        }
    }
}

// ---- flash attention (parallel softmax, heavy-first scheduling) ----
#define K4_SMEM ((128 * 68 + 128 * 68 + 64 * 65 + 192 + 64 * 32) * 4)
__global__ void attn_kernel(const float* __restrict__ am,
                            const float* __restrict__ scale_param,
                            const float* __restrict__ mem_values)
{
    extern __shared__ float sm[];
    float* Qs  = sm;
    float* KV  = Qs + 128 * 68;
    float* Sc  = KV + 128 * 68;
    float* msh = Sc + 64 * 65;
    float* lsh = msh + 64;
    float* csh = lsh + 64;
    int*   Ti  = (int*)(csh + 64);

    const int tid = threadIdx.x;
    const int h   = blockIdx.y;
    const int q0  = (gridDim.x - 1 - blockIdx.x) * 64;
    const int ty  = tid >> 4, tx = tid & 15;
    const int srow = tid >> 2, sl4 = tid & 3;
    const float scale = expf(scale_param[h]);

    for (int idx = tid; idx < 64 * 32; idx += 256) {
        int row = idx >> 5, seg = idx & 31;
        float4 v = *(const float4*)(g_q + ((size_t)h * S_ + q0 + row) * DH_ + seg * 4);
        Qs[(seg*4+0)*68+row] = v.x; Qs[(seg*4+1)*68+row] = v.y;
        Qs[(seg*4+2)*68+row] = v.z; Qs[(seg*4+3)*68+row] = v.w;
    }
    for (int idx = tid; idx < 64 * 32; idx += 256) {
        int q = idx >> 5, n = idx & 31;
        Sc[q*65+n] = g_topv[((size_t)h * S_ + q0 + q) * NN_ + n] * scale;
        Ti[q*32+n] = g_topi[((size_t)h * S_ + q0 + q) * NN_ + n];
    }
    __syncthreads();

    {
        float mm = -3.0e38f;
#pragma unroll
        for (int j = 0; j < 8; j++) mm = fmaxf(mm, Sc[srow*65 + sl4*8 + j]);
        mm = fmaxf(mm, __shfl_xor_sync(0xffffffffu, mm, 1));
        mm = fmaxf(mm, __shfl_xor_sync(0xffffffffu, mm, 2));
        float ll = 0.f;
#pragma unroll
        for (int j = 0; j < 8; j++){
            float p = expf(Sc[srow*65 + sl4*8 + j] - mm);
            Sc[srow*65 + sl4*8 + j] = p; ll += p;
        }
        ll += __shfl_xor_sync(0xffffffffu, ll, 1);
        ll += __shfl_xor_sync(0xffffffffu, ll, 2);
        if (sl4 == 0){ msh[srow] = mm; lsh[srow] = ll; }
    }
    __syncthreads();

    float oacc[4][8];
#pragma unroll
    for (int i = 0; i < 4; i++)
#pragma unroll
        for (int j = 0; j < 8; j++) oacc[i][j] = 0.f;

#pragma unroll
    for (int i = 0; i < 4; i++) {
        int qr = ty * 4 + i;
        for (int n = 0; n < NN_; n++) {
            float w = Sc[qr*65+n];
            const float4* vr = (const float4*)(mem_values +
                ((size_t)h * MK_ + Ti[qr*32+n]) * DH_ + tx * 8);
            float4 v0 = vr[0], v1 = vr[1];
            oacc[i][0]+=w*v0.x; oacc[i][1]+=w*v0.y; oacc[i][2]+=w*v0.z; oacc[i][3]+=w*v0.w;
            oacc[i][4]+=w*v1.x; oacc[i][5]+=w*v1.y; oacc[i][6]+=w*v1.z; oacc[i][7]+=w*v1.w;
        }
    }

    const int kcmax = q0 / 64;
    for (int kc = 0; kc <= kcmax; kc++) {
        __syncthreads();
        for (int idx = tid; idx < 64 * 32; idx += 256) {
            int row = idx >> 5, seg = idx & 31;
            float4 v = *(const float4*)(g_k + ((size_t)h * S_ + kc*64 + row) * DH_ + seg * 4);
            KV[(seg*4+0)*68+row] = v.x; KV[(seg*4+1)*68+row] = v.y;
            KV[(seg*4+2)*68+row] = v.z; KV[(seg*4+3)*68+row] = v.w;
        }
        __syncthreads();

        float sc4[4][4];
#pragma unroll
        for (int i = 0; i < 4; i++)
#pragma unroll
            for (int j = 0; j < 4; j++) sc4[i][j] = 0.f;

#pragma unroll 8
        for (int kd = 0; kd < DH_; kd++) {
            float4 aq = *(const float4*)&Qs[kd*68 + ty*4];
            float4 bk = *(const float4*)&KV[kd*68 + tx*4];
            float a[4] = {aq.x, aq.y, aq.z, aq.w};
            float b[4] = {bk.x, bk.y, bk.z, bk.w};
#pragma unroll
            for (int i = 0; i < 4; i++)
#pragma unroll
                for (int j = 0; j < 4; j++) sc4[i][j] += a[i] * b[j];
        }
#pragma unroll
        for (int i = 0; i < 4; i++) {
            int qg = q0 + ty*4 + i;
#pragma unroll
            for (int j = 0; j < 4; j++) {
                int kg = kc*64 + tx*4 + j;
                float v = (kg <= qg) ? (sc4[i][j] * scale + am[kg]) : -1.0e30f;
                Sc[(ty*4+i)*65 + tx*4+j] = v;
            }
        }
        __syncthreads();

        {
            float mm = msh[srow], rmax = mm;
#pragma unroll
            for (int j = 0; j < 16; j++) rmax = fmaxf(rmax, Sc[srow*65 + sl4*16 + j]);
            rmax = fmaxf(rmax, __shfl_xor_sync(0xffffffffu, rmax, 1));
            rmax = fmaxf(rmax, __shfl_xor_sync(0xffffffffu, rmax, 2));
            float cor = expf(mm - rmax);
            float ll = (sl4 == 0) ? lsh[srow] * cor : 0.f;
#pragma unroll
            for (int j = 0; j < 16; j++){
                float p = expf(Sc[srow*65 + sl4*16 + j] - rmax);
                Sc[srow*65 + sl4*16 + j] = p; ll += p;
            }
            ll += __shfl_xor_sync(0xffffffffu, ll, 1);
            ll += __shfl_xor_sync(0xffffffffu, ll, 2);
            if (sl4 == 0){ msh[srow] = rmax; lsh[srow] = ll; csh[srow] = cor; }
        }
        __syncthreads();

        for (int idx = tid; idx < 64 * 32; idx += 256) {
            int row = idx >> 5, seg = idx & 31;
            float4 v = *(const float4*)(g_v + ((size_t)h * S_ + kc*64 + row) * DH_ + seg * 4);
            *(float4*)&KV[row*132 + seg*4] = v;
        }
        __syncthreads();

#pragma unroll
        for (int i = 0; i < 4; i++) {
            int qr = ty*4 + i;
            float cor = csh[qr];
#pragma unroll
            for (int j = 0; j < 8; j++) oacc[i][j] *= cor;
            for (int n = 0; n < 64; n++) {
                float w = Sc[qr*65+n];
                float4 v0 = *(const float4*)&KV[n*132 + tx*8];
                float4 v1 = *(const float4*)&KV[n*132 + tx*8 + 4];
                oacc[i][0]+=w*v0.x; oacc[i][1]+=w*v0.y; oacc[i][2]+=w*v0.z; oacc[i][3]+=w*v0.w;
                oacc[i][4]+=w*v1.x; oacc[i][5]+=w*v1.y; oacc[i][6]+=w*v1.z; oacc[i][7]+=w*v1.w;
            }
        }
    }

#pragma unroll
    for (int i = 0; i < 4; i++) {
        int qr = ty*4 + i;
        float inv = 1.0f / lsh[qr];
#pragma unroll
        for (int j = 0; j < 8; j++)
            g_ctx[(size_t)(q0+qr) * H_ + h*DH_ + tx*8 + j] = oacc[i][j] * inv;
    }
}

extern "C" void kernel_launch(void* const* d_in, const int* in_sizes, int n_in,
                              void* d_out, int out_size)
{
    const float* hidden      = (const float*)d_in[0];
    const float* am          = (const float*)d_in[1];
    const int*   pos         = (const int*)d_in[2];
    const float* Wqkv        = (const float*)d_in[3];
    const float* bqkv        = (const float*)d_in[4];
    const float* Wd          = (const float*)d_in[5];
    const float* bd          = (const float*)d_in[6];
    const float* scale_param = (const float*)d_in[7];
    const float* mem_keys    = (const float*)d_in[8];
    const float* mem_values  = (const float*)d_in[9];
    float*       out         = (float*)d_out;

    cudaFuncSetAttribute(out_mma_kernel,    cudaFuncAttributeMaxDynamicSharedMemorySize, GEMM_SMEM);
    cudaFuncSetAttribute(qkv_kv_mma_kernel, cudaFuncAttributeMaxDynamicSharedMemorySize, GEMM_SMEM);
    cudaFuncSetAttribute(knn_pool_kernel,   cudaFuncAttributeMaxDynamicSharedMemorySize, KNP_SMEM);
    cudaFuncSetAttribute(attn_kernel,       cudaFuncAttributeMaxDynamicSharedMemorySize, K4_SMEM);

    split_kernel<<<2048, 256>>>(Wqkv,   HQKV_ * H_, H_, 0);
    split_kernel<<<512,  256>>>(hidden, S_ * H_,    H_, 1);

    qkv_q_kernel<<<dim3(NH_, S_/128), 256>>>(hidden, Wqkv, bqkv);
    qkv_kv_mma_kernel<<<dim3(2*NH_, S_/128), 256, GEMM_SMEM>>>(bqkv);
    norm_rope_kernel<<<dim3(S_, NH_), 128>>>(pos);
    knn_pool_kernel<<<dim3(S_/64, NH_), 256, KNP_SMEM>>>(mem_keys);
    rescore_kernel<<<dim3(S_/4, NH_), 128>>>(mem_keys);
    attn_kernel<<<dim3(S_/64, NH_), 256, K4_SMEM>>>(am, scale_param, mem_values);

    split_kernel<<<512,  256>>>(hidden, S_ * H_, H_, 3);
    split_kernel<<<1024, 256>>>(Wd,     H_ * H_, H_, 4);
    out_mma_kernel<<<dim3(H_/128, S_/128), 256, GEMM_SMEM>>>(bd, out);
}

// round 12
// speedup vs baseline: 1.5727x; 1.0357x over previous
#include <cuda_runtime.h>
#include <math.h>
#include <stdint.h>

#define S_    1024
#define H_    2048
#define NH_   16
#define DH_   128
#define NN_   32
#define NP_   64
#define MK_   8192
#define HQKV_ 6144
#define KB_   6144

__device__ __align__(16) float g_qkv[S_ * HQKV_];
__device__ __align__(16) float g_q  [NH_ * S_ * DH_];
__device__ __align__(16) float g_k  [NH_ * S_ * DH_];
__device__ __align__(16) float g_v  [NH_ * S_ * DH_];
__device__ __align__(16) float g_ctx[S_ * H_];
__device__ __align__(16) float g_topv[NH_ * S_ * NN_];
__device__ __align__(16) int   g_topi[NH_ * S_ * NN_];
__device__ __align__(16) int   g_pooli[NH_ * S_ * NP_];

__device__ __align__(16) float g_ctx_s [S_ * KB_];
__device__ __align__(16) float g_wd_s  [(size_t)H_ * KB_];
__device__ __align__(16) float g_hid_s [S_ * KB_];
__device__ __align__(16) float g_wqkv_s[(size_t)HQKV_ * KB_];

static __device__ __forceinline__ uint32_t smem_u32(const void* p){
    uint32_t a;
    asm("{ .reg .u64 t; cvta.to.shared.u64 t, %1; cvt.u32.u64 %0, t; }" : "=r"(a) : "l"(p));
    return a;
}
__device__ __forceinline__ int SWZ(int x){ return x ^ ((x >> 3) & 0x70); }
__device__ __forceinline__ float to_tf32(float x){
    float r; asm("cvt.rna.tf32.f32 %0, %1;" : "=f"(r) : "f"(x)); return r;
}
__device__ __forceinline__ void ldsm4(uint32_t* r, uint32_t a){
    asm volatile("ldmatrix.sync.aligned.m8n8.x4.shared.b16 {%0,%1,%2,%3}, [%4];"
        : "=r"(r[0]), "=r"(r[1]), "=r"(r[2]), "=r"(r[3]) : "r"(a));
}
__device__ __forceinline__ void mmat(float* c, const uint32_t* a, uint32_t b0, uint32_t b1){
    asm volatile(
        "mma.sync.aligned.m16n8k8.row.col.f32.tf32.tf32.f32 "
        "{%0,%1,%2,%3}, {%4,%5,%6,%7}, {%8,%9}, {%0,%1,%2,%3};"
        : "+f"(c[0]), "+f"(c[1]), "+f"(c[2]), "+f"(c[3])
        : "r"(a[0]), "r"(a[1]), "r"(a[2]), "r"(a[3]), "r"(b0), "r"(b1));
}

template<int MT>
__device__ __forceinline__ void mma_chunk(uint32_t sA, uint32_t sB,
                                          int lane, int wm, int wn, float* acc){
    const int rl = lane & 15, uh = lane >> 4;
#pragma unroll
    for (int ks = 0; ks < 4; ks++){
        uint32_t a[MT][4], b[2][4];
#pragma unroll
        for (int mt = 0; mt < MT; mt++)
            ldsm4(a[mt], sA + SWZ((wm*(MT*16) + mt*16 + rl)*128 + (ks*2+uh)*16));
#pragma unroll
        for (int bt = 0; bt < 2; bt++)
            ldsm4(b[bt], sB + SWZ((wn*32 + bt*16 + rl)*128 + (ks*2+uh)*16));
#pragma unroll
        for (int mt = 0; mt < MT; mt++)
#pragma unroll
            for (int nt = 0; nt < 4; nt++)
                mmat(acc + (mt*4+nt)*4, a[mt], b[nt>>1][nt&1], b[nt>>1][(nt&1)+2]);
    }
}

// ---- tf32 hi/lo split: 0 Wqkv(B), 1 hidden(A), 3 ctx(A), 4 Wd(B) ----
__global__ void split_kernel(const float* __restrict__ src, int total, int Kc, int which)
{
    const float* s = src; float* d; int atype = 0;
    switch (which){
        case 0: d = g_wqkv_s; break;
        case 1: d = g_hid_s; atype = 1; break;
        case 3: s = g_ctx; d = g_ctx_s; atype = 1; break;
        default: d = g_wd_s; break;
    }
    for (int i = blockIdx.x * blockDim.x + threadIdx.x; i < total;
         i += gridDim.x * blockDim.x) {
        float x  = s[i];
        float hi = to_tf32(x);
        float lo = to_tf32(x - hi);
        int r = i / Kc, k = i - r * Kc;
        size_t base = (size_t)r * 3 * Kc + k;
        d[base] = hi;
        d[base + Kc]     = atype ? lo : hi;
        d[base + 2 * Kc] = atype ? hi : lo;
    }
}

// ---- shared tf32 MMA 128x128 tile body ----
#define GEMM_SMEM 65536
__device__ __forceinline__ void gemm_mma_tile(const float* __restrict__ A,
                                              const float* __restrict__ B,
                                              const float* __restrict__ bias,
                                              float* __restrict__ C,
                                              int N, int K, int m0, int n0)
{
    extern __shared__ char smraw[];
    uint32_t sb = smem_u32(smraw);
    const int tid = threadIdx.x, lane = tid & 31, wid = tid >> 5;
    const int wm = wid >> 2, wn = wid & 3;
    const int nch = K >> 5;

    float acc[64];
#pragma unroll
    for (int i = 0; i < 64; i++) acc[i] = 0.f;

#pragma unroll
    for (int i = 0; i < 4; i++){
        int g = tid + i * 256, r = g >> 3, u = g & 7;
        uint4 va = ((const uint4*)(A + (size_t)(m0 + r) * K))[u];
        uint4 vb = ((const uint4*)(B + (size_t)(n0 + r) * K))[u];
        *(uint4*)(smraw + SWZ(r*128 + u*16)) = va;
        *(uint4*)(smraw + 32768 + SWZ(r*128 + u*16)) = vb;
    }
    __syncthreads();

    for (int c = 0; c < nch; c++){
        const int buf = c & 1;
        uint4 pa[4], pb[4];
        if (c + 1 < nch){
#pragma unroll
            for (int i = 0; i < 4; i++){
                int g = tid + i * 256, r = g >> 3, u = g & 7;
                pa[i] = ((const uint4*)(A + (size_t)(m0 + r) * K))[(c+1)*8 + u];
                pb[i] = ((const uint4*)(B + (size_t)(n0 + r) * K))[(c+1)*8 + u];
            }
        }
        mma_chunk<4>(sb + buf*16384, sb + 32768 + buf*16384, lane, wm, wn, acc);
        if (c + 1 < nch){
            int nb = buf ^ 1;
#pragma unroll
            for (int i = 0; i < 4; i++){
                int g = tid + i * 256, r = g >> 3, u = g & 7;
                *(uint4*)(smraw + nb*16384 + SWZ(r*128 + u*16)) = pa[i];
                *(uint4*)(smraw + 32768 + nb*16384 + SWZ(r*128 + u*16)) = pb[i];
            }
        }
        __syncthreads();
    }

    const int gr = lane >> 2, gc2 = (lane & 3) * 2;
#pragma unroll
    for (int mt = 0; mt < 4; mt++)
#pragma unroll
        for (int nt = 0; nt < 4; nt++){
            const float* cp = acc + (mt*4+nt)*4;
            int r = m0 + wm*64 + mt*16 + gr;
            int col = n0 + wn*32 + nt*8 + gc2;
            float b0 = bias[col], b1 = bias[col+1];
            *(float2*)(C + (size_t)r * N + col)     = make_float2(cp[0]+b0, cp[1]+b1);
            *(float2*)(C + (size_t)(r+8) * N + col) = make_float2(cp[2]+b0, cp[3]+b1);
        }
}

__global__ void __launch_bounds__(256) out_mma_kernel(const float* __restrict__ bias,
                                                      float* __restrict__ C)
{
    gemm_mma_tile(g_ctx_s, g_wd_s, bias, C, H_, KB_,
                  blockIdx.y * 128, blockIdx.x * 128);
}

__global__ void __launch_bounds__(256) qkv_kv_mma_kernel(const float* __restrict__ bias)
{
    const int t = blockIdx.x >> 1, which = 1 + (blockIdx.x & 1);
    const int n0 = t * 384 + which * 128;
    gemm_mma_tile(g_hid_s, g_wqkv_s, bias, g_qkv, HQKV_, KB_,
                  blockIdx.y * 128, n0);
}

// ---- exact SIMT fp32 GEMM for q columns only ----
__global__ void qkv_q_kernel(const float* __restrict__ A,
                             const float* __restrict__ B,
                             const float* __restrict__ bias)
{
    const int N = HQKV_, K = H_;
    __shared__ float As[8 * 128];
    __shared__ float Bs[8 * 128];
    const int tid  = threadIdx.x;
    const int m0   = blockIdx.y * 128;
    const int n0   = blockIdx.x * 384;
    const int ty   = tid >> 4, tx = tid & 15;
    const int lrow = tid >> 1, lk4 = (tid & 1) * 4;

    float c[8][8];
#pragma unroll
    for (int i = 0; i < 8; i++)
#pragma unroll
        for (int j = 0; j < 8; j++) c[i][j] = 0.f;

    const float* Ab = A + (size_t)(m0 + lrow) * K + lk4;
    const float* Bb = B + (size_t)(n0 + lrow) * K + lk4;

    for (int k0 = 0; k0 < K; k0 += 8) {
        float4 av = *(const float4*)(Ab + k0);
        float4 bv = *(const float4*)(Bb + k0);
        As[(lk4+0)*128+lrow] = av.x; As[(lk4+1)*128+lrow] = av.y;
        As[(lk4+2)*128+lrow] = av.z; As[(lk4+3)*128+lrow] = av.w;
        Bs[(lk4+0)*128+lrow] = bv.x; Bs[(lk4+1)*128+lrow] = bv.y;
        Bs[(lk4+2)*128+lrow] = bv.z; Bs[(lk4+3)*128+lrow] = bv.w;
        __syncthreads();
#pragma unroll
        for (int kk = 0; kk < 8; kk++) {
            float a[8], b[8];
            *(float4*)&a[0] = *(const float4*)&As[kk*128 + ty*8];
            *(float4*)&a[4] = *(const float4*)&As[kk*128 + ty*8 + 4];
            *(float4*)&b[0] = *(const float4*)&Bs[kk*128 + tx*8];
            *(float4*)&b[4] = *(const float4*)&Bs[kk*128 + tx*8 + 4];
#pragma unroll
            for (int i = 0; i < 8; i++)
#pragma unroll
                for (int j = 0; j < 8; j++) c[i][j] += a[i] * b[j];
        }
        __syncthreads();
    }
#pragma unroll
    for (int i = 0; i < 8; i++) {
        int row = m0 + ty * 8 + i;
#pragma unroll
        for (int j = 0; j < 8; j++) {
            int col = n0 + tx * 8 + j;
            g_qkv[(size_t)row * N + col] = c[i][j] + bias[col];
        }
    }
}

// ---- norm + rope ----
__global__ void norm_rope_kernel(const int* __restrict__ pos)
{
    const int s = blockIdx.x, h = blockIdx.y, d = threadIdx.x;
    const float* base = g_qkv + (size_t)s * HQKV_ + h * (3 * DH_);
    float qv = base[d], kv = base[DH_ + d], vv = base[2 * DH_ + d];

    float sq = qv * qv, sk = kv * kv;
#pragma unroll
    for (int o = 16; o > 0; o >>= 1) {
        sq += __shfl_xor_sync(0xffffffffu, sq, o);
        sk += __shfl_xor_sync(0xffffffffu, sk, o);
    }
    __shared__ float rq[4], rk[4];
    if ((d & 31) == 0) { rq[d >> 5] = sq; rk[d >> 5] = sk; }
    __syncthreads();
    float nq = sqrtf(rq[0] + rq[1] + rq[2] + rq[3]);
    float nk = sqrtf(rk[0] + rk[1] + rk[2] + rk[3]);
    float qn = qv / fmaxf(nq, 1e-12f);
    float kn = kv / fmaxf(nk, 1e-12f);

    __shared__ float qs[DH_], ks[DH_];
    qs[d] = qn; ks[d] = kn;
    __syncthreads();

    float qo = qn, ko = kn;
    if (d < 32) {
        int i = (d < 16) ? d : d - 16;
        float freq = powf(10000.0f, -(float)i / 16.0f);
        float ang  = (float)pos[s] * freq;
        float cs = cosf(ang), sn = sinf(ang);
        float rqh = (d < 16) ? -qs[d + 16] : qs[d - 16];
        float rkh = (d < 16) ? -ks[d + 16] : ks[d - 16];
        qo = qn * cs + rqh * sn;
        ko = kn * cs + rkh * sn;
    }
    size_t o = ((size_t)h * S_ + s) * DH_ + d;
    g_q[o] = qo; g_k[o] = ko; g_v[o] = vv;
}

// ---- kNN pool (unchanged from r11) ----
#define KNA   0
#define KNB   32768
#define KNSC  65536
#define KNTI  98816
#define KNP_SMEM 107008
__global__ void __launch_bounds__(256, 2) knn_pool_kernel(const float* __restrict__ mem_keys)
{
    extern __shared__ char smraw[];
    uint32_t sb = smem_u32(smraw);
    const int tid = threadIdx.x, lane = tid & 31, wid = tid >> 5;
    const int wm = wid >> 2, wn = wid & 3;
    const int h = blockIdx.y, q0 = blockIdx.x * 64;
    float* Sc = (float*)(smraw + KNSC);
    unsigned short* Ti = (unsigned short*)(smraw + KNTI);

    const int half = lane >> 4, hl = lane & 15;
    const unsigned hmask = half ? 0xffff0000u : 0x0000ffffu;
    const int qbase = wid * 8;

    {
        int r = tid >> 2, part = tid & 3;
        const uint4* Ar = (const uint4*)(g_q + ((size_t)h * S_ + q0 + r) * DH_);
#pragma unroll
        for (int j = 0; j < 8; j++)
            *(uint4*)(smraw + KNA + part*8192 + SWZ(r*128 + j*16)) = Ar[part*8 + j];
    }
#pragma unroll
    for (int i = 0; i < 4; i++){
        int g = tid + i * 256, r = g >> 3, u = g & 7;
        uint4 v = ((const uint4*)(mem_keys + ((size_t)h * MK_ + r) * DH_))[u];
        *(uint4*)(smraw + KNB + SWZ(r*128 + u*16)) = v;
    }
    __syncthreads();

    float pv[4][4];
    float mv[4];
#pragma unroll
    for (int p = 0; p < 4; p++){
        mv[p] = -3.0e38f;
#pragma unroll
        for (int j = 0; j < 4; j++) pv[p][j] = -3.0e38f;
    }

    float acc[32];
#pragma unroll
    for (int i = 0; i < 32; i++) acc[i] = 0.f;

    for (int g = 0; g < 64 * 4; g++){
        const int t = g >> 2, ci = g & 3;
        const int buf = g & 1;
        uint4 pb[4];
        if (g + 1 < 64 * 4){
            int tn = (g + 1) >> 2, cn = (g + 1) & 3;
#pragma unroll
            for (int i = 0; i < 4; i++){
                int gi = tid + i * 256, r = gi >> 3, u = gi & 7;
                pb[i] = ((const uint4*)(mem_keys +
                         ((size_t)h * MK_ + tn * 128 + r) * DH_))[cn*8 + u];
            }
        }
        mma_chunk<2>(sb + KNA + ci*8192, sb + KNB + buf*16384, lane, wm, wn, acc);
        if (g + 1 < 64 * 4){
            int nb = buf ^ 1;
#pragma unroll
            for (int i = 0; i < 4; i++){
                int gi = tid + i * 256, r = gi >> 3, u = gi & 7;
                *(uint4*)(smraw + KNB + nb*16384 + SWZ(r*128 + u*16)) = pb[i];
            }
        }
        __syncthreads();

        if (ci == 3){
            const int gr = lane >> 2, gc2 = (lane & 3) * 2;
#pragma unroll
            for (int mt = 0; mt < 2; mt++)
#pragma unroll
                for (int nt = 0; nt < 4; nt++){
                    float* cp = acc + (mt*4+nt)*4;
                    int r = wm*32 + mt*16 + gr, col = wn*32 + nt*8 + gc2;
                    *(float2*)(Sc + r*130 + col)     = make_float2(cp[0], cp[1]);
                    *(float2*)(Sc + (r+8)*130 + col) = make_float2(cp[2], cp[3]);
                }
#pragma unroll
            for (int i = 0; i < 32; i++) acc[i] = 0.f;
            __syncthreads();

            for (int p = 0; p < 4; p++){
                const int q = qbase + p*2 + half;
                const float* srow = Sc + q*130;
                float m_ = mv[p];
                int seg0 = 0;
                if (t == 0){
#pragma unroll
                    for (int j = 0; j < 4; j++){
                        pv[p][j] = srow[hl*4 + j];
                        Ti[q*64 + hl*4 + j] = (unsigned short)(hl*4 + j);
                    }
                    float pm = pv[p][0];
#pragma unroll
                    for (int j = 1; j < 4; j++) pm = fminf(pm, pv[p][j]);
#pragma unroll
                    for (int o = 8; o > 0; o >>= 1)
                        pm = fminf(pm, __shfl_xor_sync(hmask, pm, o));
                    m_ = pm;
                    seg0 = 4;
                }
                for (int seg = seg0; seg < 8; seg++){
                    float s = srow[seg*16 + hl];
                    unsigned bal = __ballot_sync(0xffffffffu, s > m_);
                    unsigned m = (bal >> (half*16)) & 0xffffu;
                    while (m){
                        int b = __ffs(m) - 1; m &= m - 1;
                        float sv = __shfl_sync(hmask, s, half*16 + b);
                        float pm = pv[p][0]; int pc = 0;
#pragma unroll
                        for (int j = 1; j < 4; j++)
                            if (pv[p][j] < pm){ pm = pv[p][j]; pc = j; }
                        int code = hl*4 + pc;
#pragma unroll
                        for (int o = 8; o > 0; o >>= 1){
                            float ov = __shfl_xor_sync(hmask, pm, o);
                            int   oc = __shfl_xor_sync(hmask, code, o);
                            if (ov < pm || (ov == pm && oc < code)){ pm = ov; code = oc; }
                        }
                        if (sv > pm && hl == (code >> 2)){
                            pv[p][code & 3] = sv;
                            Ti[q*64 + code] = (unsigned short)(t*128 + seg*16 + b);
                        }
                        m_ = pm;
                    }
                }
                mv[p] = m_;
            }
            __syncthreads();
        }
    }
    for (int i = tid; i < 64 * NP_; i += 256)
        g_pooli[((size_t)h * S_ + q0 + (i >> 6)) * NP_ + (i & 63)] = (int)Ti[i];
}

// ---- exact fp32 rescore (unchanged) ----
__global__ void rescore_kernel(const float* __restrict__ mem_keys)
{
    __shared__ float ssc[4][NP_];
    __shared__ int   sid[4][NP_];
    const int lane = threadIdx.x & 31, w = threadIdx.x >> 5;
    const int h = blockIdx.y;
    const int q = blockIdx.x * 4 + w;
    const size_t qi = (size_t)h * S_ + q;

    float4 qv = ((const float4*)(g_q + qi * DH_))[lane];
    for (int c = lane; c < NP_; c += 32) sid[w][c] = g_pooli[qi * NP_ + c];
    __syncwarp();

    for (int c = 0; c < NP_; c++){
        float4 kv = ((const float4*)(mem_keys + ((size_t)h * MK_ + sid[w][c]) * DH_))[lane];
        float d = qv.x*kv.x + qv.y*kv.y + qv.z*kv.z + qv.w*kv.w;
#pragma unroll
        for (int o = 16; o > 0; o >>= 1) d += __shfl_xor_sync(0xffffffffu, d, o);
        if (lane == 0) ssc[w][c] = d;
    }
    __syncwarp();

    float v1 = ssc[w][lane];
    float v2 = ssc[w][32 + lane];
    for (int it = 0; it < NN_; it++){
        float mvv; int mi;
        if (v1 >= v2){ mvv = v1; mi = lane; } else { mvv = v2; mi = 32 + lane; }
#pragma unroll
        for (int o = 16; o > 0; o >>= 1){
            float ov = __shfl_xor_sync(0xffffffffu, mvv, o);
            int   oi = __shfl_xor_sync(0xffffffffu, mi, o);
            if (ov > mvv || (ov == mvv && oi < mi)){ mvv = ov; mi = oi; }
        }
        if (mi < 32){ if (lane == mi) v1 = -3.0e38f; }
        else        { if (lane == mi - 32) v2 = -3.0e38f; }
        if (lane == 0){
            g_topv[qi * NN_ + it] = mvv;
            g_topi[qi * NN_ + it] = sid[w][mi];
        }
    }
}

// ---- flash attention: QK^T via tf32 MMA, PV exact SIMT ----
// smem: Q 4x8KB | K/V dbuf 2x16KB | Sc [64][130] | msh/lsh/csh | Ti [64][32]
#define AT_Q   0
#define AT_K   32768
#define AT_SC  65536
#define AT_MS  98816
#define AT_TI  99584
#define ATTN_SMEM 107776
__global__ void __launch_bounds__(256, 2) attn_kernel(const float* __restrict__ am,
                            const float* __restrict__ scale_param,
                            const float* __restrict__ mem_values)
{
    extern __shared__ char smraw[];
    uint32_t sb = smem_u32(smraw);
    float* Sc  = (float*)(smraw + AT_SC);    // [64][130]
    float* msh = (float*)(smraw + AT_MS);
    float* lsh = msh + 64;
    float* csh = lsh + 64;
    int*   Ti  = (int*)(smraw + AT_TI);      // [64][32]
    float* Vs  = (float*)(smraw + AT_K);     // V half [64][128], reuses K dbuf

    const int tid = threadIdx.x, lane = tid & 31, wid = tid >> 5;
    const int wm = wid >> 2, wn = wid & 3;
    const int h = blockIdx.y;
    const int q0 = (gridDim.x - 1 - blockIdx.x) * 64;
    const int ty = tid >> 4, tx = tid & 15;
    const int srow = tid >> 2, sl4 = tid & 3;
    const float scale = expf(scale_param[h]);

    // Q resident chunk tiles (64 rows x 4 chunks of 8KB)
    {
        int r = tid >> 2, part = tid & 3;
        const uint4* Ar = (const uint4*)(g_q + ((size_t)h * S_ + q0 + r) * DH_);
#pragma unroll
        for (int j = 0; j < 8; j++)
            *(uint4*)(smraw + AT_Q + part*8192 + SWZ(r*128 + j*16)) = Ar[part*8 + j];
    }
    for (int idx = tid; idx < 64 * 32; idx += 256) {
        int q = idx >> 5, n = idx & 31;
        Sc[q*130+n] = g_topv[((size_t)h * S_ + q0 + q) * NN_ + n] * scale;
        Ti[q*32+n]  = g_topi[((size_t)h * S_ + q0 + q) * NN_ + n];
    }
    __syncthreads();

    {   // mem softmax init (32 cols), rows srow x 4 lanes
        float mm = -3.0e38f;
#pragma unroll
        for (int j = 0; j < 8; j++) mm = fmaxf(mm, Sc[srow*130 + sl4*8 + j]);
        mm = fmaxf(mm, __shfl_xor_sync(0xffffffffu, mm, 1));
        mm = fmaxf(mm, __shfl_xor_sync(0xffffffffu, mm, 2));
        float ll = 0.f;
#pragma unroll
        for (int j = 0; j < 8; j++){
            float p = expf(Sc[srow*130 + sl4*8 + j] - mm);
            Sc[srow*130 + sl4*8 + j] = p; ll += p;
        }
        ll += __shfl_xor_sync(0xffffffffu, ll, 1);
        ll += __shfl_xor_sync(0xffffffffu, ll, 2);
        if (sl4 == 0){ msh[srow] = mm; lsh[srow] = ll; }
    }
    __syncthreads();

    float oacc[4][8];
#pragma unroll
    for (int i = 0; i < 4; i++)
#pragma unroll
        for (int j = 0; j < 8; j++) oacc[i][j] = 0.f;

#pragma unroll
    for (int i = 0; i < 4; i++) {
        int qr = ty * 4 + i;
        for (int n = 0; n < NN_; n++) {
            float w = Sc[qr*130+n];
            const float4* vr = (const float4*)(mem_values +
                ((size_t)h * MK_ + Ti[qr*32+n]) * DH_ + tx * 8);
            float4 v0 = vr[0], v1 = vr[1];
            oacc[i][0]+=w*v0.x; oacc[i][1]+=w*v0.y; oacc[i][2]+=w*v0.z; oacc[i][3]+=w*v0.w;
            oacc[i][4]+=w*v1.x; oacc[i][5]+=w*v1.y; oacc[i][6]+=w*v1.z; oacc[i][7]+=w*v1.w;
        }
    }

    float acc[32];
#pragma unroll
    for (int i = 0; i < 32; i++) acc[i] = 0.f;

    const int ntiles = (q0 >> 7) + 1;
    for (int t = 0; t < ntiles; t++){
        // load K chunk 0 -> buf0 (PV of prev tile synced)
#pragma unroll
        for (int i = 0; i < 4; i++){
            int g = tid + i * 256, r = g >> 3, u = g & 7;
            uint4 v = ((const uint4*)(g_k + ((size_t)h * S_ + t*128 + r) * DH_))[u];
            *(uint4*)(smraw + AT_K + SWZ(r*128 + u*16)) = v;
        }
        __syncthreads();
        for (int ci = 0; ci < 4; ci++){
            uint4 pb[4];
            if (ci < 3){
#pragma unroll
                for (int i = 0; i < 4; i++){
                    int g = tid + i * 256, r = g >> 3, u = g & 7;
                    pb[i] = ((const uint4*)(g_k + ((size_t)h * S_ + t*128 + r) * DH_))[(ci+1)*8 + u];
                }
            }
            mma_chunk<2>(sb + AT_Q + ci*8192, sb + AT_K + (ci&1)*16384, lane, wm, wn, acc);
            if (ci < 3){
                int nb = (ci+1) & 1;
#pragma unroll
                for (int i = 0; i < 4; i++){
                    int g = tid + i * 256, r = g >> 3, u = g & 7;
                    *(uint4*)(smraw + AT_K + nb*16384 + SWZ(r*128 + u*16)) = pb[i];
                }
            }
            __syncthreads();
        }
        {   // raw scores -> Sc
            const int gr = lane >> 2, gc2 = (lane & 3) * 2;
#pragma unroll
            for (int mt = 0; mt < 2; mt++)
#pragma unroll
                for (int nt = 0; nt < 4; nt++){
                    float* cp = acc + (mt*4+nt)*4;
                    int r = wm*32 + mt*16 + gr, col = wn*32 + nt*8 + gc2;
                    *(float2*)(Sc + r*130 + col)     = make_float2(cp[0], cp[1]);
                    *(float2*)(Sc + (r+8)*130 + col) = make_float2(cp[2], cp[3]);
                }
#pragma unroll
            for (int i = 0; i < 32; i++) acc[i] = 0.f;
        }
        __syncthreads();

        {   // masked softmax over 128 cols: rows srow x 4 lanes (32 cols each)
            const int qg = q0 + srow;
            float mm = msh[srow], rmax = mm;
#pragma unroll
            for (int j = 0; j < 32; j++){
                int kg = t*128 + sl4*32 + j;
                float s = Sc[srow*130 + sl4*32 + j];
                float v = (kg <= qg) ? (s * scale + am[kg]) : -1.0e30f;
                rmax = fmaxf(rmax, v);
            }
            rmax = fmaxf(rmax, __shfl_xor_sync(0xffffffffu, rmax, 1));
            rmax = fmaxf(rmax, __shfl_xor_sync(0xffffffffu, rmax, 2));
            float cor = expf(mm - rmax);
            float ll = (sl4 == 0) ? lsh[srow] * cor : 0.f;
#pragma unroll
            for (int j = 0; j < 32; j++){
                int kg = t*128 + sl4*32 + j;
                float s = Sc[srow*130 + sl4*32 + j];
                float v = (kg <= qg) ? (s * scale + am[kg]) : -1.0e30f;
                float p = expf(v - rmax);
                Sc[srow*130 + sl4*32 + j] = p;
                ll += p;
            }
            ll += __shfl_xor_sync(0xffffffffu, ll, 1);
            ll += __shfl_xor_sync(0xffffffffu, ll, 2);
            if (sl4 == 0){ msh[srow] = rmax; lsh[srow] = ll; csh[srow] = cor; }
        }
        __syncthreads();

        // PV in two 64-key halves (V reuses the K dbuf region)
        for (int ph = 0; ph < 2; ph++){
            for (int idx = tid; idx < 64 * 32; idx += 256){
                int row = idx >> 5, seg = idx & 31;
                *(float4*)&Vs[row*128 + seg*4] =
                    *(const float4*)(g_v + ((size_t)h * S_ + t*128 + ph*64 + row) * DH_ + seg*4);
            }
            __syncthreads();
#pragma unroll
            for (int i = 0; i < 4; i++){
                int qr = ty*4 + i;
                if (ph == 0){
                    float cor = csh[qr];
#pragma unroll
                    for (int j = 0; j < 8; j++) oacc[i][j] *= cor;
                }
                for (int n = 0; n < 64; n++){
                    float w = Sc[qr*130 + ph*64 + n];
                    float4 v0 = *(const float4*)&Vs[n*128 + tx*8];
                    float4 v1 = *(const float4*)&Vs[n*128 + tx*8 + 4];
                    oacc[i][0]+=w*v0.x; oacc[i][1]+=w*v0.y; oacc[i][2]+=w*v0.z; oacc[i][3]+=w*v0.w;
                    oacc[i][4]+=w*v1.x; oacc[i][5]+=w*v1.y; oacc[i][6]+=w*v1.z; oacc[i][7]+=w*v1.w;
                }
            }
            __syncthreads();
        }
    }

#pragma unroll
    for (int i = 0; i < 4; i++) {
        int qr = ty*4 + i;
        float inv = 1.0f / lsh[qr];
#pragma unroll
        for (int j = 0; j < 8; j++)
            g_ctx[(size_t)(q0+qr) * H_ + h*DH_ + tx*8 + j] = oacc[i][j] * inv;
    }
}

extern "C" void kernel_launch(void* const* d_in, const int* in_sizes, int n_in,
                              void* d_out, int out_size)
{
    const float* hidden      = (const float*)d_in[0];
    const float* am          = (const float*)d_in[1];
    const int*   pos         = (const int*)d_in[2];
    const float* Wqkv        = (const float*)d_in[3];
    const float* bqkv        = (const float*)d_in[4];
    const float* Wd          = (const float*)d_in[5];
    const float* bd          = (const float*)d_in[6];
    const float* scale_param = (const float*)d_in[7];
    const float* mem_keys    = (const float*)d_in[8];
    const float* mem_values  = (const float*)d_in[9];
    float*       out         = (float*)d_out;

    cudaFuncSetAttribute(out_mma_kernel,    cudaFuncAttributeMaxDynamicSharedMemorySize, GEMM_SMEM);
    cudaFuncSetAttribute(qkv_kv_mma_kernel, cudaFuncAttributeMaxDynamicSharedMemorySize, GEMM_SMEM);
    cudaFuncSetAttribute(knn_pool_kernel,   cudaFuncAttributeMaxDynamicSharedMemorySize, KNP_SMEM);
    cudaFuncSetAttribute(attn_kernel,       cudaFuncAttributeMaxDynamicSharedMemorySize, ATTN_SMEM);

    split_kernel<<<2048, 256>>>(Wqkv,   HQKV_ * H_, H_, 0);
    split_kernel<<<512,  256>>>(hidden, S_ * H_,    H_, 1);

    qkv_q_kernel<<<dim3(NH_, S_/128), 256>>>(hidden, Wqkv, bqkv);
    qkv_kv_mma_kernel<<<dim3(2*NH_, S_/128), 256, GEMM_SMEM>>>(bqkv);
    norm_rope_kernel<<<dim3(S_, NH_), 128>>>(pos);
    knn_pool_kernel<<<dim3(S_/64, NH_), 256, KNP_SMEM>>>(mem_keys);
    rescore_kernel<<<dim3(S_/4, NH_), 128>>>(mem_keys);
    attn_kernel<<<dim3(S_/64, NH_), 256, ATTN_SMEM>>>(am, scale_param, mem_values);

    split_kernel<<<512,  256>>>(hidden, S_ * H_, H_, 3);
    split_kernel<<<1024, 256>>>(Wd,     H_ * H_, H_, 4);
    out_mma_kernel<<<dim3(H_/128, S_/128), 256, GEMM_SMEM>>>(bd, out);
}

// round 13
// speedup vs baseline: 1.5869x; 1.0090x over previous
#include <cuda_runtime.h>
#include <math.h>
#include <stdint.h>

#define S_    1024
#define H_    2048
#define NH_   16
#define DH_   128
#define NN_   32
#define NP_   64
#define MK_   8192
#define HQKV_ 6144
#define KB_   6144

__device__ __align__(16) float g_qkv[S_ * HQKV_];
__device__ __align__(16) float g_q  [NH_ * S_ * DH_];
__device__ __align__(16) float g_k  [NH_ * S_ * DH_];
__device__ __align__(16) float g_v  [NH_ * S_ * DH_];
__device__ __align__(16) float g_topv[NH_ * S_ * NN_];
__device__ __align__(16) int   g_topi[NH_ * S_ * NN_];
__device__ __align__(16) int   g_pooli[NH_ * S_ * NP_];

__device__ __align__(16) float g_ctx_s [S_ * KB_];
__device__ __align__(16) float g_wd_s  [(size_t)H_ * KB_];
__device__ __align__(16) float g_hid_s [S_ * KB_];
__device__ __align__(16) float g_wqkv_s[(size_t)HQKV_ * KB_];

static __device__ __forceinline__ uint32_t smem_u32(const void* p){
    uint32_t a;
    asm("{ .reg .u64 t; cvta.to.shared.u64 t, %1; cvt.u32.u64 %0, t; }" : "=r"(a) : "l"(p));
    return a;
}
__device__ __forceinline__ int SWZ(int x){ return x ^ (((x) >> 3) & 0x70); }
__device__ __forceinline__ float to_tf32(float x){
    float r; asm("cvt.rna.tf32.f32 %0, %1;" : "=f"(r) : "f"(x)); return r;
}
__device__ __forceinline__ void ldsm4(uint32_t* r, uint32_t a){
    asm volatile("ldmatrix.sync.aligned.m8n8.x4.shared.b16 {%0,%1,%2,%3}, [%4];"
        : "=r"(r[0]), "=r"(r[1]), "=r"(r[2]), "=r"(r[3]) : "r"(a));
}
__device__ __forceinline__ void mmat(float* c, const uint32_t* a, uint32_t b0, uint32_t b1){
    asm volatile(
        "mma.sync.aligned.m16n8k8.row.col.f32.tf32.tf32.f32 "
        "{%0,%1,%2,%3}, {%4,%5,%6,%7}, {%8,%9}, {%0,%1,%2,%3};"
        : "+f"(c[0]), "+f"(c[1]), "+f"(c[2]), "+f"(c[3])
        : "r"(a[0]), "r"(a[1]), "r"(a[2]), "r"(a[3]), "r"(b0), "r"(b1));
}

template<int MT>
__device__ __forceinline__ void mma_chunk(uint32_t sA, uint32_t sB,
                                          int lane, int wm, int wn, float* acc){
    const int rl = lane & 15, uh = lane >> 4;
#pragma unroll
    for (int ks = 0; ks < 4; ks++){
        uint32_t a[MT][4], b[2][4];
#pragma unroll
        for (int mt = 0; mt < MT; mt++)
            ldsm4(a[mt], sA + SWZ((wm*(MT*16) + mt*16 + rl)*128 + (ks*2+uh)*16));
#pragma unroll
        for (int bt = 0; bt < 2; bt++)
            ldsm4(b[bt], sB + SWZ((wn*32 + bt*16 + rl)*128 + (ks*2+uh)*16));
#pragma unroll
        for (int mt = 0; mt < MT; mt++)
#pragma unroll
            for (int nt = 0; nt < 4; nt++)
                mmat(acc + (mt*4+nt)*4, a[mt], b[nt>>1][nt&1], b[nt>>1][(nt&1)+2]);
    }
}

// ---- one combined split launch: Wqkv(B), hidden(A), Wd(B) ----
#define SPL_NB0 2048
#define SPL_NB1 512
#define SPL_NB2 1024
__global__ void split_all_kernel(const float* __restrict__ Wqkv,
                                 const float* __restrict__ hidden,
                                 const float* __restrict__ Wd)
{
    int b = blockIdx.x;
    const float* s; float* d; int total, atype = 0, bstart, nb;
    if (b < SPL_NB0){ s = Wqkv;   d = g_wqkv_s; total = HQKV_ * H_; bstart = 0; nb = SPL_NB0; }
    else if (b < SPL_NB0 + SPL_NB1){
        s = hidden; d = g_hid_s; total = S_ * H_; atype = 1; bstart = SPL_NB0; nb = SPL_NB1; }
    else { s = Wd; d = g_wd_s; total = H_ * H_; bstart = SPL_NB0 + SPL_NB1; nb = SPL_NB2; }

    for (int i = (b - bstart) * 256 + threadIdx.x; i < total; i += nb * 256){
        float x  = s[i];
        float hi = to_tf32(x);
        float lo = to_tf32(x - hi);
        int r = i / H_, k = i - r * H_;
        size_t base = (size_t)r * 3 * H_ + k;
        d[base] = hi;
        d[base + H_]     = atype ? lo : hi;
        d[base + 2 * H_] = atype ? hi : lo;
    }
}

// ---- shared tf32 MMA 128x128 tile body ----
#define GEMM_SMEM 65536
__device__ __forceinline__ void gemm_mma_tile(const float* __restrict__ A,
                                              const float* __restrict__ B,
                                              const float* __restrict__ bias,
                                              float* __restrict__ C,
                                              int N, int K, int m0, int n0)
{
    extern __shared__ char smraw[];
    uint32_t sb = smem_u32(smraw);
    const int tid = threadIdx.x, lane = tid & 31, wid = tid >> 5;
    const int wm = wid >> 2, wn = wid & 3;
    const int nch = K >> 5;

    float acc[64];
#pragma unroll
    for (int i = 0; i < 64; i++) acc[i] = 0.f;

#pragma unroll
    for (int i = 0; i < 4; i++){
        int g = tid + i * 256, r = g >> 3, u = g & 7;
        uint4 va = ((const uint4*)(A + (size_t)(m0 + r) * K))[u];
        uint4 vb = ((const uint4*)(B + (size_t)(n0 + r) * K))[u];
        *(uint4*)(smraw + SWZ(r*128 + u*16)) = va;
        *(uint4*)(smraw + 32768 + SWZ(r*128 + u*16)) = vb;
    }
    __syncthreads();

    for (int c = 0; c < nch; c++){
        const int buf = c & 1;
        uint4 pa[4], pb[4];
        if (c + 1 < nch){
#pragma unroll
            for (int i = 0; i < 4; i++){
                int g = tid + i * 256, r = g >> 3, u = g & 7;
                pa[i] = ((const uint4*)(A + (size_t)(m0 + r) * K))[(c+1)*8 + u];
                pb[i] = ((const uint4*)(B + (size_t)(n0 + r) * K))[(c+1)*8 + u];
            }
        }
        mma_chunk<4>(sb + buf*16384, sb + 32768 + buf*16384, lane, wm, wn, acc);
        if (c + 1 < nch){
            int nb = buf ^ 1;
#pragma unroll
            for (int i = 0; i < 4; i++){
                int g = tid + i * 256, r = g >> 3, u = g & 7;
                *(uint4*)(smraw + nb*16384 + SWZ(r*128 + u*16)) = pa[i];
                *(uint4*)(smraw + 32768 + nb*16384 + SWZ(r*128 + u*16)) = pb[i];
            }
        }
        __syncthreads();
    }

    const int gr = lane >> 2, gc2 = (lane & 3) * 2;
#pragma unroll
    for (int mt = 0; mt < 4; mt++)
#pragma unroll
        for (int nt = 0; nt < 4; nt++){
            const float* cp = acc + (mt*4+nt)*4;
            int r = m0 + wm*64 + mt*16 + gr;
            int col = n0 + wn*32 + nt*8 + gc2;
            float b0 = bias[col], b1 = bias[col+1];
            *(float2*)(C + (size_t)r * N + col)     = make_float2(cp[0]+b0, cp[1]+b1);
            *(float2*)(C + (size_t)(r+8) * N + col) = make_float2(cp[2]+b0, cp[3]+b1);
        }
}

__global__ void __launch_bounds__(256) out_mma_kernel(const float* __restrict__ bias,
                                                      float* __restrict__ C)
{
    gemm_mma_tile(g_ctx_s, g_wd_s, bias, C, H_, KB_,
                  blockIdx.y * 128, blockIdx.x * 128);
}

// ---- fat qkv: SIMT-exact q (FMA pipe) + tf32-MMA k,v (tensor pipe), one launch
__global__ void __launch_bounds__(256) qkv_fat_kernel(const float* __restrict__ A,
                                                      const float* __restrict__ B,
                                                      const float* __restrict__ bias)
{
    extern __shared__ char smraw[];
    if (blockIdx.x >= NH_){
        const int idx = blockIdx.x - NH_;
        const int t = idx >> 1, which = 1 + (idx & 1);
        gemm_mma_tile(g_hid_s, g_wqkv_s, bias, g_qkv, HQKV_, KB_,
                      blockIdx.y * 128, t * 384 + which * 128);
        return;
    }
    // exact SIMT fp32 q path
    const int N = HQKV_, K = H_;
    float* As = (float*)smraw;
    float* Bs = As + 1024;
    const int tid  = threadIdx.x;
    const int m0   = blockIdx.y * 128;
    const int n0   = blockIdx.x * 384;
    const int ty   = tid >> 4, tx = tid & 15;
    const int lrow = tid >> 1, lk4 = (tid & 1) * 4;

    float c[8][8];
#pragma unroll
    for (int i = 0; i < 8; i++)
#pragma unroll
        for (int j = 0; j < 8; j++) c[i][j] = 0.f;

    const float* Ab = A + (size_t)(m0 + lrow) * K + lk4;
    const float* Bb = B + (size_t)(n0 + lrow) * K + lk4;

    for (int k0 = 0; k0 < K; k0 += 8) {
        float4 av = *(const float4*)(Ab + k0);
        float4 bv = *(const float4*)(Bb + k0);
        As[(lk4+0)*128+lrow] = av.x; As[(lk4+1)*128+lrow] = av.y;
        As[(lk4+2)*128+lrow] = av.z; As[(lk4+3)*128+lrow] = av.w;
        Bs[(lk4+0)*128+lrow] = bv.x; Bs[(lk4+1)*128+lrow] = bv.y;
        Bs[(lk4+2)*128+lrow] = bv.z; Bs[(lk4+3)*128+lrow] = bv.w;
        __syncthreads();
#pragma unroll
        for (int kk = 0; kk < 8; kk++) {
            float a[8], b[8];
            *(float4*)&a[0] = *(const float4*)&As[kk*128 + ty*8];
            *(float4*)&a[4] = *(const float4*)&As[kk*128 + ty*8 + 4];
            *(float4*)&b[0] = *(const float4*)&Bs[kk*128 + tx*8];
            *(float4*)&b[4] = *(const float4*)&Bs[kk*128 + tx*8 + 4];
#pragma unroll
            for (int i = 0; i < 8; i++)
#pragma unroll
                for (int j = 0; j < 8; j++) c[i][j] += a[i] * b[j];
        }
        __syncthreads();
    }
#pragma unroll
    for (int i = 0; i < 8; i++) {
        int row = m0 + ty * 8 + i;
#pragma unroll
        for (int j = 0; j < 8; j++) {
            int col = n0 + tx * 8 + j;
            g_qkv[(size_t)row * N + col] = c[i][j] + bias[col];
        }
    }
}

// ---- norm + rope ----
__global__ void norm_rope_kernel(const int* __restrict__ pos)
{
    const int s = blockIdx.x, h = blockIdx.y, d = threadIdx.x;
    const float* base = g_qkv + (size_t)s * HQKV_ + h * (3 * DH_);
    float qv = base[d], kv = base[DH_ + d], vv = base[2 * DH_ + d];

    float sq = qv * qv, sk = kv * kv;
#pragma unroll
    for (int o = 16; o > 0; o >>= 1) {
        sq += __shfl_xor_sync(0xffffffffu, sq, o);
        sk += __shfl_xor_sync(0xffffffffu, sk, o);
    }
    __shared__ float rq[4], rk[4];
    if ((d & 31) == 0) { rq[d >> 5] = sq; rk[d >> 5] = sk; }
    __syncthreads();
    float nq = sqrtf(rq[0] + rq[1] + rq[2] + rq[3]);
    float nk = sqrtf(rk[0] + rk[1] + rk[2] + rk[3]);
    float qn = qv / fmaxf(nq, 1e-12f);
    float kn = kv / fmaxf(nk, 1e-12f);

    __shared__ float qs[DH_], ks[DH_];
    qs[d] = qn; ks[d] = kn;
    __syncthreads();

    float qo = qn, ko = kn;
    if (d < 32) {
        int i = (d < 16) ? d : d - 16;
        float freq = powf(10000.0f, -(float)i / 16.0f);
        float ang  = (float)pos[s] * freq;
        float cs = cosf(ang), sn = sinf(ang);
        float rqh = (d < 16) ? -qs[d + 16] : qs[d - 16];
        float rkh = (d < 16) ? -ks[d + 16] : ks[d - 16];
        qo = qn * cs + rqh * sn;
        ko = kn * cs + rkh * sn;
    }
    size_t o = ((size_t)h * S_ + s) * DH_ + d;
    g_q[o] = qo; g_k[o] = ko; g_v[o] = vv;
}

// ---- kNN pool (unchanged) ----
#define KNA   0
#define KNB   32768
#define KNSC  65536
#define KNTI  98816
#define KNP_SMEM 107008
__global__ void __launch_bounds__(256, 2) knn_pool_kernel(const float* __restrict__ mem_keys)
{
    extern __shared__ char smraw[];
    uint32_t sb = smem_u32(smraw);
    const int tid = threadIdx.x, lane = tid & 31, wid = tid >> 5;
    const int wm = wid >> 2, wn = wid & 3;
    const int h = blockIdx.y, q0 = blockIdx.x * 64;
    float* Sc = (float*)(smraw + KNSC);
    unsigned short* Ti = (unsigned short*)(smraw + KNTI);

    const int half = lane >> 4, hl = lane & 15;
    const unsigned hmask = half ? 0xffff0000u : 0x0000ffffu;
    const int qbase = wid * 8;

    {
        int r = tid >> 2, part = tid & 3;
        const uint4* Ar = (const uint4*)(g_q + ((size_t)h * S_ + q0 + r) * DH_);
#pragma unroll
        for (int j = 0; j < 8; j++)
            *(uint4*)(smraw + KNA + part*8192 + SWZ(r*128 + j*16)) = Ar[part*8 + j];
    }
#pragma unroll
    for (int i = 0; i < 4; i++){
        int g = tid + i * 256, r = g >> 3, u = g & 7;
        uint4 v = ((const uint4*)(mem_keys + ((size_t)h * MK_ + r) * DH_))[u];
        *(uint4*)(smraw + KNB + SWZ(r*128 + u*16)) = v;
    }
    __syncthreads();

    float pv[4][4];
    float mv[4];
#pragma unroll
    for (int p = 0; p < 4; p++){
        mv[p] = -3.0e38f;
#pragma unroll
        for (int j = 0; j < 4; j++) pv[p][j] = -3.0e38f;
    }

    float acc[32];
#pragma unroll
    for (int i = 0; i < 32; i++) acc[i] = 0.f;

    for (int g = 0; g < 64 * 4; g++){
        const int t = g >> 2, ci = g & 3;
        const int buf = g & 1;
        uint4 pb[4];
        if (g + 1 < 64 * 4){
            int tn = (g + 1) >> 2, cn = (g + 1) & 3;
#pragma unroll
            for (int i = 0; i < 4; i++){
                int gi = tid + i * 256, r = gi >> 3, u = gi & 7;
                pb[i] = ((const uint4*)(mem_keys +
                         ((size_t)h * MK_ + tn * 128 + r) * DH_))[cn*8 + u];
            }
        }
        mma_chunk<2>(sb + KNA + ci*8192, sb + KNB + buf*16384, lane, wm, wn, acc);
        if (g + 1 < 64 * 4){
            int nb = buf ^ 1;
#pragma unroll
            for (int i = 0; i < 4; i++){
                int gi = tid + i * 256, r = gi >> 3, u = gi & 7;
                *(uint4*)(smraw + KNB + nb*16384 + SWZ(r*128 + u*16)) = pb[i];
            }
        }
        __syncthreads();

        if (ci == 3){
            const int gr = lane >> 2, gc2 = (lane & 3) * 2;
#pragma unroll
            for (int mt = 0; mt < 2; mt++)
#pragma unroll
                for (int nt = 0; nt < 4; nt++){
                    float* cp = acc + (mt*4+nt)*4;
                    int r = wm*32 + mt*16 + gr, col = wn*32 + nt*8 + gc2;
                    *(float2*)(Sc + r*130 + col)     = make_float2(cp[0], cp[1]);
                    *(float2*)(Sc + (r+8)*130 + col) = make_float2(cp[2], cp[3]);
                }
#pragma unroll
            for (int i = 0; i < 32; i++) acc[i] = 0.f;
            __syncthreads();

            for (int p = 0; p < 4; p++){
                const int q = qbase + p*2 + half;
                const float* srow = Sc + q*130;
                float m_ = mv[p];
                int seg0 = 0;
                if (t == 0){
#pragma unroll
                    for (int j = 0; j < 4; j++){
                        pv[p][j] = srow[hl*4 + j];
                        Ti[q*64 + hl*4 + j] = (unsigned short)(hl*4 + j);
                    }
                    float pm = pv[p][0];
#pragma unroll
                    for (int j = 1; j < 4; j++) pm = fminf(pm, pv[p][j]);
#pragma unroll
                    for (int o = 8; o > 0; o >>= 1)
                        pm = fminf(pm, __shfl_xor_sync(hmask, pm, o));
                    m_ = pm;
                    seg0 = 4;
                }
                for (int seg = seg0; seg < 8; seg++){
                    float s = srow[seg*16 + hl];
                    unsigned bal = __ballot_sync(0xffffffffu, s > m_);
                    unsigned m = (bal >> (half*16)) & 0xffffu;
                    while (m){
                        int b = __ffs(m) - 1; m &= m - 1;
                        float sv = __shfl_sync(hmask, s, half*16 + b);
                        float pm = pv[p][0]; int pc = 0;
#pragma unroll
                        for (int j = 1; j < 4; j++)
                            if (pv[p][j] < pm){ pm = pv[p][j]; pc = j; }
                        int code = hl*4 + pc;
#pragma unroll
                        for (int o = 8; o > 0; o >>= 1){
                            float ov = __shfl_xor_sync(hmask, pm, o);
                            int   oc = __shfl_xor_sync(hmask, code, o);
                            if (ov < pm || (ov == pm && oc < code)){ pm = ov; code = oc; }
                        }
                        if (sv > pm && hl == (code >> 2)){
                            pv[p][code & 3] = sv;
                            Ti[q*64 + code] = (unsigned short)(t*128 + seg*16 + b);
                        }
                        m_ = pm;
                    }
                }
                mv[p] = m_;
            }
            __syncthreads();
        }
    }
    for (int i = tid; i < 64 * NP_; i += 256)
        g_pooli[((size_t)h * S_ + q0 + (i >> 6)) * NP_ + (i & 63)] = (int)Ti[i];
}

// ---- exact fp32 rescore (unchanged) ----
__global__ void rescore_kernel(const float* __restrict__ mem_keys)
{
    __shared__ float ssc[4][NP_];
    __shared__ int   sid[4][NP_];
    const int lane = threadIdx.x & 31, w = threadIdx.x >> 5;
    const int h = blockIdx.y;
    const int q = blockIdx.x * 4 + w;
    const size_t qi = (size_t)h * S_ + q;

    float4 qv = ((const float4*)(g_q + qi * DH_))[lane];
    for (int c = lane; c < NP_; c += 32) sid[w][c] = g_pooli[qi * NP_ + c];
    __syncwarp();

    for (int c = 0; c < NP_; c++){
        float4 kv = ((const float4*)(mem_keys + ((size_t)h * MK_ + sid[w][c]) * DH_))[lane];
        float d = qv.x*kv.x + qv.y*kv.y + qv.z*kv.z + qv.w*kv.w;
#pragma unroll
        for (int o = 16; o > 0; o >>= 1) d += __shfl_xor_sync(0xffffffffu, d, o);
        if (lane == 0) ssc[w][c] = d;
    }
    __syncwarp();

    float v1 = ssc[w][lane];
    float v2 = ssc[w][32 + lane];
    for (int it = 0; it < NN_; it++){
        float mvv; int mi;
        if (v1 >= v2){ mvv = v1; mi = lane; } else { mvv = v2; mi = 32 + lane; }
#pragma unroll
        for (int o = 16; o > 0; o >>= 1){
            float ov = __shfl_xor_sync(0xffffffffu, mvv, o);
            int   oi = __shfl_xor_sync(0xffffffffu, mi, o);
            if (ov > mvv || (ov == mvv && oi < mi)){ mvv = ov; mi = oi; }
        }
        if (mi < 32){ if (lane == mi) v1 = -3.0e38f; }
        else        { if (lane == mi - 32) v2 = -3.0e38f; }
        if (lane == 0){
            g_topv[qi * NN_ + it] = mvv;
            g_topi[qi * NN_ + it] = sid[w][mi];
        }
    }
}

// ---- flash attention: QK^T via tf32 MMA, PV exact SIMT; writes ctx_s ----
#define AT_Q   0
#define AT_K   32768
#define AT_SC  65536
#define AT_MS  98816
#define AT_TI  99584
#define ATTN_SMEM 107776
__global__ void __launch_bounds__(256, 2) attn_kernel(const float* __restrict__ am,
                            const float* __restrict__ scale_param,
                            const float* __restrict__ mem_values)
{
    extern __shared__ char smraw[];
    uint32_t sb = smem_u32(smraw);
    float* Sc  = (float*)(smraw + AT_SC);
    float* msh = (float*)(smraw + AT_MS);
    float* lsh = msh + 64;
    float* csh = lsh + 64;
    int*   Ti  = (int*)(smraw + AT_TI);
    float* Vs  = (float*)(smraw + AT_K);

    const int tid = threadIdx.x, lane = tid & 31, wid = tid >> 5;
    const int wm = wid >> 2, wn = wid & 3;
    const int h = blockIdx.y;
    const int q0 = (gridDim.x - 1 - blockIdx.x) * 64;
    const int ty = tid >> 4, tx = tid & 15;
    const int srow = tid >> 2, sl4 = tid & 3;
    const float scale = expf(scale_param[h]);

    {
        int r = tid >> 2, part = tid & 3;
        const uint4* Ar = (const uint4*)(g_q + ((size_t)h * S_ + q0 + r) * DH_);
#pragma unroll
        for (int j = 0; j < 8; j++)
            *(uint4*)(smraw + AT_Q + part*8192 + SWZ(r*128 + j*16)) = Ar[part*8 + j];
    }
    for (int idx = tid; idx < 64 * 32; idx += 256) {
        int q = idx >> 5, n = idx & 31;
        Sc[q*130+n] = g_topv[((size_t)h * S_ + q0 + q) * NN_ + n] * scale;
        Ti[q*32+n]  = g_topi[((size_t)h * S_ + q0 + q) * NN_ + n];
    }
    __syncthreads();

    {
        float mm = -3.0e38f;
#pragma unroll
        for (int j = 0; j < 8; j++) mm = fmaxf(mm, Sc[srow*130 + sl4*8 + j]);
        mm = fmaxf(mm, __shfl_xor_sync(0xffffffffu, mm, 1));
        mm = fmaxf(mm, __shfl_xor_sync(0xffffffffu, mm, 2));
        float ll = 0.f;
#pragma unroll
        for (int j = 0; j < 8; j++){
            float p = expf(Sc[srow*130 + sl4*8 + j] - mm);
            Sc[srow*130 + sl4*8 + j] = p; ll += p;
        }
        ll += __shfl_xor_sync(0xffffffffu, ll, 1);
        ll += __shfl_xor_sync(0xffffffffu, ll, 2);
        if (sl4 == 0){ msh[srow] = mm; lsh[srow] = ll; }
    }
    __syncthreads();

    float oacc[4][8];
#pragma unroll
    for (int i = 0; i < 4; i++)
#pragma unroll
        for (int j = 0; j < 8; j++) oacc[i][j] = 0.f;

#pragma unroll
    for (int i = 0; i < 4; i++) {
        int qr = ty * 4 + i;
        for (int n = 0; n < NN_; n++) {
            float w = Sc[qr*130+n];
            const float4* vr = (const float4*)(mem_values +
                ((size_t)h * MK_ + Ti[qr*32+n]) * DH_ + tx * 8);
            float4 v0 = vr[0], v1 = vr[1];
            oacc[i][0]+=w*v0.x; oacc[i][1]+=w*v0.y; oacc[i][2]+=w*v0.z; oacc[i][3]+=w*v0.w;
            oacc[i][4]+=w*v1.x; oacc[i][5]+=w*v1.y; oacc[i][6]+=w*v1.z; oacc[i][7]+=w*v1.w;
        }
    }

    float acc[32];
#pragma unroll
    for (int i = 0; i < 32; i++) acc[i] = 0.f;

    const int ntiles = (q0 >> 7) + 1;
    for (int t = 0; t < ntiles; t++){
#pragma unroll
        for (int i = 0; i < 4; i++){
            int g = tid + i * 256, r = g >> 3, u = g & 7;
            uint4 v = ((const uint4*)(g_k + ((size_t)h * S_ + t*128 + r) * DH_))[u];
            *(uint4*)(smraw + AT_K + SWZ(r*128 + u*16)) = v;
        }
        __syncthreads();
        for (int ci = 0; ci < 4; ci++){
            uint4 pb[4];
            if (ci < 3){
#pragma unroll
                for (int i = 0; i < 4; i++){
                    int g = tid + i * 256, r = g >> 3, u = g & 7;
                    pb[i] = ((const uint4*)(g_k + ((size_t)h * S_ + t*128 + r) * DH_))[(ci+1)*8 + u];
                }
            }
            mma_chunk<2>(sb + AT_Q + ci*8192, sb + AT_K + (ci&1)*16384, lane, wm, wn, acc);
            if (ci < 3){
                int nb = (ci+1) & 1;
#pragma unroll
                for (int i = 0; i < 4; i++){
                    int g = tid + i * 256, r = g >> 3, u = g & 7;
                    *(uint4*)(smraw + AT_K + nb*16384 + SWZ(r*128 + u*16)) = pb[i];
                }
            }
            __syncthreads();
        }
        {
            const int gr = lane >> 2, gc2 = (lane & 3) * 2;
#pragma unroll
            for (int mt = 0; mt < 2; mt++)
#pragma unroll
                for (int nt = 0; nt < 4; nt++){
                    float* cp = acc + (mt*4+nt)*4;
                    int r = wm*32 + mt*16 + gr, col = wn*32 + nt*8 + gc2;
                    *(float2*)(Sc + r*130 + col)     = make_float2(cp[0], cp[1]);
                    *(float2*)(Sc + (r+8)*130 + col) = make_float2(cp[2], cp[3]);
                }
#pragma unroll
            for (int i = 0; i < 32; i++) acc[i] = 0.f;
        }
        __syncthreads();

        {
            const int qg = q0 + srow;
            float mm = msh[srow], rmax = mm;
#pragma unroll
            for (int j = 0; j < 32; j++){
                int kg = t*128 + sl4*32 + j;
                float s = Sc[srow*130 + sl4*32 + j];
                float v = (kg <= qg) ? (s * scale + am[kg]) : -1.0e30f;
                rmax = fmaxf(rmax, v);
            }
            rmax = fmaxf(rmax, __shfl_xor_sync(0xffffffffu, rmax, 1));
            rmax = fmaxf(rmax, __shfl_xor_sync(0xffffffffu, rmax, 2));
            float cor = expf(mm - rmax);
            float ll = (sl4 == 0) ? lsh[srow] * cor : 0.f;
#pragma unroll
            for (int j = 0; j < 32; j++){
                int kg = t*128 + sl4*32 + j;
                float s = Sc[srow*130 + sl4*32 + j];
                float v = (kg <= qg) ? (s * scale + am[kg]) : -1.0e30f;
                float p = expf(v - rmax);
                Sc[srow*130 + sl4*32 + j] = p;
                ll += p;
            }
            ll += __shfl_xor_sync(0xffffffffu, ll, 1);
            ll += __shfl_xor_sync(0xffffffffu, ll, 2);
            if (sl4 == 0){ msh[srow] = rmax; lsh[srow] = ll; csh[srow] = cor; }
        }
        __syncthreads();

        for (int ph = 0; ph < 2; ph++){
            for (int idx = tid; idx < 64 * 32; idx += 256){
                int row = idx >> 5, seg = idx & 31;
                *(float4*)&Vs[row*128 + seg*4] =
                    *(const float4*)(g_v + ((size_t)h * S_ + t*128 + ph*64 + row) * DH_ + seg*4);
            }
            __syncthreads();
#pragma unroll
            for (int i = 0; i < 4; i++){
                int qr = ty*4 + i;
                if (ph == 0){
                    float cor = csh[qr];
#pragma unroll
                    for (int j = 0; j < 8; j++) oacc[i][j] *= cor;
                }
                for (int n = 0; n < 64; n++){
                    float w = Sc[qr*130 + ph*64 + n];
                    float4 v0 = *(const float4*)&Vs[n*128 + tx*8];
                    float4 v1 = *(const float4*)&Vs[n*128 + tx*8 + 4];
                    oacc[i][0]+=w*v0.x; oacc[i][1]+=w*v0.y; oacc[i][2]+=w*v0.z; oacc[i][3]+=w*v0.w;
                    oacc[i][4]+=w*v1.x; oacc[i][5]+=w*v1.y; oacc[i][6]+=w*v1.z; oacc[i][7]+=w*v1.w;
                }
            }
            __syncthreads();
        }
    }

    // epilogue: normalize + write hi/lo/hi directly into ctx_s (A-type)
#pragma unroll
    for (int i = 0; i < 4; i++) {
        int qr = ty*4 + i;
        float inv = 1.0f / lsh[qr];
#pragma unroll
        for (int j = 0; j < 8; j++){
            float x  = oacc[i][j] * inv;
            float hi = to_tf32(x);
            float lo = to_tf32(x - hi);
            size_t base = (size_t)(q0+qr) * KB_ + h*DH_ + tx*8 + j;
            g_ctx_s[base]          = hi;
            g_ctx_s[base + H_]     = lo;
            g_ctx_s[base + 2*H_]   = hi;
        }
    }
}

extern "C" void kernel_launch(void* const* d_in, const int* in_sizes, int n_in,
                              void* d_out, int out_size)
{
    const float* hidden      = (const float*)d_in[0];
    const float* am          = (const float*)d_in[1];
    const int*   pos         = (const int*)d_in[2];
    const float* Wqkv        = (const float*)d_in[3];
    const float* bqkv        = (const float*)d_in[4];
    const float* Wd          = (const float*)d_in[5];
    const float* bd          = (const float*)d_in[6];
    const float* scale_param = (const float*)d_in[7];
    const float* mem_keys    = (const float*)d_in[8];
    const float* mem_values  = (const float*)d_in[9];
    float*       out         = (float*)d_out;

    cudaFuncSetAttribute(out_mma_kernel,  cudaFuncAttributeMaxDynamicSharedMemorySize, GEMM_SMEM);
    cudaFuncSetAttribute(qkv_fat_kernel,  cudaFuncAttributeMaxDynamicSharedMemorySize, GEMM_SMEM);
    cudaFuncSetAttribute(knn_pool_kernel, cudaFuncAttributeMaxDynamicSharedMemorySize, KNP_SMEM);
    cudaFuncSetAttribute(attn_kernel,     cudaFuncAttributeMaxDynamicSharedMemorySize, ATTN_SMEM);

    split_all_kernel<<<SPL_NB0 + SPL_NB1 + SPL_NB2, 256>>>(Wqkv, hidden, Wd);
    qkv_fat_kernel<<<dim3(NH_ + 2*NH_, S_/128), 256, GEMM_SMEM>>>(hidden, Wqkv, bqkv);
    norm_rope_kernel<<<dim3(S_, NH_), 128>>>(pos);
    knn_pool_kernel<<<dim3(S_/64, NH_), 256, KNP_SMEM>>>(mem_keys);
    rescore_kernel<<<dim3(S_/4, NH_), 128>>>(mem_keys);
    attn_kernel<<<dim3(S_/64, NH_), 256, ATTN_SMEM>>>(am, scale_param, mem_values);
    out_mma_kernel<<<dim3(H_/128, S_/128), 256, GEMM_SMEM>>>(bd, out);
}

// round 14
// speedup vs baseline: 1.5997x; 1.0081x over previous
#include <cuda_runtime.h>
#include <math.h>
#include <stdint.h>

#define S_    1024
#define H_    2048
#define NH_   16
#define DH_   128
#define NN_   32
#define NP_   64
#define MK_   8192
#define HQKV_ 6144
#define KB_   6144

__device__ __align__(16) float g_qkv[S_ * HQKV_];
__device__ __align__(16) float g_q  [NH_ * S_ * DH_];
__device__ __align__(16) float g_k  [NH_ * S_ * DH_];
__device__ __align__(16) float g_v  [NH_ * S_ * DH_];
__device__ __align__(16) float g_topv[NH_ * S_ * NN_];
__device__ __align__(16) int   g_topi[NH_ * S_ * NN_];
__device__ __align__(16) int   g_pooli[NH_ * S_ * NP_];

__device__ __align__(16) float g_ctx_s [S_ * KB_];
__device__ __align__(16) float g_wd_s  [(size_t)H_ * KB_];
__device__ __align__(16) float g_hid_s [S_ * KB_];
__device__ __align__(16) float g_wqkv_s[(size_t)HQKV_ * KB_];

static __device__ __forceinline__ uint32_t smem_u32(const void* p){
    uint32_t a;
    asm("{ .reg .u64 t; cvta.to.shared.u64 t, %1; cvt.u32.u64 %0, t; }" : "=r"(a) : "l"(p));
    return a;
}
__device__ __forceinline__ int SWZ(int x){ return x ^ (((x) >> 3) & 0x70); }
__device__ __forceinline__ float to_tf32(float x){
    float r; asm("cvt.rna.tf32.f32 %0, %1;" : "=f"(r) : "f"(x)); return r;
}
__device__ __forceinline__ void ldsm4(uint32_t* r, uint32_t a){
    asm volatile("ldmatrix.sync.aligned.m8n8.x4.shared.b16 {%0,%1,%2,%3}, [%4];"
        : "=r"(r[0]), "=r"(r[1]), "=r"(r[2]), "=r"(r[3]) : "r"(a));
}
__device__ __forceinline__ void mmat(float* c, const uint32_t* a, uint32_t b0, uint32_t b1){
    asm volatile(
        "mma.sync.aligned.m16n8k8.row.col.f32.tf32.tf32.f32 "
        "{%0,%1,%2,%3}, {%4,%5,%6,%7}, {%8,%9}, {%0,%1,%2,%3};"
        : "+f"(c[0]), "+f"(c[1]), "+f"(c[2]), "+f"(c[3])
        : "r"(a[0]), "r"(a[1]), "r"(a[2]), "r"(a[3]), "r"(b0), "r"(b1));
}

template<int MT>
__device__ __forceinline__ void mma_chunk(uint32_t sA, uint32_t sB,
                                          int lane, int wm, int wn, float* acc){
    const int rl = lane & 15, uh = lane >> 4;
#pragma unroll
    for (int ks = 0; ks < 4; ks++){
        uint32_t a[MT][4], b[2][4];
#pragma unroll
        for (int mt = 0; mt < MT; mt++)
            ldsm4(a[mt], sA + SWZ((wm*(MT*16) + mt*16 + rl)*128 + (ks*2+uh)*16));
#pragma unroll
        for (int bt = 0; bt < 2; bt++)
            ldsm4(b[bt], sB + SWZ((wn*32 + bt*16 + rl)*128 + (ks*2+uh)*16));
#pragma unroll
        for (int mt = 0; mt < MT; mt++)
#pragma unroll
            for (int nt = 0; nt < 4; nt++)
                mmat(acc + (mt*4+nt)*4, a[mt], b[nt>>1][nt&1], b[nt>>1][(nt&1)+2]);
    }
}

// ---- one combined split launch: Wqkv(B), hidden(A), Wd(B) ----
#define SPL_NB0 2048
#define SPL_NB1 512
#define SPL_NB2 1024
__global__ void split_all_kernel(const float* __restrict__ Wqkv,
                                 const float* __restrict__ hidden,
                                 const float* __restrict__ Wd)
{
    int b = blockIdx.x;
    const float* s; float* d; int total, atype = 0, bstart, nb;
    if (b < SPL_NB0){ s = Wqkv;   d = g_wqkv_s; total = HQKV_ * H_; bstart = 0; nb = SPL_NB0; }
    else if (b < SPL_NB0 + SPL_NB1){
        s = hidden; d = g_hid_s; total = S_ * H_; atype = 1; bstart = SPL_NB0; nb = SPL_NB1; }
    else { s = Wd; d = g_wd_s; total = H_ * H_; bstart = SPL_NB0 + SPL_NB1; nb = SPL_NB2; }

    for (int i = (b - bstart) * 256 + threadIdx.x; i < total; i += nb * 256){
        float x  = s[i];
        float hi = to_tf32(x);
        float lo = to_tf32(x - hi);
        int r = i / H_, k = i - r * H_;
        size_t base = (size_t)r * 3 * H_ + k;
        d[base] = hi;
        d[base + H_]     = atype ? lo : hi;
        d[base + 2 * H_] = atype ? hi : lo;
    }
}

// ---- shared tf32 MMA 128x128 tile body ----
#define GEMM_SMEM 65536
__device__ __forceinline__ void gemm_mma_tile(const float* __restrict__ A,
                                              const float* __restrict__ B,
                                              const float* __restrict__ bias,
                                              float* __restrict__ C,
                                              int N, int K, int m0, int n0)
{
    extern __shared__ char smraw[];
    uint32_t sb = smem_u32(smraw);
    const int tid = threadIdx.x, lane = tid & 31, wid = tid >> 5;
    const int wm = wid >> 2, wn = wid & 3;
    const int nch = K >> 5;

    float acc[64];
#pragma unroll
    for (int i = 0; i < 64; i++) acc[i] = 0.f;

#pragma unroll
    for (int i = 0; i < 4; i++){
        int g = tid + i * 256, r = g >> 3, u = g & 7;
        uint4 va = ((const uint4*)(A + (size_t)(m0 + r) * K))[u];
        uint4 vb = ((const uint4*)(B + (size_t)(n0 + r) * K))[u];
        *(uint4*)(smraw + SWZ(r*128 + u*16)) = va;
        *(uint4*)(smraw + 32768 + SWZ(r*128 + u*16)) = vb;
    }
    __syncthreads();

    for (int c = 0; c < nch; c++){
        const int buf = c & 1;
        uint4 pa[4], pb[4];
        if (c + 1 < nch){
#pragma unroll
            for (int i = 0; i < 4; i++){
                int g = tid + i * 256, r = g >> 3, u = g & 7;
                pa[i] = ((const uint4*)(A + (size_t)(m0 + r) * K))[(c+1)*8 + u];
                pb[i] = ((const uint4*)(B + (size_t)(n0 + r) * K))[(c+1)*8 + u];
            }
        }
        mma_chunk<4>(sb + buf*16384, sb + 32768 + buf*16384, lane, wm, wn, acc);
        if (c + 1 < nch){
            int nb = buf ^ 1;
#pragma unroll
            for (int i = 0; i < 4; i++){
                int g = tid + i * 256, r = g >> 3, u = g & 7;
                *(uint4*)(smraw + nb*16384 + SWZ(r*128 + u*16)) = pa[i];
                *(uint4*)(smraw + 32768 + nb*16384 + SWZ(r*128 + u*16)) = pb[i];
            }
        }
        __syncthreads();
    }

    const int gr = lane >> 2, gc2 = (lane & 3) * 2;
#pragma unroll
    for (int mt = 0; mt < 4; mt++)
#pragma unroll
        for (int nt = 0; nt < 4; nt++){
            const float* cp = acc + (mt*4+nt)*4;
            int r = m0 + wm*64 + mt*16 + gr;
            int col = n0 + wn*32 + nt*8 + gc2;
            float b0 = bias[col], b1 = bias[col+1];
            *(float2*)(C + (size_t)r * N + col)     = make_float2(cp[0]+b0, cp[1]+b1);
            *(float2*)(C + (size_t)(r+8) * N + col) = make_float2(cp[2]+b0, cp[3]+b1);
        }
}

__global__ void __launch_bounds__(256) out_mma_kernel(const float* __restrict__ bias,
                                                      float* __restrict__ C)
{
    gemm_mma_tile(g_ctx_s, g_wd_s, bias, C, H_, KB_,
                  blockIdx.y * 128, blockIdx.x * 128);
}

__global__ void __launch_bounds__(256) qkv_kv_mma_kernel(const float* __restrict__ bias)
{
    const int t = blockIdx.x >> 1, which = 1 + (blockIdx.x & 1);
    gemm_mma_tile(g_hid_s, g_wqkv_s, bias, g_qkv, HQKV_, KB_,
                  blockIdx.y * 128, t * 384 + which * 128);
}

// ---- exact SIMT fp32 q GEMM: 64x128 tiles, 128 threads, grid (16,16) ----
// Per-element FMA order identical to the r2/r10 kernel -> bitwise-same q.
__global__ void __launch_bounds__(128) qkv_q_kernel(const float* __restrict__ A,
                                                    const float* __restrict__ B,
                                                    const float* __restrict__ bias)
{
    const int N = HQKV_, K = H_;
    __shared__ float As[8 * 64];
    __shared__ float Bs[8 * 128];
    const int tid  = threadIdx.x;
    const int m0   = blockIdx.y * 64;
    const int n0   = blockIdx.x * 384;       // q columns of head blockIdx.x
    const int ty   = tid >> 4, tx = tid & 15;
    const int lrow = tid >> 1, lk4 = (tid & 1) * 4;

    float c[8][8];
#pragma unroll
    for (int i = 0; i < 8; i++)
#pragma unroll
        for (int j = 0; j < 8; j++) c[i][j] = 0.f;

    const float* Ab  = A + (size_t)(m0 + lrow) * K + lk4;
    const float* Bb0 = B + (size_t)(n0 + lrow) * K + lk4;
    const float* Bb1 = B + (size_t)(n0 + 64 + lrow) * K + lk4;

    for (int k0 = 0; k0 < K; k0 += 8) {
        float4 av  = *(const float4*)(Ab  + k0);
        float4 bv0 = *(const float4*)(Bb0 + k0);
        float4 bv1 = *(const float4*)(Bb1 + k0);
        As[(lk4+0)*64+lrow] = av.x; As[(lk4+1)*64+lrow] = av.y;
        As[(lk4+2)*64+lrow] = av.z; As[(lk4+3)*64+lrow] = av.w;
        Bs[(lk4+0)*128+lrow] = bv0.x; Bs[(lk4+1)*128+lrow] = bv0.y;
        Bs[(lk4+2)*128+lrow] = bv0.z; Bs[(lk4+3)*128+lrow] = bv0.w;
        Bs[(lk4+0)*128+64+lrow] = bv1.x; Bs[(lk4+1)*128+64+lrow] = bv1.y;
        Bs[(lk4+2)*128+64+lrow] = bv1.z; Bs[(lk4+3)*128+64+lrow] = bv1.w;
        __syncthreads();
#pragma unroll
        for (int kk = 0; kk < 8; kk++) {
            float a[8], b[8];
            *(float4*)&a[0] = *(const float4*)&As[kk*64 + ty*8];
            *(float4*)&a[4] = *(const float4*)&As[kk*64 + ty*8 + 4];
            *(float4*)&b[0] = *(const float4*)&Bs[kk*128 + tx*8];
            *(float4*)&b[4] = *(const float4*)&Bs[kk*128 + tx*8 + 4];
#pragma unroll
            for (int i = 0; i < 8; i++)
#pragma unroll
                for (int j = 0; j < 8; j++) c[i][j] += a[i] * b[j];
        }
        __syncthreads();
    }
#pragma unroll
    for (int i = 0; i < 8; i++) {
        int row = m0 + ty * 8 + i;
#pragma unroll
        for (int j = 0; j < 8; j++) {
            int col = n0 + tx * 8 + j;
            g_qkv[(size_t)row * N + col] = c[i][j] + bias[col];
        }
    }
}

// ---- norm + rope ----
__global__ void norm_rope_kernel(const int* __restrict__ pos)
{
    const int s = blockIdx.x, h = blockIdx.y, d = threadIdx.x;
    const float* base = g_qkv + (size_t)s * HQKV_ + h * (3 * DH_);
    float qv = base[d], kv = base[DH_ + d], vv = base[2 * DH_ + d];

    float sq = qv * qv, sk = kv * kv;
#pragma unroll
    for (int o = 16; o > 0; o >>= 1) {
        sq += __shfl_xor_sync(0xffffffffu, sq, o);
        sk += __shfl_xor_sync(0xffffffffu, sk, o);
    }
    __shared__ float rq[4], rk[4];
    if ((d & 31) == 0) { rq[d >> 5] = sq; rk[d >> 5] = sk; }
    __syncthreads();
    float nq = sqrtf(rq[0] + rq[1] + rq[2] + rq[3]);
    float nk = sqrtf(rk[0] + rk[1] + rk[2] + rk[3]);
    float qn = qv / fmaxf(nq, 1e-12f);
    float kn = kv / fmaxf(nk, 1e-12f);

    __shared__ float qs[DH_], ks[DH_];
    qs[d] = qn; ks[d] = kn;
    __syncthreads();

    float qo = qn, ko = kn;
    if (d < 32) {
        int i = (d < 16) ? d : d - 16;
        float freq = powf(10000.0f, -(float)i / 16.0f);
        float ang  = (float)pos[s] * freq;
        float cs = cosf(ang), sn = sinf(ang);
        float rqh = (d < 16) ? -qs[d + 16] : qs[d - 16];
        float rkh = (d < 16) ? -ks[d + 16] : ks[d - 16];
        qo = qn * cs + rqh * sn;
        ko = kn * cs + rkh * sn;
    }
    size_t o = ((size_t)h * S_ + s) * DH_ + d;
    g_q[o] = qo; g_k[o] = ko; g_v[o] = vv;
}

// ---- kNN pool (unchanged) ----
#define KNA   0
#define KNB   32768
#define KNSC  65536
#define KNTI  98816
#define KNP_SMEM 107008
__global__ void __launch_bounds__(256, 2) knn_pool_kernel(const float* __restrict__ mem_keys)
{
    extern __shared__ char smraw[];
    uint32_t sb = smem_u32(smraw);
    const int tid = threadIdx.x, lane = tid & 31, wid = tid >> 5;
    const int wm = wid >> 2, wn = wid & 3;
    const int h = blockIdx.y, q0 = blockIdx.x * 64;
    float* Sc = (float*)(smraw + KNSC);
    unsigned short* Ti = (unsigned short*)(smraw + KNTI);

    const int half = lane >> 4, hl = lane & 15;
    const unsigned hmask = half ? 0xffff0000u : 0x0000ffffu;
    const int qbase = wid * 8;

    {
        int r = tid >> 2, part = tid & 3;
        const uint4* Ar = (const uint4*)(g_q + ((size_t)h * S_ + q0 + r) * DH_);
#pragma unroll
        for (int j = 0; j < 8; j++)
            *(uint4*)(smraw + KNA + part*8192 + SWZ(r*128 + j*16)) = Ar[part*8 + j];
    }
#pragma unroll
    for (int i = 0; i < 4; i++){
        int g = tid + i * 256, r = g >> 3, u = g & 7;
        uint4 v = ((const uint4*)(mem_keys + ((size_t)h * MK_ + r) * DH_))[u];
        *(uint4*)(smraw + KNB + SWZ(r*128 + u*16)) = v;
    }
    __syncthreads();

    float pv[4][4];
    float mv[4];
#pragma unroll
    for (int p = 0; p < 4; p++){
        mv[p] = -3.0e38f;
#pragma unroll
        for (int j = 0; j < 4; j++) pv[p][j] = -3.0e38f;
    }

    float acc[32];
#pragma unroll
    for (int i = 0; i < 32; i++) acc[i] = 0.f;

    for (int g = 0; g < 64 * 4; g++){
        const int t = g >> 2, ci = g & 3;
        const int buf = g & 1;
        uint4 pb[4];
        if (g + 1 < 64 * 4){
            int tn = (g + 1) >> 2, cn = (g + 1) & 3;
#pragma unroll
            for (int i = 0; i < 4; i++){
                int gi = tid + i * 256, r = gi >> 3, u = gi & 7;
                pb[i] = ((const uint4*)(mem_keys +
                         ((size_t)h * MK_ + tn * 128 + r) * DH_))[cn*8 + u];
            }
        }
        mma_chunk<2>(sb + KNA + ci*8192, sb + KNB + buf*16384, lane, wm, wn, acc);
        if (g + 1 < 64 * 4){
            int nb = buf ^ 1;
#pragma unroll
            for (int i = 0; i < 4; i++){
                int gi = tid + i * 256, r = gi >> 3, u = gi & 7;
                *(uint4*)(smraw + KNB + nb*16384 + SWZ(r*128 + u*16)) = pb[i];
            }
        }
        __syncthreads();

        if (ci == 3){
            const int gr = lane >> 2, gc2 = (lane & 3) * 2;
#pragma unroll
            for (int mt = 0; mt < 2; mt++)
#pragma unroll
                for (int nt = 0; nt < 4; nt++){
                    float* cp = acc + (mt*4+nt)*4;
                    int r = wm*32 + mt*16 + gr, col = wn*32 + nt*8 + gc2;
                    *(float2*)(Sc + r*130 + col)     = make_float2(cp[0], cp[1]);
                    *(float2*)(Sc + (r+8)*130 + col) = make_float2(cp[2], cp[3]);
                }
#pragma unroll
            for (int i = 0; i < 32; i++) acc[i] = 0.f;
            __syncthreads();

            for (int p = 0; p < 4; p++){
                const int q = qbase + p*2 + half;
                const float* srow = Sc + q*130;
                float m_ = mv[p];
                int seg0 = 0;
                if (t == 0){
#pragma unroll
                    for (int j = 0; j < 4; j++){
                        pv[p][j] = srow[hl*4 + j];
                        Ti[q*64 + hl*4 + j] = (unsigned short)(hl*4 + j);
                    }
                    float pm = pv[p][0];
#pragma unroll
                    for (int j = 1; j < 4; j++) pm = fminf(pm, pv[p][j]);
#pragma unroll
                    for (int o = 8; o > 0; o >>= 1)
                        pm = fminf(pm, __shfl_xor_sync(hmask, pm, o));
                    m_ = pm;
                    seg0 = 4;
                }
                for (int seg = seg0; seg < 8; seg++){
                    float s = srow[seg*16 + hl];
                    unsigned bal = __ballot_sync(0xffffffffu, s > m_);
                    unsigned m = (bal >> (half*16)) & 0xffffu;
                    while (m){
                        int b = __ffs(m) - 1; m &= m - 1;
                        float sv = __shfl_sync(hmask, s, half*16 + b);
                        float pm = pv[p][0]; int pc = 0;
#pragma unroll
                        for (int j = 1; j < 4; j++)
                            if (pv[p][j] < pm){ pm = pv[p][j]; pc = j; }
                        int code = hl*4 + pc;
#pragma unroll
                        for (int o = 8; o > 0; o >>= 1){
                            float ov = __shfl_xor_sync(hmask, pm, o);
                            int   oc = __shfl_xor_sync(hmask, code, o);
                            if (ov < pm || (ov == pm && oc < code)){ pm = ov; code = oc; }
                        }
                        if (sv > pm && hl == (code >> 2)){
                            pv[p][code & 3] = sv;
                            Ti[q*64 + code] = (unsigned short)(t*128 + seg*16 + b);
                        }
                        m_ = pm;
                    }
                }
                mv[p] = m_;
            }
            __syncthreads();
        }
    }
    for (int i = tid; i < 64 * NP_; i += 256)
        g_pooli[((size_t)h * S_ + q0 + (i >> 6)) * NP_ + (i & 63)] = (int)Ti[i];
}

// ---- exact fp32 rescore (unchanged) ----
__global__ void rescore_kernel(const float* __restrict__ mem_keys)
{
    __shared__ float ssc[4][NP_];
    __shared__ int   sid[4][NP_];
    const int lane = threadIdx.x & 31, w = threadIdx.x >> 5;
    const int h = blockIdx.y;
    const int q = blockIdx.x * 4 + w;
    const size_t qi = (size_t)h * S_ + q;

    float4 qv = ((const float4*)(g_q + qi * DH_))[lane];
    for (int c = lane; c < NP_; c += 32) sid[w][c] = g_pooli[qi * NP_ + c];
    __syncwarp();

    for (int c = 0; c < NP_; c++){
        float4 kv = ((const float4*)(mem_keys + ((size_t)h * MK_ + sid[w][c]) * DH_))[lane];
        float d = qv.x*kv.x + qv.y*kv.y + qv.z*kv.z + qv.w*kv.w;
#pragma unroll
        for (int o = 16; o > 0; o >>= 1) d += __shfl_xor_sync(0xffffffffu, d, o);
        if (lane == 0) ssc[w][c] = d;
    }
    __syncwarp();

    float v1 = ssc[w][lane];
    float v2 = ssc[w][32 + lane];
    for (int it = 0; it < NN_; it++){
        float mvv; int mi;
        if (v1 >= v2){ mvv = v1; mi = lane; } else { mvv = v2; mi = 32 + lane; }
#pragma unroll
        for (int o = 16; o > 0; o >>= 1){
            float ov = __shfl_xor_sync(0xffffffffu, mvv, o);
            int   oi = __shfl_xor_sync(0xffffffffu, mi, o);
            if (ov > mvv || (ov == mvv && oi < mi)){ mvv = ov; mi = oi; }
        }
        if (mi < 32){ if (lane == mi) v1 = -3.0e38f; }
        else        { if (lane == mi - 32) v2 = -3.0e38f; }
        if (lane == 0){
            g_topv[qi * NN_ + it] = mvv;
            g_topi[qi * NN_ + it] = sid[w][mi];
        }
    }
}

// ---- flash attention: QK^T via tf32 MMA, PV exact SIMT; writes ctx_s ----
#define AT_Q   0
#define AT_K   32768
#define AT_SC  65536
#define AT_MS  98816
#define AT_TI  99584
#define ATTN_SMEM 107776
__global__ void __launch_bounds__(256, 2) attn_kernel(const float* __restrict__ am,
                            const float* __restrict__ scale_param,
                            const float* __restrict__ mem_values)
{
    extern __shared__ char smraw[];
    uint32_t sb = smem_u32(smraw);
    float* Sc  = (float*)(smraw + AT_SC);
    float* msh = (float*)(smraw + AT_MS);
    float* lsh = msh + 64;
    float* csh = lsh + 64;
    int*   Ti  = (int*)(smraw + AT_TI);
    float* Vs  = (float*)(smraw + AT_K);

    const int tid = threadIdx.x, lane = tid & 31, wid = tid >> 5;
    const int wm = wid >> 2, wn = wid & 3;
    const int h = blockIdx.y;
    const int q0 = (gridDim.x - 1 - blockIdx.x) * 64;
    const int ty = tid >> 4, tx = tid & 15;
    const int srow = tid >> 2, sl4 = tid & 3;
    const float scale = expf(scale_param[h]);

    {
        int r = tid >> 2, part = tid & 3;
        const uint4* Ar = (const uint4*)(g_q + ((size_t)h * S_ + q0 + r) * DH_);
#pragma unroll
        for (int j = 0; j < 8; j++)
            *(uint4*)(smraw + AT_Q + part*8192 + SWZ(r*128 + j*16)) = Ar[part*8 + j];
    }
    for (int idx = tid; idx < 64 * 32; idx += 256) {
        int q = idx >> 5, n = idx & 31;
        Sc[q*130+n] = g_topv[((size_t)h * S_ + q0 + q) * NN_ + n] * scale;
        Ti[q*32+n]  = g_topi[((size_t)h * S_ + q0 + q) * NN_ + n];
    }
    __syncthreads();

    {
        float mm = -3.0e38f;
#pragma unroll
        for (int j = 0; j < 8; j++) mm = fmaxf(mm, Sc[srow*130 + sl4*8 + j]);
        mm = fmaxf(mm, __shfl_xor_sync(0xffffffffu, mm, 1));
        mm = fmaxf(mm, __shfl_xor_sync(0xffffffffu, mm, 2));
        float ll = 0.f;
#pragma unroll
        for (int j = 0; j < 8; j++){
            float p = expf(Sc[srow*130 + sl4*8 + j] - mm);
            Sc[srow*130 + sl4*8 + j] = p; ll += p;
        }
        ll += __shfl_xor_sync(0xffffffffu, ll, 1);
        ll += __shfl_xor_sync(0xffffffffu, ll, 2);
        if (sl4 == 0){ msh[srow] = mm; lsh[srow] = ll; }
    }
    __syncthreads();

    float oacc[4][8];
#pragma unroll
    for (int i = 0; i < 4; i++)
#pragma unroll
        for (int j = 0; j < 8; j++) oacc[i][j] = 0.f;

#pragma unroll
    for (int i = 0; i < 4; i++) {
        int qr = ty * 4 + i;
        for (int n = 0; n < NN_; n++) {
            float w = Sc[qr*130+n];
            const float4* vr = (const float4*)(mem_values +
                ((size_t)h * MK_ + Ti[qr*32+n]) * DH_ + tx * 8);
            float4 v0 = vr[0], v1 = vr[1];
            oacc[i][0]+=w*v0.x; oacc[i][1]+=w*v0.y; oacc[i][2]+=w*v0.z; oacc[i][3]+=w*v0.w;
            oacc[i][4]+=w*v1.x; oacc[i][5]+=w*v1.y; oacc[i][6]+=w*v1.z; oacc[i][7]+=w*v1.w;
        }
    }

    float acc[32];
#pragma unroll
    for (int i = 0; i < 32; i++) acc[i] = 0.f;

    const int ntiles = (q0 >> 7) + 1;
    for (int t = 0; t < ntiles; t++){
#pragma unroll
        for (int i = 0; i < 4; i++){
            int g = tid + i * 256, r = g >> 3, u = g & 7;
            uint4 v = ((const uint4*)(g_k + ((size_t)h * S_ + t*128 + r) * DH_))[u];
            *(uint4*)(smraw + AT_K + SWZ(r*128 + u*16)) = v;
        }
        __syncthreads();
        for (int ci = 0; ci < 4; ci++){
            uint4 pb[4];
            if (ci < 3){
#pragma unroll
                for (int i = 0; i < 4; i++){
                    int g = tid + i * 256, r = g >> 3, u = g & 7;
                    pb[i] = ((const uint4*)(g_k + ((size_t)h * S_ + t*128 + r) * DH_))[(ci+1)*8 + u];
                }
            }
            mma_chunk<2>(sb + AT_Q + ci*8192, sb + AT_K + (ci&1)*16384, lane, wm, wn, acc);
            if (ci < 3){
                int nb = (ci+1) & 1;
#pragma unroll
                for (int i = 0; i < 4; i++){
                    int g = tid + i * 256, r = g >> 3, u = g & 7;
                    *(uint4*)(smraw + AT_K + nb*16384 + SWZ(r*128 + u*16)) = pb[i];
                }
            }
            __syncthreads();
        }
        {
            const int gr = lane >> 2, gc2 = (lane & 3) * 2;
#pragma unroll
            for (int mt = 0; mt < 2; mt++)
#pragma unroll
                for (int nt = 0; nt < 4; nt++){
                    float* cp = acc + (mt*4+nt)*4;
                    int r = wm*32 + mt*16 + gr, col = wn*32 + nt*8 + gc2;
                    *(float2*)(Sc + r*130 + col)     = make_float2(cp[0], cp[1]);
                    *(float2*)(Sc + (r+8)*130 + col) = make_float2(cp[2], cp[3]);
                }
#pragma unroll
            for (int i = 0; i < 32; i++) acc[i] = 0.f;
        }
        __syncthreads();

        {
            const int qg = q0 + srow;
            float mm = msh[srow], rmax = mm;
#pragma unroll
            for (int j = 0; j < 32; j++){
                int kg = t*128 + sl4*32 + j;
                float s = Sc[srow*130 + sl4*32 + j];
                float v = (kg <= qg) ? (s * scale + am[kg]) : -1.0e30f;
                rmax = fmaxf(rmax, v);
            }
            rmax = fmaxf(rmax, __shfl_xor_sync(0xffffffffu, rmax, 1));
            rmax = fmaxf(rmax, __shfl_xor_sync(0xffffffffu, rmax, 2));
            float cor = expf(mm - rmax);
            float ll = (sl4 == 0) ? lsh[srow] * cor : 0.f;
#pragma unroll
            for (int j = 0; j < 32; j++){
                int kg = t*128 + sl4*32 + j;
                float s = Sc[srow*130 + sl4*32 + j];
                float v = (kg <= qg) ? (s * scale + am[kg]) : -1.0e30f;
                float p = expf(v - rmax);
                Sc[srow*130 + sl4*32 + j] = p;
                ll += p;
            }
            ll += __shfl_xor_sync(0xffffffffu, ll, 1);
            ll += __shfl_xor_sync(0xffffffffu, ll, 2);
            if (sl4 == 0){ msh[srow] = rmax; lsh[srow] = ll; csh[srow] = cor; }
        }
        __syncthreads();

        for (int ph = 0; ph < 2; ph++){
            for (int idx = tid; idx < 64 * 32; idx += 256){
                int row = idx >> 5, seg = idx & 31;
                *(float4*)&Vs[row*128 + seg*4] =
                    *(const float4*)(g_v + ((size_t)h * S_ + t*128 + ph*64 + row) * DH_ + seg*4);
            }
            __syncthreads();
#pragma unroll
            for (int i = 0; i < 4; i++){
                int qr = ty*4 + i;
                if (ph == 0){
                    float cor = csh[qr];
#pragma unroll
                    for (int j = 0; j < 8; j++) oacc[i][j] *= cor;
                }
                for (int n = 0; n < 64; n++){
                    float w = Sc[qr*130 + ph*64 + n];
                    float4 v0 = *(const float4*)&Vs[n*128 + tx*8];
                    float4 v1 = *(const float4*)&Vs[n*128 + tx*8 + 4];
                    oacc[i][0]+=w*v0.x; oacc[i][1]+=w*v0.y; oacc[i][2]+=w*v0.z; oacc[i][3]+=w*v0.w;
                    oacc[i][4]+=w*v1.x; oacc[i][5]+=w*v1.y; oacc[i][6]+=w*v1.z; oacc[i][7]+=w*v1.w;
                }
            }
            __syncthreads();
        }
    }

    // epilogue: normalize + write hi/lo/hi directly into ctx_s (A-type)
#pragma unroll
    for (int i = 0; i < 4; i++) {
        int qr = ty*4 + i;
        float inv = 1.0f / lsh[qr];
#pragma unroll
        for (int j = 0; j < 8; j++){
            float x  = oacc[i][j] * inv;
            float hi = to_tf32(x);
            float lo = to_tf32(x - hi);
            size_t base = (size_t)(q0+qr) * KB_ + h*DH_ + tx*8 + j;
            g_ctx_s[base]          = hi;
            g_ctx_s[base + H_]     = lo;
            g_ctx_s[base + 2*H_]   = hi;
        }
    }
}

extern "C" void kernel_launch(void* const* d_in, const int* in_sizes, int n_in,
                              void* d_out, int out_size)
{
    const float* hidden      = (const float*)d_in[0];
    const float* am          = (const float*)d_in[1];
    const int*   pos         = (const int*)d_in[2];
    const float* Wqkv        = (const float*)d_in[3];
    const float* bqkv        = (const float*)d_in[4];
    const float* Wd          = (const float*)d_in[5];
    const float* bd          = (const float*)d_in[6];
    const float* scale_param = (const float*)d_in[7];
    const float* mem_keys    = (const float*)d_in[8];
    const float* mem_values  = (const float*)d_in[9];
    float*       out         = (float*)d_out;

    cudaFuncSetAttribute(out_mma_kernel,    cudaFuncAttributeMaxDynamicSharedMemorySize, GEMM_SMEM);
    cudaFuncSetAttribute(qkv_kv_mma_kernel, cudaFuncAttributeMaxDynamicSharedMemorySize, GEMM_SMEM);
    cudaFuncSetAttribute(knn_pool_kernel,   cudaFuncAttributeMaxDynamicSharedMemorySize, KNP_SMEM);
    cudaFuncSetAttribute(attn_kernel,       cudaFuncAttributeMaxDynamicSharedMemorySize, ATTN_SMEM);

    split_all_kernel<<<SPL_NB0 + SPL_NB1 + SPL_NB2, 256>>>(Wqkv, hidden, Wd);
    qkv_q_kernel<<<dim3(NH_, S_/64), 128>>>(hidden, Wqkv, bqkv);
    qkv_kv_mma_kernel<<<dim3(2*NH_, S_/128), 256, GEMM_SMEM>>>(bqkv);
    norm_rope_kernel<<<dim3(S_, NH_), 128>>>(pos);
    knn_pool_kernel<<<dim3(S_/64, NH_), 256, KNP_SMEM>>>(mem_keys);
    rescore_kernel<<<dim3(S_/4, NH_), 128>>>(mem_keys);
    attn_kernel<<<dim3(S_/64, NH_), 256, ATTN_SMEM>>>(am, scale_param, mem_values);
    out_mma_kernel<<<dim3(H_/128, S_/128), 256, GEMM_SMEM>>>(bd, out);
}

// round 15
// speedup vs baseline: 1.8424x; 1.1517x over previous
#include <cuda_runtime.h>
#include <math.h>
#include <stdint.h>

#define S_    1024
#define H_    2048
#define NH_   16
#define DH_   128
#define NN_   32
#define NP_   64
#define MK_   8192
#define HQKV_ 6144
#define KB_   6144

__device__ __align__(16) float g_qkv[S_ * HQKV_];
__device__ __align__(16) float g_q  [NH_ * S_ * DH_];
__device__ __align__(16) float g_k  [NH_ * S_ * DH_];
__device__ __align__(16) float g_v  [NH_ * S_ * DH_];
__device__ __align__(16) float g_topv[NH_ * S_ * NN_];
__device__ __align__(16) int   g_topi[NH_ * S_ * NN_];
__device__ __align__(16) int   g_pooli[NH_ * S_ * NP_];

__device__ __align__(16) float g_ctx_s [S_ * KB_];
__device__ __align__(16) float g_wd_s  [(size_t)H_ * KB_];
__device__ __align__(16) float g_hid_s [S_ * KB_];
__device__ __align__(16) float g_wqkv_s[(size_t)HQKV_ * KB_];

static __device__ __forceinline__ uint32_t smem_u32(const void* p){
    uint32_t a;
    asm("{ .reg .u64 t; cvta.to.shared.u64 t, %1; cvt.u32.u64 %0, t; }" : "=r"(a) : "l"(p));
    return a;
}
__device__ __forceinline__ int SWZ(int x){ return x ^ (((x) >> 3) & 0x70); }
__device__ __forceinline__ float to_tf32(float x){
    float r; asm("cvt.rna.tf32.f32 %0, %1;" : "=f"(r) : "f"(x)); return r;
}
__device__ __forceinline__ void ldsm4(uint32_t* r, uint32_t a){
    asm volatile("ldmatrix.sync.aligned.m8n8.x4.shared.b16 {%0,%1,%2,%3}, [%4];"
        : "=r"(r[0]), "=r"(r[1]), "=r"(r[2]), "=r"(r[3]) : "r"(a));
}
__device__ __forceinline__ void mmat(float* c, const uint32_t* a, uint32_t b0, uint32_t b1){
    asm volatile(
        "mma.sync.aligned.m16n8k8.row.col.f32.tf32.tf32.f32 "
        "{%0,%1,%2,%3}, {%4,%5,%6,%7}, {%8,%9}, {%0,%1,%2,%3};"
        : "+f"(c[0]), "+f"(c[1]), "+f"(c[2]), "+f"(c[3])
        : "r"(a[0]), "r"(a[1]), "r"(a[2]), "r"(a[3]), "r"(b0), "r"(b1));
}

template<int MT>
__device__ __forceinline__ void mma_chunk(uint32_t sA, uint32_t sB,
                                          int lane, int wm, int wn, float* acc){
    const int rl = lane & 15, uh = lane >> 4;
#pragma unroll
    for (int ks = 0; ks < 4; ks++){
        uint32_t a[MT][4], b[2][4];
#pragma unroll
        for (int mt = 0; mt < MT; mt++)
            ldsm4(a[mt], sA + SWZ((wm*(MT*16) + mt*16 + rl)*128 + (ks*2+uh)*16));
#pragma unroll
        for (int bt = 0; bt < 2; bt++)
            ldsm4(b[bt], sB + SWZ((wn*32 + bt*16 + rl)*128 + (ks*2+uh)*16));
#pragma unroll
        for (int mt = 0; mt < MT; mt++)
#pragma unroll
            for (int nt = 0; nt < 4; nt++)
                mmat(acc + (mt*4+nt)*4, a[mt], b[nt>>1][nt&1], b[nt>>1][(nt&1)+2]);
    }
}

// ---- one combined split launch: Wqkv(B), hidden(A), Wd(B) ----
#define SPL_NB0 2048
#define SPL_NB1 512
#define SPL_NB2 1024
__global__ void split_all_kernel(const float* __restrict__ Wqkv,
                                 const float* __restrict__ hidden,
                                 const float* __restrict__ Wd)
{
    int b = blockIdx.x;
    const float* s; float* d; int total, atype = 0, bstart, nb;
    if (b < SPL_NB0){ s = Wqkv;   d = g_wqkv_s; total = HQKV_ * H_; bstart = 0; nb = SPL_NB0; }
    else if (b < SPL_NB0 + SPL_NB1){
        s = hidden; d = g_hid_s; total = S_ * H_; atype = 1; bstart = SPL_NB0; nb = SPL_NB1; }
    else { s = Wd; d = g_wd_s; total = H_ * H_; bstart = SPL_NB0 + SPL_NB1; nb = SPL_NB2; }

    for (int i = (b - bstart) * 256 + threadIdx.x; i < total; i += nb * 256){
        float x  = s[i];
        float hi = to_tf32(x);
        float lo = to_tf32(x - hi);
        int r = i / H_, k = i - r * H_;
        size_t base = (size_t)r * 3 * H_ + k;
        d[base] = hi;
        d[base + H_]     = atype ? lo : hi;
        d[base + 2 * H_] = atype ? hi : lo;
    }
}

// ---- shared tf32 MMA 128x128 tile body ----
#define GEMM_SMEM 65536
__device__ __forceinline__ void gemm_mma_tile(const float* __restrict__ A,
                                              const float* __restrict__ B,
                                              const float* __restrict__ bias,
                                              float* __restrict__ C,
                                              int N, int K, int m0, int n0)
{
    extern __shared__ char smraw[];
    uint32_t sb = smem_u32(smraw);
    const int tid = threadIdx.x, lane = tid & 31, wid = tid >> 5;
    const int wm = wid >> 2, wn = wid & 3;
    const int nch = K >> 5;

    float acc[64];
#pragma unroll
    for (int i = 0; i < 64; i++) acc[i] = 0.f;

#pragma unroll
    for (int i = 0; i < 4; i++){
        int g = tid + i * 256, r = g >> 3, u = g & 7;
        uint4 va = ((const uint4*)(A + (size_t)(m0 + r) * K))[u];
        uint4 vb = ((const uint4*)(B + (size_t)(n0 + r) * K))[u];
        *(uint4*)(smraw + SWZ(r*128 + u*16)) = va;
        *(uint4*)(smraw + 32768 + SWZ(r*128 + u*16)) = vb;
    }
    __syncthreads();

    for (int c = 0; c < nch; c++){
        const int buf = c & 1;
        uint4 pa[4], pb[4];
        if (c + 1 < nch){
#pragma unroll
            for (int i = 0; i < 4; i++){
                int g = tid + i * 256, r = g >> 3, u = g & 7;
                pa[i] = ((const uint4*)(A + (size_t)(m0 + r) * K))[(c+1)*8 + u];
                pb[i] = ((const uint4*)(B + (size_t)(n0 + r) * K))[(c+1)*8 + u];
            }
        }
        mma_chunk<4>(sb + buf*16384, sb + 32768 + buf*16384, lane, wm, wn, acc);
        if (c + 1 < nch){
            int nb = buf ^ 1;
#pragma unroll
            for (int i = 0; i < 4; i++){
                int g = tid + i * 256, r = g >> 3, u = g & 7;
                *(uint4*)(smraw + nb*16384 + SWZ(r*128 + u*16)) = pa[i];
                *(uint4*)(smraw + 32768 + nb*16384 + SWZ(r*128 + u*16)) = pb[i];
            }
        }
        __syncthreads();
    }

    const int gr = lane >> 2, gc2 = (lane & 3) * 2;
#pragma unroll
    for (int mt = 0; mt < 4; mt++)
#pragma unroll
        for (int nt = 0; nt < 4; nt++){
            const float* cp = acc + (mt*4+nt)*4;
            int r = m0 + wm*64 + mt*16 + gr;
            int col = n0 + wn*32 + nt*8 + gc2;
            float b0 = bias[col], b1 = bias[col+1];
            *(float2*)(C + (size_t)r * N + col)     = make_float2(cp[0]+b0, cp[1]+b1);
            *(float2*)(C + (size_t)(r+8) * N + col) = make_float2(cp[2]+b0, cp[3]+b1);
        }
}

__global__ void __launch_bounds__(256, 2) out_mma_kernel(const float* __restrict__ bias,
                                                         float* __restrict__ C)
{
    gemm_mma_tile(g_ctx_s, g_wd_s, bias, C, H_, KB_,
                  blockIdx.y * 128, blockIdx.x * 128);
}

__global__ void __launch_bounds__(256, 2) qkv_kv_mma_kernel(const float* __restrict__ bias)
{
    const int t = blockIdx.x >> 1, which = 1 + (blockIdx.x & 1);
    gemm_mma_tile(g_hid_s, g_wqkv_s, bias, g_qkv, HQKV_, KB_,
                  blockIdx.y * 128, t * 384 + which * 128);
}

// ---- exact SIMT fp32 q GEMM: 64x128 tiles, 128 threads, grid (16,16) ----
__global__ void __launch_bounds__(128) qkv_q_kernel(const float* __restrict__ A,
                                                    const float* __restrict__ B,
                                                    const float* __restrict__ bias)
{
    const int N = HQKV_, K = H_;
    __shared__ float As[8 * 64];
    __shared__ float Bs[8 * 128];
    const int tid  = threadIdx.x;
    const int m0   = blockIdx.y * 64;
    const int n0   = blockIdx.x * 384;
    const int ty   = tid >> 4, tx = tid & 15;
    const int lrow = tid >> 1, lk4 = (tid & 1) * 4;

    float c[8][8];
#pragma unroll
    for (int i = 0; i < 8; i++)
#pragma unroll
        for (int j = 0; j < 8; j++) c[i][j] = 0.f;

    const float* Ab  = A + (size_t)(m0 + lrow) * K + lk4;
    const float* Bb0 = B + (size_t)(n0 + lrow) * K + lk4;
    const float* Bb1 = B + (size_t)(n0 + 64 + lrow) * K + lk4;

    for (int k0 = 0; k0 < K; k0 += 8) {
        float4 av  = *(const float4*)(Ab  + k0);
        float4 bv0 = *(const float4*)(Bb0 + k0);
        float4 bv1 = *(const float4*)(Bb1 + k0);
        As[(lk4+0)*64+lrow] = av.x; As[(lk4+1)*64+lrow] = av.y;
        As[(lk4+2)*64+lrow] = av.z; As[(lk4+3)*64+lrow] = av.w;
        Bs[(lk4+0)*128+lrow] = bv0.x; Bs[(lk4+1)*128+lrow] = bv0.y;
        Bs[(lk4+2)*128+lrow] = bv0.z; Bs[(lk4+3)*128+lrow] = bv0.w;
        Bs[(lk4+0)*128+64+lrow] = bv1.x; Bs[(lk4+1)*128+64+lrow] = bv1.y;
        Bs[(lk4+2)*128+64+lrow] = bv1.z; Bs[(lk4+3)*128+64+lrow] = bv1.w;
        __syncthreads();
#pragma unroll
        for (int kk = 0; kk < 8; kk++) {
            float a[8], b[8];
            *(float4*)&a[0] = *(const float4*)&As[kk*64 + ty*8];
            *(float4*)&a[4] = *(const float4*)&As[kk*64 + ty*8 + 4];
            *(float4*)&b[0] = *(const float4*)&Bs[kk*128 + tx*8];
            *(float4*)&b[4] = *(const float4*)&Bs[kk*128 + tx*8 + 4];
#pragma unroll
            for (int i = 0; i < 8; i++)
#pragma unroll
                for (int j = 0; j < 8; j++) c[i][j] += a[i] * b[j];
        }
        __syncthreads();
    }
#pragma unroll
    for (int i = 0; i < 8; i++) {
        int row = m0 + ty * 8 + i;
#pragma unroll
        for (int j = 0; j < 8; j++) {
            int col = n0 + tx * 8 + j;
            g_qkv[(size_t)row * N + col] = c[i][j] + bias[col];
        }
    }
}

// ---- norm + rope ----
__global__ void norm_rope_kernel(const int* __restrict__ pos)
{
    const int s = blockIdx.x, h = blockIdx.y, d = threadIdx.x;
    const float* base = g_qkv + (size_t)s * HQKV_ + h * (3 * DH_);
    float qv = base[d], kv = base[DH_ + d], vv = base[2 * DH_ + d];

    float sq = qv * qv, sk = kv * kv;
#pragma unroll
    for (int o = 16; o > 0; o >>= 1) {
        sq += __shfl_xor_sync(0xffffffffu, sq, o);
        sk += __shfl_xor_sync(0xffffffffu, sk, o);
    }
    __shared__ float rq[4], rk[4];
    if ((d & 31) == 0) { rq[d >> 5] = sq; rk[d >> 5] = sk; }
    __syncthreads();
    float nq = sqrtf(rq[0] + rq[1] + rq[2] + rq[3]);
    float nk = sqrtf(rk[0] + rk[1] + rk[2] + rk[3]);
    float qn = qv / fmaxf(nq, 1e-12f);
    float kn = kv / fmaxf(nk, 1e-12f);

    __shared__ float qs[DH_], ks[DH_];
    qs[d] = qn; ks[d] = kn;
    __syncthreads();

    float qo = qn, ko = kn;
    if (d < 32) {
        int i = (d < 16) ? d : d - 16;
        float freq = powf(10000.0f, -(float)i / 16.0f);
        float ang  = (float)pos[s] * freq;
        float cs = cosf(ang), sn = sinf(ang);
        float rqh = (d < 16) ? -qs[d + 16] : qs[d - 16];
        float rkh = (d < 16) ? -ks[d + 16] : ks[d - 16];
        qo = qn * cs + rqh * sn;
        ko = kn * cs + rkh * sn;
    }
    size_t o = ((size_t)h * S_ + s) * DH_ + d;
    g_q[o] = qo; g_k[o] = ko; g_v[o] = vv;
}

// ---- kNN pool (unchanged) ----
#define KNA   0
#define KNB   32768
#define KNSC  65536
#define KNTI  98816
#define KNP_SMEM 107008
__global__ void __launch_bounds__(256, 2) knn_pool_kernel(const float* __restrict__ mem_keys)
{
    extern __shared__ char smraw[];
    uint32_t sb = smem_u32(smraw);
    const int tid = threadIdx.x, lane = tid & 31, wid = tid >> 5;
    const int wm = wid >> 2, wn = wid & 3;
    const int h = blockIdx.y, q0 = blockIdx.x * 64;
    float* Sc = (float*)(smraw + KNSC);
    unsigned short* Ti = (unsigned short*)(smraw + KNTI);

    const int half = lane >> 4, hl = lane & 15;
    const unsigned hmask = half ? 0xffff0000u : 0x0000ffffu;
    const int qbase = wid * 8;

    {
        int r = tid >> 2, part = tid & 3;
        const uint4* Ar = (const uint4*)(g_q + ((size_t)h * S_ + q0 + r) * DH_);
#pragma unroll
        for (int j = 0; j < 8; j++)
            *(uint4*)(smraw + KNA + part*8192 + SWZ(r*128 + j*16)) = Ar[part*8 + j];
    }
#pragma unroll
    for (int i = 0; i < 4; i++){
        int g = tid + i * 256, r = g >> 3, u = g & 7;
        uint4 v = ((const uint4*)(mem_keys + ((size_t)h * MK_ + r) * DH_))[u];
        *(uint4*)(smraw + KNB + SWZ(r*128 + u*16)) = v;
    }
    __syncthreads();

    float pv[4][4];
    float mv[4];
#pragma unroll
    for (int p = 0; p < 4; p++){
        mv[p] = -3.0e38f;
#pragma unroll
        for (int j = 0; j < 4; j++) pv[p][j] = -3.0e38f;
    }

    float acc[32];
#pragma unroll
    for (int i = 0; i < 32; i++) acc[i] = 0.f;

    for (int g = 0; g < 64 * 4; g++){
        const int t = g >> 2, ci = g & 3;
        const int buf = g & 1;
        uint4 pb[4];
        if (g + 1 < 64 * 4){
            int tn = (g + 1) >> 2, cn = (g + 1) & 3;
#pragma unroll
            for (int i = 0; i < 4; i++){
                int gi = tid + i * 256, r = gi >> 3, u = gi & 7;
                pb[i] = ((const uint4*)(mem_keys +
                         ((size_t)h * MK_ + tn * 128 + r) * DH_))[cn*8 + u];
            }
        }
        mma_chunk<2>(sb + KNA + ci*8192, sb + KNB + buf*16384, lane, wm, wn, acc);
        if (g + 1 < 64 * 4){
            int nb = buf ^ 1;
#pragma unroll
            for (int i = 0; i < 4; i++){
                int gi = tid + i * 256, r = gi >> 3, u = gi & 7;
                *(uint4*)(smraw + KNB + nb*16384 + SWZ(r*128 + u*16)) = pb[i];
            }
        }
        __syncthreads();

        if (ci == 3){
            const int gr = lane >> 2, gc2 = (lane & 3) * 2;
#pragma unroll
            for (int mt = 0; mt < 2; mt++)
#pragma unroll
                for (int nt = 0; nt < 4; nt++){
                    float* cp = acc + (mt*4+nt)*4;
                    int r = wm*32 + mt*16 + gr, col = wn*32 + nt*8 + gc2;
                    *(float2*)(Sc + r*130 + col)     = make_float2(cp[0], cp[1]);
                    *(float2*)(Sc + (r+8)*130 + col) = make_float2(cp[2], cp[3]);
                }
#pragma unroll
            for (int i = 0; i < 32; i++) acc[i] = 0.f;
            __syncthreads();

            for (int p = 0; p < 4; p++){
                const int q = qbase + p*2 + half;
                const float* srow = Sc + q*130;
                float m_ = mv[p];
                int seg0 = 0;
                if (t == 0){
#pragma unroll
                    for (int j = 0; j < 4; j++){
                        pv[p][j] = srow[hl*4 + j];
                        Ti[q*64 + hl*4 + j] = (unsigned short)(hl*4 + j);
                    }
                    float pm = pv[p][0];
#pragma unroll
                    for (int j = 1; j < 4; j++) pm = fminf(pm, pv[p][j]);
#pragma unroll
                    for (int o = 8; o > 0; o >>= 1)
                        pm = fminf(pm, __shfl_xor_sync(hmask, pm, o));
                    m_ = pm;
                    seg0 = 4;
                }
                for (int seg = seg0; seg < 8; seg++){
                    float s = srow[seg*16 + hl];
                    unsigned bal = __ballot_sync(0xffffffffu, s > m_);
                    unsigned m = (bal >> (half*16)) & 0xffffu;
                    while (m){
                        int b = __ffs(m) - 1; m &= m - 1;
                        float sv = __shfl_sync(hmask, s, half*16 + b);
                        float pm = pv[p][0]; int pc = 0;
#pragma unroll
                        for (int j = 1; j < 4; j++)
                            if (pv[p][j] < pm){ pm = pv[p][j]; pc = j; }
                        int code = hl*4 + pc;
#pragma unroll
                        for (int o = 8; o > 0; o >>= 1){
                            float ov = __shfl_xor_sync(hmask, pm, o);
                            int   oc = __shfl_xor_sync(hmask, code, o);
                            if (ov < pm || (ov == pm && oc < code)){ pm = ov; code = oc; }
                        }
                        if (sv > pm && hl == (code >> 2)){
                            pv[p][code & 3] = sv;
                            Ti[q*64 + code] = (unsigned short)(t*128 + seg*16 + b);
                        }
                        m_ = pm;
                    }
                }
                mv[p] = m_;
            }
            __syncthreads();
        }
    }
    for (int i = tid; i < 64 * NP_; i += 256)
        g_pooli[((size_t)h * S_ + q0 + (i >> 6)) * NP_ + (i & 63)] = (int)Ti[i];
}

// ---- exact fp32 rescore (unchanged) ----
__global__ void rescore_kernel(const float* __restrict__ mem_keys)
{
    __shared__ float ssc[4][NP_];
    __shared__ int   sid[4][NP_];
    const int lane = threadIdx.x & 31, w = threadIdx.x >> 5;
    const int h = blockIdx.y;
    const int q = blockIdx.x * 4 + w;
    const size_t qi = (size_t)h * S_ + q;

    float4 qv = ((const float4*)(g_q + qi * DH_))[lane];
    for (int c = lane; c < NP_; c += 32) sid[w][c] = g_pooli[qi * NP_ + c];
    __syncwarp();

    for (int c = 0; c < NP_; c++){
        float4 kv = ((const float4*)(mem_keys + ((size_t)h * MK_ + sid[w][c]) * DH_))[lane];
        float d = qv.x*kv.x + qv.y*kv.y + qv.z*kv.z + qv.w*kv.w;
#pragma unroll
        for (int o = 16; o > 0; o >>= 1) d += __shfl_xor_sync(0xffffffffu, d, o);
        if (lane == 0) ssc[w][c] = d;
    }
    __syncwarp();

    float v1 = ssc[w][lane];
    float v2 = ssc[w][32 + lane];
    for (int it = 0; it < NN_; it++){
        float mvv; int mi;
        if (v1 >= v2){ mvv = v1; mi = lane; } else { mvv = v2; mi = 32 + lane; }
#pragma unroll
        for (int o = 16; o > 0; o >>= 1){
            float ov = __shfl_xor_sync(0xffffffffu, mvv, o);
            int   oi = __shfl_xor_sync(0xffffffffu, mi, o);
            if (ov > mvv || (ov == mvv && oi < mi)){ mvv = ov; mi = oi; }
        }
        if (mi < 32){ if (lane == mi) v1 = -3.0e38f; }
        else        { if (lane == mi - 32) v2 = -3.0e38f; }
        if (lane == 0){
            g_topv[qi * NN_ + it] = mvv;
            g_topi[qi * NN_ + it] = sid[w][mi];
        }
    }
}

// ---- flash attention: QK^T via tf32 MMA, PV exact SIMT (V loads hoisted) ----
#define AT_Q   0
#define AT_K   32768
#define AT_SC  65536
#define AT_MS  98816
#define AT_TI  99584
#define ATTN_SMEM 107776
__global__ void __launch_bounds__(256, 2) attn_kernel(const float* __restrict__ am,
                            const float* __restrict__ scale_param,
                            const float* __restrict__ mem_values)
{
    extern __shared__ char smraw[];
    uint32_t sb = smem_u32(smraw);
    float* Sc  = (float*)(smraw + AT_SC);
    float* msh = (float*)(smraw + AT_MS);
    float* lsh = msh + 64;
    float* csh = lsh + 64;
    int*   Ti  = (int*)(smraw + AT_TI);
    float* Vs  = (float*)(smraw + AT_K);

    const int tid = threadIdx.x, lane = tid & 31, wid = tid >> 5;
    const int wm = wid >> 2, wn = wid & 3;
    const int h = blockIdx.y;
    const int q0 = (gridDim.x - 1 - blockIdx.x) * 64;
    const int ty = tid >> 4, tx = tid & 15;
    const int srow = tid >> 2, sl4 = tid & 3;
    const float scale = expf(scale_param[h]);

    {
        int r = tid >> 2, part = tid & 3;
        const uint4* Ar = (const uint4*)(g_q + ((size_t)h * S_ + q0 + r) * DH_);
#pragma unroll
        for (int j = 0; j < 8; j++)
            *(uint4*)(smraw + AT_Q + part*8192 + SWZ(r*128 + j*16)) = Ar[part*8 + j];
    }
    for (int idx = tid; idx < 64 * 32; idx += 256) {
        int q = idx >> 5, n = idx & 31;
        Sc[q*130+n] = g_topv[((size_t)h * S_ + q0 + q) * NN_ + n] * scale;
        Ti[q*32+n]  = g_topi[((size_t)h * S_ + q0 + q) * NN_ + n];
    }
    __syncthreads();

    {
        float mm = -3.0e38f;
#pragma unroll
        for (int j = 0; j < 8; j++) mm = fmaxf(mm, Sc[srow*130 + sl4*8 + j]);
        mm = fmaxf(mm, __shfl_xor_sync(0xffffffffu, mm, 1));
        mm = fmaxf(mm, __shfl_xor_sync(0xffffffffu, mm, 2));
        float ll = 0.f;
#pragma unroll
        for (int j = 0; j < 8; j++){
            float p = expf(Sc[srow*130 + sl4*8 + j] - mm);
            Sc[srow*130 + sl4*8 + j] = p; ll += p;
        }
        ll += __shfl_xor_sync(0xffffffffu, ll, 1);
        ll += __shfl_xor_sync(0xffffffffu, ll, 2);
        if (sl4 == 0){ msh[srow] = mm; lsh[srow] = ll; }
    }
    __syncthreads();

    float oacc[4][8];
#pragma unroll
    for (int i = 0; i < 4; i++)
#pragma unroll
        for (int j = 0; j < 8; j++) oacc[i][j] = 0.f;

#pragma unroll
    for (int i = 0; i < 4; i++) {
        int qr = ty * 4 + i;
        for (int n = 0; n < NN_; n++) {
            float w = Sc[qr*130+n];
            const float4* vr = (const float4*)(mem_values +
                ((size_t)h * MK_ + Ti[qr*32+n]) * DH_ + tx * 8);
            float4 v0 = vr[0], v1 = vr[1];
            oacc[i][0]+=w*v0.x; oacc[i][1]+=w*v0.y; oacc[i][2]+=w*v0.z; oacc[i][3]+=w*v0.w;
            oacc[i][4]+=w*v1.x; oacc[i][5]+=w*v1.y; oacc[i][6]+=w*v1.z; oacc[i][7]+=w*v1.w;
        }
    }

    float acc[32];
#pragma unroll
    for (int i = 0; i < 32; i++) acc[i] = 0.f;

    const int ntiles = (q0 >> 7) + 1;
    for (int t = 0; t < ntiles; t++){
#pragma unroll
        for (int i = 0; i < 4; i++){
            int g = tid + i * 256, r = g >> 3, u = g & 7;
            uint4 v = ((const uint4*)(g_k + ((size_t)h * S_ + t*128 + r) * DH_))[u];
            *(uint4*)(smraw + AT_K + SWZ(r*128 + u*16)) = v;
        }
        __syncthreads();
        for (int ci = 0; ci < 4; ci++){
            uint4 pb[4];
            if (ci < 3){
#pragma unroll
                for (int i = 0; i < 4; i++){
                    int g = tid + i * 256, r = g >> 3, u = g & 7;
                    pb[i] = ((const uint4*)(g_k + ((size_t)h * S_ + t*128 + r) * DH_))[(ci+1)*8 + u];
                }
            }
            mma_chunk<2>(sb + AT_Q + ci*8192, sb + AT_K + (ci&1)*16384, lane, wm, wn, acc);
            if (ci < 3){
                int nb = (ci+1) & 1;
#pragma unroll
                for (int i = 0; i < 4; i++){
                    int g = tid + i * 256, r = g >> 3, u = g & 7;
                    *(uint4*)(smraw + AT_K + nb*16384 + SWZ(r*128 + u*16)) = pb[i];
                }
            }
            __syncthreads();
        }
        {
            const int gr = lane >> 2, gc2 = (lane & 3) * 2;
#pragma unroll
            for (int mt = 0; mt < 2; mt++)
#pragma unroll
                for (int nt = 0; nt < 4; nt++){
                    float* cp = acc + (mt*4+nt)*4;
                    int r = wm*32 + mt*16 + gr, col = wn*32 + nt*8 + gc2;
                    *(float2*)(Sc + r*130 + col)     = make_float2(cp[0], cp[1]);
                    *(float2*)(Sc + (r+8)*130 + col) = make_float2(cp[2], cp[3]);
                }
#pragma unroll
            for (int i = 0; i < 32; i++) acc[i] = 0.f;
        }
        __syncthreads();

        {
            const int qg = q0 + srow;
            float mm = msh[srow], rmax = mm;
#pragma unroll
            for (int j = 0; j < 32; j++){
                int kg = t*128 + sl4*32 + j;
                float s = Sc[srow*130 + sl4*32 + j];
                float v = (kg <= qg) ? (s * scale + am[kg]) : -1.0e30f;
                rmax = fmaxf(rmax, v);
            }
            rmax = fmaxf(rmax, __shfl_xor_sync(0xffffffffu, rmax, 1));
            rmax = fmaxf(rmax, __shfl_xor_sync(0xffffffffu, rmax, 2));
            float cor = expf(mm - rmax);
            float ll = (sl4 == 0) ? lsh[srow] * cor : 0.f;
#pragma unroll
            for (int j = 0; j < 32; j++){
                int kg = t*128 + sl4*32 + j;
                float s = Sc[srow*130 + sl4*32 + j];
                float v = (kg <= qg) ? (s * scale + am[kg]) : -1.0e30f;
                float p = expf(v - rmax);
                Sc[srow*130 + sl4*32 + j] = p;
                ll += p;
            }
            ll += __shfl_xor_sync(0xffffffffu, ll, 1);
            ll += __shfl_xor_sync(0xffffffffu, ll, 2);
            if (sl4 == 0){ msh[srow] = rmax; lsh[srow] = ll; csh[srow] = cor; }
        }
        __syncthreads();

        for (int ph = 0; ph < 2; ph++){
            for (int idx = tid; idx < 64 * 32; idx += 256){
                int row = idx >> 5, seg = idx & 31;
                *(float4*)&Vs[row*128 + seg*4] =
                    *(const float4*)(g_v + ((size_t)h * S_ + t*128 + ph*64 + row) * DH_ + seg*4);
            }
            __syncthreads();
            if (ph == 0){
#pragma unroll
                for (int i = 0; i < 4; i++){
                    float cor = csh[ty*4 + i];
#pragma unroll
                    for (int j = 0; j < 8; j++) oacc[i][j] *= cor;
                }
            }
            // V loads hoisted: each V row fetched once, used for 4 q-rows.
            for (int n = 0; n < 64; n++){
                float4 v0 = *(const float4*)&Vs[n*128 + tx*8];
                float4 v1 = *(const float4*)&Vs[n*128 + tx*8 + 4];
#pragma unroll
                for (int i = 0; i < 4; i++){
                    float w = Sc[(ty*4+i)*130 + ph*64 + n];
                    oacc[i][0]+=w*v0.x; oacc[i][1]+=w*v0.y; oacc[i][2]+=w*v0.z; oacc[i][3]+=w*v0.w;
                    oacc[i][4]+=w*v1.x; oacc[i][5]+=w*v1.y; oacc[i][6]+=w*v1.z; oacc[i][7]+=w*v1.w;
                }
            }
            __syncthreads();
        }
    }

    // epilogue: normalize + write hi/lo/hi directly into ctx_s (A-type)
#pragma unroll
    for (int i = 0; i < 4; i++) {
        int qr = ty*4 + i;
        float inv = 1.0f / lsh[qr];
#pragma unroll
        for (int j = 0; j < 8; j++){
            float x  = oacc[i][j] * inv;
            float hi = to_tf32(x);
            float lo = to_tf32(x - hi);
            size_t base = (size_t)(q0+qr) * KB_ + h*DH_ + tx*8 + j;
            g_ctx_s[base]          = hi;
            g_ctx_s[base + H_]     = lo;
            g_ctx_s[base + 2*H_]   = hi;
        }
    }
}

extern "C" void kernel_launch(void* const* d_in, const int* in_sizes, int n_in,
                              void* d_out, int out_size)
{
    const float* hidden      = (const float*)d_in[0];
    const float* am          = (const float*)d_in[1];
    const int*   pos         = (const int*)d_in[2];
    const float* Wqkv        = (const float*)d_in[3];
    const float* bqkv        = (const float*)d_in[4];
    const float* Wd          = (const float*)d_in[5];
    const float* bd          = (const float*)d_in[6];
    const float* scale_param = (const float*)d_in[7];
    const float* mem_keys    = (const float*)d_in[8];
    const float* mem_values  = (const float*)d_in[9];
    float*       out         = (float*)d_out;

    cudaFuncSetAttribute(out_mma_kernel,    cudaFuncAttributeMaxDynamicSharedMemorySize, GEMM_SMEM);
    cudaFuncSetAttribute(qkv_kv_mma_kernel, cudaFuncAttributeMaxDynamicSharedMemorySize, GEMM_SMEM);
    cudaFuncSetAttribute(knn_pool_kernel,   cudaFuncAttributeMaxDynamicSharedMemorySize, KNP_SMEM);
    cudaFuncSetAttribute(attn_kernel,       cudaFuncAttributeMaxDynamicSharedMemorySize, ATTN_SMEM);

    split_all_kernel<<<SPL_NB0 + SPL_NB1 + SPL_NB2, 256>>>(Wqkv, hidden, Wd);
    qkv_q_kernel<<<dim3(NH_, S_/64), 128>>>(hidden, Wqkv, bqkv);
    qkv_kv_mma_kernel<<<dim3(2*NH_, S_/128), 256, GEMM_SMEM>>>(bqkv);
    norm_rope_kernel<<<dim3(S_, NH_), 128>>>(pos);
    knn_pool_kernel<<<dim3(S_/64, NH_), 256, KNP_SMEM>>>(mem_keys);
    rescore_kernel<<<dim3(S_/4, NH_), 128>>>(mem_keys);
    attn_kernel<<<dim3(S_/64, NH_), 256, ATTN_SMEM>>>(am, scale_param, mem_values);
    out_mma_kernel<<<dim3(H_/128, S_/128), 256, GEMM_SMEM>>>(bd, out);
}